// round 5
// baseline (speedup 1.0000x reference)
#include <cuda_runtime.h>
#include <cstdint>

#define B_   16
#define S_   1024
#define DM_  768
#define H_   12
#define DH_  64
#define MTOT (B_ * S_)   // 16384
#define WSZ  589824      // 768*768

// Scratch (allocation-free rule: __device__ globals)
// g_q, g_ctx, g_xf: a-fragment layout. g_wf: b-fragment layout.
__device__ __align__(16) float g_q[(size_t)B_ * H_ * S_ * DH_];   // a-frag per (b,h)
__device__ __align__(16) float g_k[(size_t)B_ * H_ * S_ * DH_];   // [b,h,s,d]
__device__ __align__(16) float g_v[(size_t)B_ * H_ * S_ * DH_];   // [b,h,d,s]
__device__ __align__(16) float g_ctx[(size_t)B_ * S_ * DM_];      // a-frag [16384,768]
__device__ __align__(16) float g_xf[(size_t)MTOT * DM_];          // a-frag x
__device__ __align__(16) float g_wf[(size_t)4 * WSZ];             // b-frag Wq,Wk,Wv,Wc

// ---------------- helpers ----------------
__device__ __forceinline__ float tf32r(float x) {
    uint32_t u;
    asm("cvt.rna.tf32.f32 %0, %1;" : "=r"(u) : "f"(x));
    return __uint_as_float(u);
}

__device__ __forceinline__ void mma_tf32(float c[4],
                                         uint32_t a0, uint32_t a1, uint32_t a2, uint32_t a3,
                                         uint32_t b0, uint32_t b1) {
    asm volatile(
        "mma.sync.aligned.m16n8k8.row.col.f32.tf32.tf32.f32 "
        "{%0,%1,%2,%3}, {%4,%5,%6,%7}, {%8,%9}, {%0,%1,%2,%3};"
        : "+f"(c[0]), "+f"(c[1]), "+f"(c[2]), "+f"(c[3])
        : "r"(a0), "r"(a1), "r"(a2), "r"(a3), "r"(b0), "r"(b1));
}

// ---------------- pre-swizzle kernels (tf32-RN fused) ----------------
// a-frag: addr = ((mt*(K/8)) + kt)*128 + ((row%8)*4 + col%4)*4 + row/8%2 + 2*(col%8/4)
__global__ void swizzle_a_kernel(const float4* __restrict__ src, float* __restrict__ dst) {
    int i = blockIdx.x * 256 + threadIdx.x;          // one float4 of [M][768]
    float4 v = src[i];
    int row = i / (DM_ / 4);
    int kc  = (i % (DM_ / 4)) * 4;
    int mt = row >> 4, rowt = row & 15, kt = kc >> 3, chi = (kc >> 2) & 1;
    float* d = dst + ((size_t)mt * 96 + kt) * 128
                   + ((rowt & 7) << 4) + (rowt >> 3) + (chi << 1);
    d[0]  = tf32r(v.x);
    d[4]  = tf32r(v.y);
    d[8]  = tf32r(v.z);
    d[12] = tf32r(v.w);
}

// b-frag: addr = ((nt*(K/8)) + kt)*64 + ((n%8)*4 + k%4)*2 + (k%8)/4
__global__ void swizzle_b_kernel(const float4* __restrict__ W0,
                                 const float4* __restrict__ W1,
                                 const float4* __restrict__ W2,
                                 const float4* __restrict__ W3) {
    int w = blockIdx.y;
    const float4* src = (w == 0) ? W0 : (w == 1) ? W1 : (w == 2) ? W2 : W3;
    int i = blockIdx.x * 256 + threadIdx.x;          // one float4 of [768][768]
    float4 v = src[i];
    int n  = i / (DM_ / 4);
    int kc = (i % (DM_ / 4)) * 4;
    int nt = n >> 3, kt = kc >> 3, chi = (kc >> 2) & 1;
    float* d = g_wf + (size_t)w * WSZ + ((size_t)nt * 96 + kt) * 64
                    + ((n & 7) << 3) + chi;
    d[0] = tf32r(v.x);
    d[2] = tf32r(v.y);
    d[4] = tf32r(v.z);
    d[6] = tf32r(v.w);
}

// ---------------- pipelined fragment-direct GEMM core ----------------
// Y[m,n] = sum_k A[m,k]*W[n,k]; A,B already in frag layout in gmem.
// Block 128x128, BK=32 (4 kt-tiles/stage), 3-stage cp.async, 256 threads.
#define STGW 8192                       // words/stage: 4096 A + 4096 B
#define GEMM_SMEM (3 * STGW * 4)        // 98304 bytes

__device__ __forceinline__ void tc_gemm_frag(const float* __restrict__ Ag,
                                             const float* __restrict__ Bg,
                                             int m0, int n0, float* smem,
                                             float acc[4][4][4])
{
    const int tid  = threadIdx.x;
    const int lane = tid & 31;
    const int wid  = tid >> 5;
    const int wm   = wid >> 2;
    const int wn   = wid & 3;
    const int mt0  = m0 >> 4, nt0 = n0 >> 3;
    const uint32_t sb = (uint32_t)__cvta_generic_to_shared(smem);

    auto pf = [&](int kt, int buf) {
#pragma unroll
        for (int i = 0; i < 4; i++) {               // A: 8 mt * 512 words
            int idx = tid + (i << 8);
            const float* src = Ag + ((size_t)(mt0 + (idx >> 7)) * 96 + (kt << 2)) * 128
                                  + ((idx & 127) << 2);
            uint32_t dst = sb + (uint32_t)(buf * STGW + ((idx >> 7) << 9)
                                           + ((idx & 127) << 2)) * 4u;
            asm volatile("cp.async.cg.shared.global [%0], [%1], 16;"
                         :: "r"(dst), "l"(src));
        }
#pragma unroll
        for (int i = 0; i < 4; i++) {               // B: 16 nt * 256 words
            int idx = tid + (i << 8);
            const float* src = Bg + ((size_t)(nt0 + (idx >> 6)) * 96 + (kt << 2)) * 64
                                  + ((idx & 63) << 2);
            uint32_t dst = sb + (uint32_t)(buf * STGW + 4096 + ((idx >> 6) << 8)
                                           + ((idx & 63) << 2)) * 4u;
            asm volatile("cp.async.cg.shared.global [%0], [%1], 16;"
                         :: "r"(dst), "l"(src));
        }
        asm volatile("cp.async.commit_group;" ::: "memory");
    };

    pf(0, 0); pf(1, 1);
    for (int kt = 0; kt < 24; kt++) {
        if (kt < 22) asm volatile("cp.async.wait_group 1;" ::: "memory");
        else         asm volatile("cp.async.wait_group 0;" ::: "memory");
        __syncthreads();
        if (kt + 2 < 24) pf(kt + 2, (kt + 2) % 3);

        const uint32_t* sA = (const uint32_t*)smem + (kt % 3) * STGW;
        const uint32_t* sB = sA + 4096;
#pragma unroll
        for (int ks = 0; ks < 4; ks++) {
            uint4 a[4]; uint2 b[4];
#pragma unroll
            for (int mi = 0; mi < 4; mi++)
                a[mi] = *(const uint4*)(sA + (((wm * 4 + mi) << 2) + ks) * 128 + (lane << 2));
#pragma unroll
            for (int ni = 0; ni < 4; ni++)
                b[ni] = *(const uint2*)(sB + (((wn * 4 + ni) << 2) + ks) * 64 + (lane << 1));
#pragma unroll
            for (int mi = 0; mi < 4; mi++)
#pragma unroll
                for (int ni = 0; ni < 4; ni++)
                    mma_tf32(acc[mi][ni], a[mi].x, a[mi].y, a[mi].z, a[mi].w,
                             b[ni].x, b[ni].y);
        }
    }
}

// ---------------- Kernel 1: fused QKV projection ----------------
// Q written in a-frag layout per (b,h); K row-major [b,h,s,d];
// V transposed [b,h,d,s]. All tf32-RN.
__global__ void __launch_bounds__(256, 2) qkv_tc_kernel(
    const float* __restrict__ bq, const float* __restrict__ bk,
    const float* __restrict__ bv)
{
    extern __shared__ float smem[];
    const int which = blockIdx.z;
    const float* bias = (which == 0) ? bq : (which == 1) ? bk : bv;

    const int m0 = blockIdx.x * 128;
    const int n0 = blockIdx.y * 128;
    float acc[4][4][4] = {};
    tc_gemm_frag(g_xf, g_wf + (size_t)which * WSZ, m0, n0, smem, acc);

    const int tid  = threadIdx.x;
    const int lane = tid & 31;
    const int wid  = tid >> 5;
    const int wm = wid >> 2, wn = wid & 3;
    const int r = lane >> 2, c = lane & 3;
    const int c2 = 2 * c;
    const int b0w = ((r << 2) + (c2 & 3)) * 4 + ((c2 >> 2) << 1);

    if (which == 0) {
        // Q -> a-frag layout per (b,h): tile (mt=s/16, kt=d/8), 128 words
#pragma unroll
        for (int mi = 0; mi < 4; mi++) {
            int m  = m0 + wm * 64 + mi * 16;
            int bb = m >> 10, s = m & 1023;
#pragma unroll
            for (int ni = 0; ni < 4; ni++) {
                int n  = n0 + wn * 32 + ni * 8 + c2;
                int h  = n >> 6;
                int ktl = (n >> 3) & 7;
                float bi0 = bias[n], bi1 = bias[n + 1];
                float* dst = g_q + (size_t)(bb * H_ + h) * S_ * DH_
                                 + ((size_t)(s >> 4) * 8 + ktl) * 128;
                *(float2*)(dst + b0w) =
                    make_float2(tf32r(acc[mi][ni][0] + bi0), tf32r(acc[mi][ni][2] + bi0));
                *(float2*)(dst + b0w + 4) =
                    make_float2(tf32r(acc[mi][ni][1] + bi1), tf32r(acc[mi][ni][3] + bi1));
            }
        }
    } else if (which == 1) {
        // K -> row-major [b,h,s,d]
#pragma unroll
        for (int mi = 0; mi < 4; mi++) {
            int r0 = m0 + wm * 64 + mi * 16 + r;
#pragma unroll
            for (int ni = 0; ni < 4; ni++) {
                int n  = n0 + wn * 32 + ni * 8 + c2;
                float bi0 = bias[n], bi1 = bias[n + 1];
                int h = n >> 6, d = n & 63;
#pragma unroll
                for (int rr = 0; rr < 2; rr++) {
                    int m = r0 + rr * 8;
                    int bb = m >> 10, s = m & 1023;
                    float2 o = make_float2(tf32r(acc[mi][ni][rr * 2 + 0] + bi0),
                                           tf32r(acc[mi][ni][rr * 2 + 1] + bi1));
                    *(float2*)(g_k + ((size_t)(bb * H_ + h) * S_ + s) * DH_ + d) = o;
                }
            }
        }
    } else {
        // V: transpose through smem, write [b,h,d,s]
        float* T = smem;                   // T[64][132] = 8448 words
        const int bb = m0 >> 10, s0 = m0 & 1023;
        __syncthreads();                   // all fragment reads done
        for (int p = 0; p < 2; p++) {
            if ((wn >> 1) == p) {
#pragma unroll
                for (int mi = 0; mi < 4; mi++) {
                    int ml = wm * 64 + mi * 16 + r;
#pragma unroll
                    for (int ni = 0; ni < 4; ni++) {
                        int nl = (wn & 1) * 32 + ni * 8 + c2;
                        int n  = n0 + p * 64 + nl;
                        float bi0 = bias[n], bi1 = bias[n + 1];
#pragma unroll
                        for (int rr = 0; rr < 2; rr++) {
                            T[nl * 132 + ml + rr * 8]       = tf32r(acc[mi][ni][rr * 2 + 0] + bi0);
                            T[(nl + 1) * 132 + ml + rr * 8] = tf32r(acc[mi][ni][rr * 2 + 1] + bi1);
                        }
                    }
                }
            }
            __syncthreads();
            int h = blockIdx.y * 2 + p;
            float* dst = g_v + ((size_t)(bb * H_ + h) * DH_) * S_ + s0;
            for (int i = tid; i < 64 * 32; i += 256) {
                int dr = i >> 5, c4 = (i & 31) << 2;
                *(float4*)(dst + (size_t)dr * S_ + c4) = *(const float4*)(T + dr * 132 + c4);
            }
            __syncthreads();
        }
    }
}

// ---------------- Kernel 3: output projection ----------------
__global__ void __launch_bounds__(256, 2) proj_tc_kernel(
    const float* __restrict__ bc, float* __restrict__ out)
{
    extern __shared__ float smem[];
    const int m0 = blockIdx.x * 128;
    const int n0 = blockIdx.y * 128;
    float acc[4][4][4] = {};
    tc_gemm_frag(g_ctx, g_wf + (size_t)3 * WSZ, m0, n0, smem, acc);

    const int lane = threadIdx.x & 31;
    const int wid  = threadIdx.x >> 5;
    const int wm = wid >> 2, wn = wid & 3;
    const int r = lane >> 2, c2 = (lane & 3) * 2;
#pragma unroll
    for (int mi = 0; mi < 4; mi++) {
        int r0 = m0 + wm * 64 + mi * 16 + r;
#pragma unroll
        for (int ni = 0; ni < 4; ni++) {
            int n  = n0 + wn * 32 + ni * 8 + c2;
            float b0 = bc[n], b1 = bc[n + 1];
#pragma unroll
            for (int rr = 0; rr < 2; rr++) {
                int m = r0 + rr * 8;
                float2 o = make_float2(acc[mi][ni][rr * 2 + 0] + b0,
                                       acc[mi][ni][rr * 2 + 1] + b1);
                *(float2*)(out + (size_t)m * DM_ + n) = o;
            }
        }
    }
}

// ---------------- Kernel 2: flash attention (tf32 mma + cp.async) ----------------
#define ATS  68
#define KVW  4352                       // 64*68 words
#define PFW  1056                       // 8 ks-tiles * 132 words
#define ATT_WORDS (4 * KVW + 16 * PFW)  // 34304
#define ATT_SMEM  (ATT_WORDS * 4)       // 137216 bytes

__global__ void __launch_bounds__(512) attn_tc_kernel()
{
    extern __shared__ float sm[];
    const int tid  = threadIdx.x;
    const int lane = tid & 31, w = tid >> 5;
    const int r = lane >> 2, c = lane & 3;
    const int q0   = blockIdx.x * 256;
    const int head = blockIdx.y, batch = blockIdx.z;
    const size_t base = (size_t)(batch * H_ + head) * S_ * DH_;
    const float* kb = g_k + base;
    const float* vb = g_v + base;      // [d][s]
    const uint32_t sb = (uint32_t)__cvta_generic_to_shared(sm);

    auto stage = [&](int t, int buf) {
#pragma unroll
        for (int i = 0; i < 2; i++) {            // K rows
            int g = tid + (i << 9);
            int row = g >> 4, c4 = (g & 15) << 2;
            const float* src = kb + (size_t)(t * 64 + row) * DH_ + c4;
            uint32_t dst = sb + (uint32_t)(buf * KVW + row * ATS + c4) * 4u;
            asm volatile("cp.async.cg.shared.global [%0], [%1], 16;"
                         :: "r"(dst), "l"(src));
        }
#pragma unroll
        for (int i = 0; i < 2; i++) {            // V^T rows
            int g = tid + (i << 9);
            int row = g >> 4, c4 = (g & 15) << 2;
            const float* src = vb + (size_t)row * S_ + t * 64 + c4;
            uint32_t dst = sb + (uint32_t)((2 + buf) * KVW + row * ATS + c4) * 4u;
            asm volatile("cp.async.cg.shared.global [%0], [%1], 16;"
                         :: "r"(dst), "l"(src));
        }
        asm volatile("cp.async.commit_group;" ::: "memory");
    };

    stage(0, 0);

    // Q a-fragments: direct LDG.128 from fragment-layout g_q
    uint4 qa[8];
    {
        const float* qf = g_q + base + ((size_t)((q0 >> 4) + w) * 8) * 128 + (lane << 2);
#pragma unroll
        for (int ks = 0; ks < 8; ks++)
            qa[ks] = *(const uint4*)(qf + ks * 128);
    }

    float o[8][4];
#pragma unroll
    for (int a = 0; a < 8; a++)
#pragma unroll
        for (int j = 0; j < 4; j++) o[a][j] = 0.f;
    float mi0 = -1e30f, mi1 = -1e30f, li0 = 0.f, li1 = 0.f;

    float* Pw = sm + 4 * KVW + w * PFW;
    const int lc    = (2 * c) & 3;
    const int slotb = (c & 2) ? 2 : 0;

    for (int t = 0; t < S_ / 64; t++) {
        asm volatile("cp.async.wait_group 0;" ::: "memory");
        __syncthreads();
        if (t + 1 < S_ / 64) stage(t + 1, (t + 1) & 1);

        const float* Kb = sm + (t & 1) * KVW;
        const float* Vb = sm + (2 + (t & 1)) * KVW;

        // ---- S = Q @ K^T ----
        float s[8][4];
#pragma unroll
        for (int a = 0; a < 8; a++)
#pragma unroll
            for (int j = 0; j < 4; j++) s[a][j] = 0.f;
#pragma unroll
        for (int ks = 0; ks < 8; ks++) {
#pragma unroll
            for (int a = 0; a < 8; a++) {
                const float* kp = Kb + (a * 8 + r) * ATS + ks * 8 + c;
                mma_tf32(s[a], qa[ks].x, qa[ks].y, qa[ks].z, qa[ks].w,
                         __float_as_uint(kp[0]), __float_as_uint(kp[4]));
            }
        }

        // ---- online softmax ----
        float mx0 = -1e30f, mx1 = -1e30f;
#pragma unroll
        for (int a = 0; a < 8; a++) {
            s[a][0] *= 0.125f; s[a][1] *= 0.125f;
            s[a][2] *= 0.125f; s[a][3] *= 0.125f;
            mx0 = fmaxf(mx0, fmaxf(s[a][0], s[a][1]));
            mx1 = fmaxf(mx1, fmaxf(s[a][2], s[a][3]));
        }
        mx0 = fmaxf(mx0, __shfl_xor_sync(0xffffffffu, mx0, 1));
        mx0 = fmaxf(mx0, __shfl_xor_sync(0xffffffffu, mx0, 2));
        mx1 = fmaxf(mx1, __shfl_xor_sync(0xffffffffu, mx1, 1));
        mx1 = fmaxf(mx1, __shfl_xor_sync(0xffffffffu, mx1, 2));
        float mn0 = fmaxf(mi0, mx0), mn1 = fmaxf(mi1, mx1);
        float cr0 = __expf(mi0 - mn0), cr1 = __expf(mi1 - mn1);
        float sum0 = 0.f, sum1 = 0.f;
#pragma unroll
        for (int a = 0; a < 8; a++) {
            s[a][0] = __expf(s[a][0] - mn0);
            s[a][1] = __expf(s[a][1] - mn0);
            s[a][2] = __expf(s[a][2] - mn1);
            s[a][3] = __expf(s[a][3] - mn1);
            sum0 += s[a][0] + s[a][1];
            sum1 += s[a][2] + s[a][3];
        }
        sum0 += __shfl_xor_sync(0xffffffffu, sum0, 1);
        sum0 += __shfl_xor_sync(0xffffffffu, sum0, 2);
        sum1 += __shfl_xor_sync(0xffffffffu, sum1, 1);
        sum1 += __shfl_xor_sync(0xffffffffu, sum1, 2);
        li0 = li0 * cr0 + sum0;  mi0 = mn0;
        li1 = li1 * cr1 + sum1;  mi1 = mn1;
#pragma unroll
        for (int a = 0; a < 8; a++) {
            o[a][0] *= cr0; o[a][1] *= cr0;
            o[a][2] *= cr1; o[a][3] *= cr1;
        }

        // ---- scatter P into packed a-frag layout (warp-local) ----
#pragma unroll
        for (int a = 0; a < 8; a++) {
            float* pe = Pw + a * 132 + ((r << 2) + lc) * 4 + slotb;
            *(float2*)(pe)     = make_float2(tf32r(s[a][0]), tf32r(s[a][2]));
            *(float2*)(pe + 4) = make_float2(tf32r(s[a][1]), tf32r(s[a][3]));
        }
        __syncwarp();

        // ---- O += P @ V ----
#pragma unroll
        for (int ks = 0; ks < 8; ks++) {
            uint4 pa = *(const uint4*)(Pw + ks * 132 + (lane << 2));
#pragma unroll
            for (int a = 0; a < 8; a++) {
                const float* vp = Vb + (a * 8 + r) * ATS + ks * 8 + c;
                mma_tf32(o[a], pa.x, pa.y, pa.z, pa.w,
                         __float_as_uint(vp[0]), __float_as_uint(vp[4]));
            }
        }
    }

    // ---- epilogue: normalize + write ctx in a-frag layout ----
    float inv0 = 1.f / li0, inv1 = 1.f / li1;
    const int mt = batch * 64 + (q0 >> 4) + w;
    const int c2 = 2 * c;
    const int b0w = ((r << 2) + (c2 & 3)) * 4 + ((c2 >> 2) << 1);
    float* cf = g_ctx + ((size_t)mt * 96 + head * 8) * 128;
#pragma unroll
    for (int a = 0; a < 8; a++) {
        *(float2*)(cf + a * 128 + b0w) =
            make_float2(tf32r(o[a][0] * inv0), tf32r(o[a][2] * inv1));
        *(float2*)(cf + a * 128 + b0w + 4) =
            make_float2(tf32r(o[a][1] * inv0), tf32r(o[a][3] * inv1));
    }
}

// ---------------- Launch ----------------
extern "C" void kernel_launch(void* const* d_in, const int* in_sizes, int n_in,
                              void* d_out, int out_size)
{
    const float* x  = (const float*)d_in[0];
    const float* Wq = (const float*)d_in[1];
    const float* bq = (const float*)d_in[2];
    const float* Wk = (const float*)d_in[3];
    const float* bk = (const float*)d_in[4];
    const float* Wv = (const float*)d_in[5];
    const float* bv = (const float*)d_in[6];
    const float* Wc = (const float*)d_in[7];
    const float* bc = (const float*)d_in[8];
    float* out = (float*)d_out;

    float* xf; cudaGetSymbolAddress((void**)&xf, g_xf);

    cudaFuncSetAttribute(attn_tc_kernel,
                         cudaFuncAttributeMaxDynamicSharedMemorySize, ATT_SMEM);
    cudaFuncSetAttribute(qkv_tc_kernel,
                         cudaFuncAttributeMaxDynamicSharedMemorySize, GEMM_SMEM);
    cudaFuncSetAttribute(proj_tc_kernel,
                         cudaFuncAttributeMaxDynamicSharedMemorySize, GEMM_SMEM);

    // pre-swizzle into fragment layouts (tf32-RN fused)
    swizzle_a_kernel<<<MTOT * DM_ / 4 / 256, 256>>>((const float4*)x, xf);
    dim3 gw(WSZ / 4 / 256, 4);
    swizzle_b_kernel<<<gw, 256>>>((const float4*)Wq, (const float4*)Wk,
                                  (const float4*)Wv, (const float4*)Wc);

    dim3 gq(MTOT / 128, DM_ / 128, 3);     // 128 x 6 x 3
    qkv_tc_kernel<<<gq, 256, GEMM_SMEM>>>(bq, bk, bv);

    dim3 ga(S_ / 256, H_, B_);             // 4 x 12 x 16
    attn_tc_kernel<<<ga, 512, ATT_SMEM>>>();

    dim3 gp(MTOT / 128, DM_ / 128);        // 128 x 6
    proj_tc_kernel<<<gp, 256, GEMM_SMEM>>>(bc, out);
}

// round 6
// speedup vs baseline: 1.1866x; 1.1866x over previous
#include <cuda_runtime.h>
#include <cstdint>

#define B_   16
#define S_   1024
#define DM_  768
#define H_   12
#define DH_  64
#define MTOT (B_ * S_)   // 16384
#define HSZ  (S_ * DH_)  // 65536 floats per (b,h)

// Scratch (allocation-free rule: __device__ globals)
// g_q: a-frag layout per (b,h). g_k/g_v: b-frag layout per (b,h). g_ctx: row-major.
__device__ __align__(16) float g_q[(size_t)B_ * H_ * HSZ];
__device__ __align__(16) float g_k[(size_t)B_ * H_ * HSZ];
__device__ __align__(16) float g_v[(size_t)B_ * H_ * HSZ];
__device__ __align__(16) float g_ctx[(size_t)B_ * S_ * DM_];

// ---------------- helpers ----------------
__device__ __forceinline__ float tf32r(float x) {
    uint32_t u;
    asm("cvt.rna.tf32.f32 %0, %1;" : "=r"(u) : "f"(x));
    return __uint_as_float(u);
}

__device__ __forceinline__ void mma_tf32(float c[4],
                                         uint32_t a0, uint32_t a1, uint32_t a2, uint32_t a3,
                                         uint32_t b0, uint32_t b1) {
    asm volatile(
        "mma.sync.aligned.m16n8k8.row.col.f32.tf32.tf32.f32 "
        "{%0,%1,%2,%3}, {%4,%5,%6,%7}, {%8,%9}, {%0,%1,%2,%3};"
        : "+f"(c[0]), "+f"(c[1]), "+f"(c[2]), "+f"(c[3])
        : "r"(a0), "r"(a1), "r"(a2), "r"(a3), "r"(b0), "r"(b1));
}

// ---------------- tensor-core GEMM core (R4-proven) ----------------
// Y[m,n] = sum_k A[m,k]*W[n,k]. Block 128x128, k-step 32, 256 threads.
// tf32 RN rounding fused into the smem scatter.
#define GBK 32
#define AF_TILES 32
#define BF_TILES 64
#define AF_STRIDE 132
#define BF_STRIDE 68
#define GEMM_SMEM_WORDS (AF_TILES * AF_STRIDE + BF_TILES * BF_STRIDE)  // 8576

__device__ __forceinline__ void tc_gemm_core(const float* __restrict__ A,
                                             const float* __restrict__ W,
                                             int m0, int n0,
                                             uint32_t* Af, uint32_t* Bf,
                                             float acc[4][4][4])
{
    const int tid  = threadIdx.x;
    const int lane = tid & 31;
    const int wid  = tid >> 5;
    const int wm   = wid >> 2;
    const int wn   = wid & 3;

    for (int kt = 0; kt < DM_; kt += GBK) {
        float4 av[4], wv[4];
#pragma unroll
        for (int i = 0; i < 4; i++) {
            int f4  = tid + (i << 8);
            int row = f4 >> 3;
            int kc  = (f4 & 7) << 2;
            av[i] = *(const float4*)(A + (size_t)(m0 + row) * DM_ + kt + kc);
            wv[i] = *(const float4*)(W + (size_t)(n0 + row) * DM_ + kt + kc);
        }
        __syncthreads();
#pragma unroll
        for (int i = 0; i < 4; i++) {
            int f4  = tid + (i << 8);
            int row = f4 >> 3;
            int kc  = (f4 & 7) << 2;
            int ks  = kc >> 3;
            int chi = (kc & 7) >> 2;
            const float* pa = (const float*)&av[i];
            const float* pw = (const float*)&wv[i];
            {
                int mt = row >> 4, rr = row & 15;
                int lb = (rr & 7) << 2;
                int rg = (rr >> 3) + (chi << 1);
                uint32_t* dst = Af + ((mt << 2) + ks) * AF_STRIDE;
#pragma unroll
                for (int j = 0; j < 4; j++)
                    dst[((lb + j) << 2) + rg] = __float_as_uint(tf32r(pa[j]));
            }
            {
                int nt = row >> 3, ln = row & 7;
                int lb = ln << 2;
                uint32_t* dst = Bf + ((nt << 2) + ks) * BF_STRIDE;
#pragma unroll
                for (int j = 0; j < 4; j++)
                    dst[((lb + j) << 1) + chi] = __float_as_uint(tf32r(pw[j]));
            }
        }
        __syncthreads();
#pragma unroll
        for (int ks = 0; ks < 4; ks++) {
            uint4 a[4]; uint2 b[4];
#pragma unroll
            for (int mi = 0; mi < 4; mi++)
                a[mi] = *(const uint4*)(Af + (((wm * 4 + mi) << 2) + ks) * AF_STRIDE + (lane << 2));
#pragma unroll
            for (int ni = 0; ni < 4; ni++)
                b[ni] = *(const uint2*)(Bf + (((wn * 4 + ni) << 2) + ks) * BF_STRIDE + (lane << 1));
#pragma unroll
            for (int mi = 0; mi < 4; mi++)
#pragma unroll
                for (int ni = 0; ni < 4; ni++)
                    mma_tf32(acc[mi][ni], a[mi].x, a[mi].y, a[mi].z, a[mi].w,
                             b[ni].x, b[ni].y);
        }
    }
}

// ---------------- Kernel 1: fused QKV projection ----------------
// Q -> a-frag layout per (b,h).  K,V -> b-frag layouts per (b,h):
//   K: idx = (((sl>>6)*8 + ((sl>>3)&7))*8 + (d>>3))*64 + (sl&7)*8 + (d&3)*2 + ((d>>2)&1)
//   V: idx = (((sl>>6)*8 + (d>>3))*8 + ((sl>>3)&7))*64 + (d&7)*8 + (sl&3)*2 + ((sl>>2)&1)
__global__ void __launch_bounds__(256) qkv_tc_kernel(
    const float* __restrict__ x,
    const float* __restrict__ Wq, const float* __restrict__ Wk,
    const float* __restrict__ Wv,
    const float* __restrict__ bq, const float* __restrict__ bk,
    const float* __restrict__ bv)
{
    __shared__ __align__(16) uint32_t SBUF[GEMM_SMEM_WORDS];
    uint32_t* Af = SBUF;
    uint32_t* Bf = SBUF + AF_TILES * AF_STRIDE;

    const int which = blockIdx.z;
    const float* W    = (which == 0) ? Wq : (which == 1) ? Wk : Wv;
    const float* bias = (which == 0) ? bq : (which == 1) ? bk : bv;

    const int m0 = blockIdx.x * 128;
    const int n0 = blockIdx.y * 128;
    float acc[4][4][4] = {};
    tc_gemm_core(x, W, m0, n0, Af, Bf, acc);

    const int lane = threadIdx.x & 31;
    const int wid  = threadIdx.x >> 5;
    const int wm = wid >> 2, wn = wid & 3;
    const int r = lane >> 2, c2 = (lane & 3) * 2;

    if (which == 0) {
        // Q a-frag: tile (mt=s/16, kt=d/8) of 128 words
        const int b0w = ((r << 2) + (c2 & 3)) * 4 + ((c2 >> 2) << 1);
#pragma unroll
        for (int mi = 0; mi < 4; mi++) {
            int m  = m0 + wm * 64 + mi * 16;
            int bb = m >> 10, s = m & 1023;
#pragma unroll
            for (int ni = 0; ni < 4; ni++) {
                int n   = n0 + wn * 32 + ni * 8 + c2;
                int h   = n >> 6;
                int ktl = (n >> 3) & 7;
                float bi0 = bias[n], bi1 = bias[n + 1];
                float* dst = g_q + (size_t)(bb * H_ + h) * HSZ
                                 + ((size_t)(s >> 4) * 8 + ktl) * 128;
                *(float2*)(dst + b0w) =
                    make_float2(tf32r(acc[mi][ni][0] + bi0), tf32r(acc[mi][ni][2] + bi0));
                *(float2*)(dst + b0w + 4) =
                    make_float2(tf32r(acc[mi][ni][1] + bi1), tf32r(acc[mi][ni][3] + bi1));
            }
        }
    } else if (which == 1) {
        // K b-frag scatter
#pragma unroll
        for (int mi = 0; mi < 4; mi++) {
            int mb = m0 + wm * 64 + mi * 16 + r;
#pragma unroll
            for (int ni = 0; ni < 4; ni++) {
                int nf = n0 + wn * 32 + ni * 8 + c2;
                float bi0 = bias[nf], bi1 = bias[nf + 1];
#pragma unroll
                for (int j = 0; j < 4; j++) {
                    int m  = mb + ((j >> 1) << 3);
                    int df = nf + (j & 1);
                    int bb = m >> 10, sl = m & 1023;
                    int h = df >> 6, d = df & 63;
                    float val = tf32r(acc[mi][ni][j] + ((j & 1) ? bi1 : bi0));
                    size_t idx = (size_t)(bb * H_ + h) * HSZ
                        + (size_t)(((((sl >> 6) * 8 + ((sl >> 3) & 7)) * 8 + (d >> 3)) * 64)
                                   + ((sl & 7) << 3) + ((d & 3) << 1) + ((d >> 2) & 1));
                    g_k[idx] = val;
                }
            }
        }
    } else {
        // V b-frag scatter
#pragma unroll
        for (int mi = 0; mi < 4; mi++) {
            int mb = m0 + wm * 64 + mi * 16 + r;
#pragma unroll
            for (int ni = 0; ni < 4; ni++) {
                int nf = n0 + wn * 32 + ni * 8 + c2;
                float bi0 = bias[nf], bi1 = bias[nf + 1];
#pragma unroll
                for (int j = 0; j < 4; j++) {
                    int m  = mb + ((j >> 1) << 3);
                    int df = nf + (j & 1);
                    int bb = m >> 10, sl = m & 1023;
                    int h = df >> 6, d = df & 63;
                    float val = tf32r(acc[mi][ni][j] + ((j & 1) ? bi1 : bi0));
                    size_t idx = (size_t)(bb * H_ + h) * HSZ
                        + (size_t)(((((sl >> 6) * 8 + (d >> 3)) * 8 + ((sl >> 3) & 7)) * 64)
                                   + ((d & 7) << 3) + ((sl & 3) << 1) + ((sl >> 2) & 1));
                    g_v[idx] = val;
                }
            }
        }
    }
}

// ---------------- Kernel 3: output projection (R4-proven) ----------------
__global__ void __launch_bounds__(256) proj_tc_kernel(
    const float* __restrict__ Wc, const float* __restrict__ bc,
    float* __restrict__ out)
{
    __shared__ __align__(16) uint32_t SBUF[GEMM_SMEM_WORDS];
    uint32_t* Af = SBUF;
    uint32_t* Bf = SBUF + AF_TILES * AF_STRIDE;

    const int m0 = blockIdx.x * 128;
    const int n0 = blockIdx.y * 128;
    float acc[4][4][4] = {};
    tc_gemm_core(g_ctx, Wc, m0, n0, Af, Bf, acc);

    const int lane = threadIdx.x & 31;
    const int wid  = threadIdx.x >> 5;
    const int wm = wid >> 2, wn = wid & 3;
    const int r = lane >> 2, c2 = (lane & 3) * 2;
#pragma unroll
    for (int mi = 0; mi < 4; mi++) {
        int r0 = m0 + wm * 64 + mi * 16 + r;
#pragma unroll
        for (int ni = 0; ni < 4; ni++) {
            int n  = n0 + wn * 32 + ni * 8 + c2;
            float b0 = bc[n], b1 = bc[n + 1];
#pragma unroll
            for (int rr = 0; rr < 2; rr++) {
                int m = r0 + rr * 8;
                float2 o = make_float2(acc[mi][ni][rr * 2 + 0] + b0,
                                       acc[mi][ni][rr * 2 + 1] + b1);
                *(float2*)(out + (size_t)m * DM_ + n) = o;
            }
        }
    }
}

// ---------------- Kernel 2: flash attention ----------------
// 256 queries of one (b,h), 512 threads / 16 warps. K/V arrive in b-frag
// layout (16KB contiguous per 64-key iter) -> all b-frag reads are LDS.64.
#define KVS 8192                        // words per stage: 4096 K + 4096 V
#define PFW 1056                        // per-warp P: 8 tiles * 132 words
#define ATT_WORDS (2 * KVS + 16 * PFW)  // 33280
#define ATT_SMEM  (ATT_WORDS * 4)       // 133120 bytes

__global__ void __launch_bounds__(512) attn_tc_kernel()
{
    extern __shared__ float sm[];
    const int tid  = threadIdx.x;
    const int lane = tid & 31, w = tid >> 5;
    const int r = lane >> 2, c = lane & 3;
    const int q0   = blockIdx.x * 256;
    const int head = blockIdx.y, batch = blockIdx.z;
    const size_t base = (size_t)(batch * H_ + head) * HSZ;
    const float* kbf = g_k + base;      // b-frag chunks of 4096 words/iter
    const float* vbf = g_v + base;
    const uint32_t sb = (uint32_t)__cvta_generic_to_shared(sm);

    auto stage = [&](int t, int buf) {
        const float* ksrc = kbf + (size_t)t * 4096;
        const float* vsrc = vbf + (size_t)t * 4096;
#pragma unroll
        for (int i = 0; i < 2; i++) {
            int g = (tid + (i << 9)) << 2;           // float4 offset in words
            uint32_t dst = sb + (uint32_t)(buf * KVS + g) * 4u;
            asm volatile("cp.async.cg.shared.global [%0], [%1], 16;"
                         :: "r"(dst), "l"(ksrc + g));
        }
#pragma unroll
        for (int i = 0; i < 2; i++) {
            int g = (tid + (i << 9)) << 2;
            uint32_t dst = sb + (uint32_t)(buf * KVS + 4096 + g) * 4u;
            asm volatile("cp.async.cg.shared.global [%0], [%1], 16;"
                         :: "r"(dst), "l"(vsrc + g));
        }
        asm volatile("cp.async.commit_group;" ::: "memory");
    };

    stage(0, 0);

    // Q a-fragments: LDG.128 from fragment-layout g_q (proven in R5)
    uint4 qa[8];
    {
        const float* qf = g_q + base + ((size_t)((q0 >> 4) + w) * 8) * 128 + (lane << 2);
#pragma unroll
        for (int ks = 0; ks < 8; ks++)
            qa[ks] = *(const uint4*)(qf + ks * 128);
    }

    float o[8][4];
#pragma unroll
    for (int a = 0; a < 8; a++)
#pragma unroll
        for (int j = 0; j < 4; j++) o[a][j] = 0.f;
    float mi0 = -1e30f, mi1 = -1e30f, li0 = 0.f, li1 = 0.f;

    float* Pw = sm + 2 * KVS + w * PFW;
    const int lc    = (2 * c) & 3;
    const int slotb = (c & 2) ? 2 : 0;

    for (int t = 0; t < S_ / 64; t++) {
        asm volatile("cp.async.wait_group 0;" ::: "memory");
        __syncthreads();
        if (t + 1 < S_ / 64) stage(t + 1, (t + 1) & 1);

        const float* Kb = sm + (t & 1) * KVS;
        const float* Vb = Kb + 4096;

        // ---- S = Q @ K^T (b-frags: single LDS.64 each) ----
        float s[8][4];
#pragma unroll
        for (int a = 0; a < 8; a++)
#pragma unroll
            for (int j = 0; j < 4; j++) s[a][j] = 0.f;
#pragma unroll
        for (int ks = 0; ks < 8; ks++) {
#pragma unroll
            for (int a = 0; a < 8; a++) {
                uint2 b = *(const uint2*)(Kb + (((a << 3) + ks) << 6) + (lane << 1));
                mma_tf32(s[a], qa[ks].x, qa[ks].y, qa[ks].z, qa[ks].w, b.x, b.y);
            }
        }

        // ---- online softmax (rows r, r+8; quad-local reductions) ----
        float mx0 = -1e30f, mx1 = -1e30f;
#pragma unroll
        for (int a = 0; a < 8; a++) {
            s[a][0] *= 0.125f; s[a][1] *= 0.125f;
            s[a][2] *= 0.125f; s[a][3] *= 0.125f;
            mx0 = fmaxf(mx0, fmaxf(s[a][0], s[a][1]));
            mx1 = fmaxf(mx1, fmaxf(s[a][2], s[a][3]));
        }
        mx0 = fmaxf(mx0, __shfl_xor_sync(0xffffffffu, mx0, 1));
        mx0 = fmaxf(mx0, __shfl_xor_sync(0xffffffffu, mx0, 2));
        mx1 = fmaxf(mx1, __shfl_xor_sync(0xffffffffu, mx1, 1));
        mx1 = fmaxf(mx1, __shfl_xor_sync(0xffffffffu, mx1, 2));
        float mn0 = fmaxf(mi0, mx0), mn1 = fmaxf(mi1, mx1);
        float cr0 = __expf(mi0 - mn0), cr1 = __expf(mi1 - mn1);
        float sum0 = 0.f, sum1 = 0.f;
#pragma unroll
        for (int a = 0; a < 8; a++) {
            s[a][0] = __expf(s[a][0] - mn0);
            s[a][1] = __expf(s[a][1] - mn0);
            s[a][2] = __expf(s[a][2] - mn1);
            s[a][3] = __expf(s[a][3] - mn1);
            sum0 += s[a][0] + s[a][1];
            sum1 += s[a][2] + s[a][3];
        }
        sum0 += __shfl_xor_sync(0xffffffffu, sum0, 1);
        sum0 += __shfl_xor_sync(0xffffffffu, sum0, 2);
        sum1 += __shfl_xor_sync(0xffffffffu, sum1, 1);
        sum1 += __shfl_xor_sync(0xffffffffu, sum1, 2);
        li0 = li0 * cr0 + sum0;  mi0 = mn0;
        li1 = li1 * cr1 + sum1;  mi1 = mn1;
#pragma unroll
        for (int a = 0; a < 8; a++) {
            o[a][0] *= cr0; o[a][1] *= cr0;
            o[a][2] *= cr1; o[a][3] *= cr1;
        }

        // ---- scatter P into packed a-frag layout (warp-local) ----
#pragma unroll
        for (int a = 0; a < 8; a++) {
            float* pe = Pw + a * 132 + ((r << 2) + lc) * 4 + slotb;
            *(float2*)(pe)     = make_float2(tf32r(s[a][0]), tf32r(s[a][2]));
            *(float2*)(pe + 4) = make_float2(tf32r(s[a][1]), tf32r(s[a][3]));
        }
        __syncwarp();

        // ---- O += P @ V (a: LDS.128, b: LDS.64) ----
#pragma unroll
        for (int ks = 0; ks < 8; ks++) {
            uint4 pa = *(const uint4*)(Pw + ks * 132 + (lane << 2));
#pragma unroll
            for (int a = 0; a < 8; a++) {
                uint2 b = *(const uint2*)(Vb + (((a << 3) + ks) << 6) + (lane << 1));
                mma_tf32(o[a], pa.x, pa.y, pa.z, pa.w, b.x, b.y);
            }
        }
    }

    // ---- epilogue: normalize, tf32-round, write ctx row-major [B,S,H*Dh] ----
    float inv0 = 1.f / li0, inv1 = 1.f / li1;
    const int q_lo = q0 + w * 16 + r;
    float* out_lo = g_ctx + ((size_t)batch * S_ + q_lo) * DM_ + head * DH_;
    float* out_hi = out_lo + (size_t)8 * DM_;
#pragma unroll
    for (int a = 0; a < 8; a++) {
        int d = a * 8 + 2 * c;
        *(float2*)(out_lo + d) = make_float2(tf32r(o[a][0] * inv0), tf32r(o[a][1] * inv0));
        *(float2*)(out_hi + d) = make_float2(tf32r(o[a][2] * inv1), tf32r(o[a][3] * inv1));
    }
}

// ---------------- Launch ----------------
extern "C" void kernel_launch(void* const* d_in, const int* in_sizes, int n_in,
                              void* d_out, int out_size)
{
    const float* x  = (const float*)d_in[0];
    const float* Wq = (const float*)d_in[1];
    const float* bq = (const float*)d_in[2];
    const float* Wk = (const float*)d_in[3];
    const float* bk = (const float*)d_in[4];
    const float* Wv = (const float*)d_in[5];
    const float* bv = (const float*)d_in[6];
    const float* Wc = (const float*)d_in[7];
    const float* bc = (const float*)d_in[8];
    float* out = (float*)d_out;

    cudaFuncSetAttribute(attn_tc_kernel,
                         cudaFuncAttributeMaxDynamicSharedMemorySize, ATT_SMEM);

    dim3 gq(MTOT / 128, DM_ / 128, 3);     // 128 x 6 x 3
    qkv_tc_kernel<<<gq, 256>>>(x, Wq, Wk, Wv, bq, bk, bv);

    dim3 ga(S_ / 256, H_, B_);             // 4 x 12 x 16
    attn_tc_kernel<<<ga, 512, ATT_SMEM>>>();

    dim3 gp(MTOT / 128, DM_ / 128);        // 128 x 6
    proj_tc_kernel<<<gp, 256>>>(Wc, bc, out);
}

// round 9
// speedup vs baseline: 1.3979x; 1.1780x over previous
#include <cuda_runtime.h>
#include <cstdint>

#define B_   16
#define S_   1024
#define DM_  768
#define H_   12
#define DH_  64
#define MTOT (B_ * S_)   // 16384
#define HSZ  (S_ * DH_)  // 65536 floats per (b,h)

// Scratch (allocation-free rule: __device__ globals)
// g_q: a-frag layout per (b,h). g_k/g_v: b-frag layout per (b,h). g_ctx: row-major.
__device__ __align__(16) float g_q[(size_t)B_ * H_ * HSZ];
__device__ __align__(16) float g_k[(size_t)B_ * H_ * HSZ];
__device__ __align__(16) float g_v[(size_t)B_ * H_ * HSZ];
__device__ __align__(16) float g_ctx[(size_t)B_ * S_ * DM_];

// ---------------- helpers ----------------
__device__ __forceinline__ float tf32r(float x) {
    uint32_t u;
    asm("cvt.rna.tf32.f32 %0, %1;" : "=r"(u) : "f"(x));
    return __uint_as_float(u);
}

__device__ __forceinline__ void mma_tf32(float c[4],
                                         uint32_t a0, uint32_t a1, uint32_t a2, uint32_t a3,
                                         uint32_t b0, uint32_t b1) {
    asm volatile(
        "mma.sync.aligned.m16n8k8.row.col.f32.tf32.tf32.f32 "
        "{%0,%1,%2,%3}, {%4,%5,%6,%7}, {%8,%9}, {%0,%1,%2,%3};"
        : "+f"(c[0]), "+f"(c[1]), "+f"(c[2]), "+f"(c[3])
        : "r"(a0), "r"(a1), "r"(a2), "r"(a3), "r"(b0), "r"(b1));
}

// ---------------- tensor-core GEMM core (R4-proven) ----------------
#define GBK 32
#define AF_TILES 32
#define BF_TILES 64
#define AF_STRIDE 132
#define BF_STRIDE 68
#define GEMM_SMEM_WORDS (AF_TILES * AF_STRIDE + BF_TILES * BF_STRIDE)  // 8576

__device__ __forceinline__ void tc_gemm_core(const float* __restrict__ A,
                                             const float* __restrict__ W,
                                             int m0, int n0,
                                             uint32_t* Af, uint32_t* Bf,
                                             float acc[4][4][4])
{
    const int tid  = threadIdx.x;
    const int lane = tid & 31;
    const int wid  = tid >> 5;
    const int wm   = wid >> 2;
    const int wn   = wid & 3;

    for (int kt = 0; kt < DM_; kt += GBK) {
        float4 av[4], wv[4];
#pragma unroll
        for (int i = 0; i < 4; i++) {
            int f4  = tid + (i << 8);
            int row = f4 >> 3;
            int kc  = (f4 & 7) << 2;
            av[i] = *(const float4*)(A + (size_t)(m0 + row) * DM_ + kt + kc);
            wv[i] = *(const float4*)(W + (size_t)(n0 + row) * DM_ + kt + kc);
        }
        __syncthreads();
#pragma unroll
        for (int i = 0; i < 4; i++) {
            int f4  = tid + (i << 8);
            int row = f4 >> 3;
            int kc  = (f4 & 7) << 2;
            int ks  = kc >> 3;
            int chi = (kc & 7) >> 2;
            const float* pa = (const float*)&av[i];
            const float* pw = (const float*)&wv[i];
            {
                int mt = row >> 4, rr = row & 15;
                int lb = (rr & 7) << 2;
                int rg = (rr >> 3) + (chi << 1);
                uint32_t* dst = Af + ((mt << 2) + ks) * AF_STRIDE;
#pragma unroll
                for (int j = 0; j < 4; j++)
                    dst[((lb + j) << 2) + rg] = __float_as_uint(tf32r(pa[j]));
            }
            {
                int nt = row >> 3, ln = row & 7;
                int lb = ln << 2;
                uint32_t* dst = Bf + ((nt << 2) + ks) * BF_STRIDE;
#pragma unroll
                for (int j = 0; j < 4; j++)
                    dst[((lb + j) << 1) + chi] = __float_as_uint(tf32r(pw[j]));
            }
        }
        __syncthreads();
#pragma unroll
        for (int ks = 0; ks < 4; ks++) {
            uint4 a[4]; uint2 b[4];
#pragma unroll
            for (int mi = 0; mi < 4; mi++)
                a[mi] = *(const uint4*)(Af + (((wm * 4 + mi) << 2) + ks) * AF_STRIDE + (lane << 2));
#pragma unroll
            for (int ni = 0; ni < 4; ni++)
                b[ni] = *(const uint2*)(Bf + (((wn * 4 + ni) << 2) + ks) * BF_STRIDE + (lane << 1));
#pragma unroll
            for (int mi = 0; mi < 4; mi++)
#pragma unroll
                for (int ni = 0; ni < 4; ni++)
                    mma_tf32(acc[mi][ni], a[mi].x, a[mi].y, a[mi].z, a[mi].w,
                             b[ni].x, b[ni].y);
        }
    }
}

// ---------------- Kernel 1: fused QKV projection ----------------
// Q -> a-frag per (b,h); K,V -> b-frag per (b,h) with AFFINE scatter.
// FIX vs R7/R8: sl is the BATCH-LOCAL sequence index (m0 & 1023), matching
// the R6-proven formulas; the global m0 leaked into the chunk index before.
__global__ void __launch_bounds__(256, 2) qkv_tc_kernel(
    const float* __restrict__ x,
    const float* __restrict__ Wq, const float* __restrict__ Wk,
    const float* __restrict__ Wv,
    const float* __restrict__ bq, const float* __restrict__ bk,
    const float* __restrict__ bv)
{
    __shared__ __align__(16) uint32_t SBUF[GEMM_SMEM_WORDS];
    uint32_t* Af = SBUF;
    uint32_t* Bf = SBUF + AF_TILES * AF_STRIDE;

    const int which = blockIdx.z;
    const float* W    = (which == 0) ? Wq : (which == 1) ? Wk : Wv;
    const float* bias = (which == 0) ? bq : (which == 1) ? bk : bv;

    const int m0 = blockIdx.x * 128;
    const int n0 = blockIdx.y * 128;
    float acc[4][4][4] = {};
    tc_gemm_core(x, W, m0, n0, Af, Bf, acc);

    const int lane = threadIdx.x & 31;
    const int wid  = threadIdx.x >> 5;
    const int wm = wid >> 2, wn = wid & 3;
    const int r = lane >> 2, c2 = (lane & 3) * 2;
    const int bb = m0 >> 10;                  // batch constant per block
    const int s0 = m0 & 1023;                 // batch-local base row (THE FIX)

    if (which == 0) {
        // Q a-frag: tile (mt=s/16, kt=d/8) of 128 words
        const int b0w = ((r << 2) + (c2 & 3)) * 4 + ((c2 >> 2) << 1);
#pragma unroll
        for (int mi = 0; mi < 4; mi++) {
            int s = s0 + wm * 64 + mi * 16;
#pragma unroll
            for (int ni = 0; ni < 4; ni++) {
                int n   = n0 + wn * 32 + ni * 8 + c2;
                int h   = n >> 6;
                int ktl = (n >> 3) & 7;
                float bi0 = bias[n], bi1 = bias[n + 1];
                float* dst = g_q + (size_t)(bb * H_ + h) * HSZ
                                 + ((size_t)(s >> 4) * 8 + ktl) * 128;
                *(float2*)(dst + b0w) =
                    make_float2(tf32r(acc[mi][ni][0] + bi0), tf32r(acc[mi][ni][2] + bi0));
                *(float2*)(dst + b0w + 4) =
                    make_float2(tf32r(acc[mi][ni][1] + bi1), tf32r(acc[mi][ni][3] + bi1));
            }
        }
    } else if (which == 1) {
        // K b-frag: idx = (sl>>6)<<12 | ((sl>>3)&7)<<9 | (d>>3)<<6 | (sl&7)<<3
        //               | (d&3)<<1 | (d>>2)&1 ; offsets: d+1 -> +2, sl+8 -> +512
#pragma unroll
        for (int mi = 0; mi < 4; mi++) {
            int sl = s0 + wm * 64 + mi * 16 + r;          // batch-local
            int slp = ((sl >> 6) << 12) + (((sl >> 3) & 7) << 9) + (r << 3);
#pragma unroll
            for (int ni = 0; ni < 4; ni++) {
                int nf = n0 + wn * 32 + ni * 8 + c2;
                int h = nf >> 6, d = nf & 63;
                float bi0 = bias[nf], bi1 = bias[nf + 1];
                float* dst = g_k + (size_t)(bb * H_ + h) * HSZ + slp
                                 + ((d >> 3) << 6) + ((d & 3) << 1) + ((d >> 2) & 1);
                dst[0]   = tf32r(acc[mi][ni][0] + bi0);
                dst[2]   = tf32r(acc[mi][ni][1] + bi1);
                dst[512] = tf32r(acc[mi][ni][2] + bi0);
                dst[514] = tf32r(acc[mi][ni][3] + bi1);
            }
        }
    } else {
        // V b-frag: idx = (sl>>6)<<12 | (d>>3)<<9 | ((sl>>3)&7)<<6 | (d&7)<<3
        //               | (sl&3)<<1 | (sl>>2)&1 ; offsets: d+1 -> +8, sl+8 -> +64
#pragma unroll
        for (int mi = 0; mi < 4; mi++) {
            int sl = s0 + wm * 64 + mi * 16 + r;          // batch-local
            int slp = ((sl >> 6) << 12) + (((sl >> 3) & 7) << 6) + ((r & 3) << 1) + ((r >> 2) & 1);
#pragma unroll
            for (int ni = 0; ni < 4; ni++) {
                int nf = n0 + wn * 32 + ni * 8 + c2;
                int h = nf >> 6, d = nf & 63;
                float bi0 = bias[nf], bi1 = bias[nf + 1];
                float* dst = g_v + (size_t)(bb * H_ + h) * HSZ + slp
                                 + ((d >> 3) << 9) + ((d & 7) << 3);
                dst[0]  = tf32r(acc[mi][ni][0] + bi0);
                dst[8]  = tf32r(acc[mi][ni][1] + bi1);
                dst[64] = tf32r(acc[mi][ni][2] + bi0);
                dst[72] = tf32r(acc[mi][ni][3] + bi1);
            }
        }
    }
}

// ---------------- Kernel 3: output projection (R4-proven) ----------------
__global__ void __launch_bounds__(256, 2) proj_tc_kernel(
    const float* __restrict__ Wc, const float* __restrict__ bc,
    float* __restrict__ out)
{
    __shared__ __align__(16) uint32_t SBUF[GEMM_SMEM_WORDS];
    uint32_t* Af = SBUF;
    uint32_t* Bf = SBUF + AF_TILES * AF_STRIDE;

    const int m0 = blockIdx.x * 128;
    const int n0 = blockIdx.y * 128;
    float acc[4][4][4] = {};
    tc_gemm_core(g_ctx, Wc, m0, n0, Af, Bf, acc);

    const int lane = threadIdx.x & 31;
    const int wid  = threadIdx.x >> 5;
    const int wm = wid >> 2, wn = wid & 3;
    const int r = lane >> 2, c2 = (lane & 3) * 2;
#pragma unroll
    for (int mi = 0; mi < 4; mi++) {
        int r0 = m0 + wm * 64 + mi * 16 + r;
#pragma unroll
        for (int ni = 0; ni < 4; ni++) {
            int n  = n0 + wn * 32 + ni * 8 + c2;
            float b0 = bc[n], b1 = bc[n + 1];
#pragma unroll
            for (int rr = 0; rr < 2; rr++) {
                int m = r0 + rr * 8;
                float2 o = make_float2(acc[mi][ni][rr * 2 + 0] + b0,
                                       acc[mi][ni][rr * 2 + 1] + b1);
                *(float2*)(out + (size_t)m * DM_ + n) = o;
            }
        }
    }
}

// ---------------- Kernel 2: flash attention (EXACT R6 — proven) ----------------
#define KVS 8192                        // words per stage: 4096 K + 4096 V
#define PFW 1056                        // per-warp P: 8 tiles * 132 words
#define ATT_WORDS (2 * KVS + 16 * PFW)  // 33280
#define ATT_SMEM  (ATT_WORDS * 4)       // 133120 bytes

__global__ void __launch_bounds__(512) attn_tc_kernel()
{
    extern __shared__ float sm[];
    const int tid  = threadIdx.x;
    const int lane = tid & 31, w = tid >> 5;
    const int r = lane >> 2, c = lane & 3;
    const int q0   = blockIdx.x * 256;
    const int head = blockIdx.y, batch = blockIdx.z;
    const size_t base = (size_t)(batch * H_ + head) * HSZ;
    const float* kbf = g_k + base;      // b-frag chunks of 4096 words/iter
    const float* vbf = g_v + base;
    const uint32_t sb = (uint32_t)__cvta_generic_to_shared(sm);

    auto stage = [&](int t, int buf) {
        const float* ksrc = kbf + (size_t)t * 4096;
        const float* vsrc = vbf + (size_t)t * 4096;
#pragma unroll
        for (int i = 0; i < 2; i++) {
            int g = (tid + (i << 9)) << 2;           // float4 offset in words
            uint32_t dst = sb + (uint32_t)(buf * KVS + g) * 4u;
            asm volatile("cp.async.cg.shared.global [%0], [%1], 16;"
                         :: "r"(dst), "l"(ksrc + g));
        }
#pragma unroll
        for (int i = 0; i < 2; i++) {
            int g = (tid + (i << 9)) << 2;
            uint32_t dst = sb + (uint32_t)(buf * KVS + 4096 + g) * 4u;
            asm volatile("cp.async.cg.shared.global [%0], [%1], 16;"
                         :: "r"(dst), "l"(vsrc + g));
        }
        asm volatile("cp.async.commit_group;" ::: "memory");
    };

    stage(0, 0);

    // Q a-fragments: LDG.128 from fragment-layout g_q (proven in R5/R6)
    uint4 qa[8];
    {
        const float* qf = g_q + base + ((size_t)((q0 >> 4) + w) * 8) * 128 + (lane << 2);
#pragma unroll
        for (int ks = 0; ks < 8; ks++)
            qa[ks] = *(const uint4*)(qf + ks * 128);
    }

    float o[8][4];
#pragma unroll
    for (int a = 0; a < 8; a++)
#pragma unroll
        for (int j = 0; j < 4; j++) o[a][j] = 0.f;
    float mi0 = -1e30f, mi1 = -1e30f, li0 = 0.f, li1 = 0.f;

    float* Pw = sm + 2 * KVS + w * PFW;
    const int lc    = (2 * c) & 3;
    const int slotb = (c & 2) ? 2 : 0;

    for (int t = 0; t < S_ / 64; t++) {
        asm volatile("cp.async.wait_group 0;" ::: "memory");
        __syncthreads();
        if (t + 1 < S_ / 64) stage(t + 1, (t + 1) & 1);

        const float* Kb = sm + (t & 1) * KVS;
        const float* Vb = Kb + 4096;

        // ---- S = Q @ K^T (b-frags: single LDS.64 each) ----
        float s[8][4];
#pragma unroll
        for (int a = 0; a < 8; a++)
#pragma unroll
            for (int j = 0; j < 4; j++) s[a][j] = 0.f;
#pragma unroll
        for (int ks = 0; ks < 8; ks++) {
#pragma unroll
            for (int a = 0; a < 8; a++) {
                uint2 b = *(const uint2*)(Kb + (((a << 3) + ks) << 6) + (lane << 1));
                mma_tf32(s[a], qa[ks].x, qa[ks].y, qa[ks].z, qa[ks].w, b.x, b.y);
            }
        }

        // ---- online softmax (rows r, r+8; quad-local reductions) ----
        float mx0 = -1e30f, mx1 = -1e30f;
#pragma unroll
        for (int a = 0; a < 8; a++) {
            s[a][0] *= 0.125f; s[a][1] *= 0.125f;
            s[a][2] *= 0.125f; s[a][3] *= 0.125f;
            mx0 = fmaxf(mx0, fmaxf(s[a][0], s[a][1]));
            mx1 = fmaxf(mx1, fmaxf(s[a][2], s[a][3]));
        }
        mx0 = fmaxf(mx0, __shfl_xor_sync(0xffffffffu, mx0, 1));
        mx0 = fmaxf(mx0, __shfl_xor_sync(0xffffffffu, mx0, 2));
        mx1 = fmaxf(mx1, __shfl_xor_sync(0xffffffffu, mx1, 1));
        mx1 = fmaxf(mx1, __shfl_xor_sync(0xffffffffu, mx1, 2));
        float mn0 = fmaxf(mi0, mx0), mn1 = fmaxf(mi1, mx1);
        float cr0 = __expf(mi0 - mn0), cr1 = __expf(mi1 - mn1);
        float sum0 = 0.f, sum1 = 0.f;
#pragma unroll
        for (int a = 0; a < 8; a++) {
            s[a][0] = __expf(s[a][0] - mn0);
            s[a][1] = __expf(s[a][1] - mn0);
            s[a][2] = __expf(s[a][2] - mn1);
            s[a][3] = __expf(s[a][3] - mn1);
            sum0 += s[a][0] + s[a][1];
            sum1 += s[a][2] + s[a][3];
        }
        sum0 += __shfl_xor_sync(0xffffffffu, sum0, 1);
        sum0 += __shfl_xor_sync(0xffffffffu, sum0, 2);
        sum1 += __shfl_xor_sync(0xffffffffu, sum1, 1);
        sum1 += __shfl_xor_sync(0xffffffffu, sum1, 2);
        li0 = li0 * cr0 + sum0;  mi0 = mn0;
        li1 = li1 * cr1 + sum1;  mi1 = mn1;
#pragma unroll
        for (int a = 0; a < 8; a++) {
            o[a][0] *= cr0; o[a][1] *= cr0;
            o[a][2] *= cr1; o[a][3] *= cr1;
        }

        // ---- scatter P into packed a-frag layout (warp-local) ----
#pragma unroll
        for (int a = 0; a < 8; a++) {
            float* pe = Pw + a * 132 + ((r << 2) + lc) * 4 + slotb;
            *(float2*)(pe)     = make_float2(tf32r(s[a][0]), tf32r(s[a][2]));
            *(float2*)(pe + 4) = make_float2(tf32r(s[a][1]), tf32r(s[a][3]));
        }
        __syncwarp();

        // ---- O += P @ V (a: LDS.128, b: LDS.64) ----
#pragma unroll
        for (int ks = 0; ks < 8; ks++) {
            uint4 pa = *(const uint4*)(Pw + ks * 132 + (lane << 2));
#pragma unroll
            for (int a = 0; a < 8; a++) {
                uint2 b = *(const uint2*)(Vb + (((a << 3) + ks) << 6) + (lane << 1));
                mma_tf32(o[a], pa.x, pa.y, pa.z, pa.w, b.x, b.y);
            }
        }
    }

    // ---- epilogue: normalize, tf32-round, write ctx row-major [B,S,H*Dh] ----
    float inv0 = 1.f / li0, inv1 = 1.f / li1;
    const int q_lo = q0 + w * 16 + r;
    float* out_lo = g_ctx + ((size_t)batch * S_ + q_lo) * DM_ + head * DH_;
    float* out_hi = out_lo + (size_t)8 * DM_;
#pragma unroll
    for (int a = 0; a < 8; a++) {
        int d = a * 8 + 2 * c;
        *(float2*)(out_lo + d) = make_float2(tf32r(o[a][0] * inv0), tf32r(o[a][1] * inv0));
        *(float2*)(out_hi + d) = make_float2(tf32r(o[a][2] * inv1), tf32r(o[a][3] * inv1));
    }
}

// ---------------- Launch ----------------
extern "C" void kernel_launch(void* const* d_in, const int* in_sizes, int n_in,
                              void* d_out, int out_size)
{
    const float* x  = (const float*)d_in[0];
    const float* Wq = (const float*)d_in[1];
    const float* bq = (const float*)d_in[2];
    const float* Wk = (const float*)d_in[3];
    const float* bk = (const float*)d_in[4];
    const float* Wv = (const float*)d_in[5];
    const float* bv = (const float*)d_in[6];
    const float* Wc = (const float*)d_in[7];
    const float* bc = (const float*)d_in[8];
    float* out = (float*)d_out;

    cudaFuncSetAttribute(attn_tc_kernel,
                         cudaFuncAttributeMaxDynamicSharedMemorySize, ATT_SMEM);

    dim3 gq(MTOT / 128, DM_ / 128, 3);     // 128 x 6 x 3
    qkv_tc_kernel<<<gq, 256>>>(x, Wq, Wk, Wv, bq, bk, bv);

    dim3 ga(S_ / 256, H_, B_);             // 4 x 12 x 16
    attn_tc_kernel<<<ga, 512, ATT_SMEM>>>();

    dim3 gp(MTOT / 128, DM_ / 128);        // 128 x 6
    proj_tc_kernel<<<gp, 256>>>(Wc, bc, out);
}

// round 10
// speedup vs baseline: 1.4303x; 1.0232x over previous
#include <cuda_runtime.h>
#include <cstdint>

#define B_   16
#define S_   1024
#define DM_  768
#define H_   12
#define DH_  64
#define MTOT (B_ * S_)   // 16384
#define HSZ  (S_ * DH_)  // 65536 floats per (b,h)

// Scratch (allocation-free rule: __device__ globals)
// g_q: a-frag layout per (b,h). g_k/g_v: b-frag layout per (b,h). g_ctx: row-major.
__device__ __align__(16) float g_q[(size_t)B_ * H_ * HSZ];
__device__ __align__(16) float g_k[(size_t)B_ * H_ * HSZ];
__device__ __align__(16) float g_v[(size_t)B_ * H_ * HSZ];
__device__ __align__(16) float g_ctx[(size_t)B_ * S_ * DM_];

// ---------------- helpers ----------------
__device__ __forceinline__ float tf32r(float x) {
    uint32_t u;
    asm("cvt.rna.tf32.f32 %0, %1;" : "=r"(u) : "f"(x));
    return __uint_as_float(u);
}

__device__ __forceinline__ void mma_tf32(float c[4],
                                         uint32_t a0, uint32_t a1, uint32_t a2, uint32_t a3,
                                         uint32_t b0, uint32_t b1) {
    asm volatile(
        "mma.sync.aligned.m16n8k8.row.col.f32.tf32.tf32.f32 "
        "{%0,%1,%2,%3}, {%4,%5,%6,%7}, {%8,%9}, {%0,%1,%2,%3};"
        : "+f"(c[0]), "+f"(c[1]), "+f"(c[2]), "+f"(c[3])
        : "r"(a0), "r"(a1), "r"(a2), "r"(a3), "r"(b0), "r"(b1));
}

// ---------------- tensor-core GEMM core (R4-proven) ----------------
#define GBK 32
#define AF_TILES 32
#define BF_TILES 64
#define AF_STRIDE 132
#define BF_STRIDE 68
#define GEMM_SMEM_WORDS (AF_TILES * AF_STRIDE + BF_TILES * BF_STRIDE)  // 8576

__device__ __forceinline__ void tc_gemm_core(const float* __restrict__ A,
                                             const float* __restrict__ W,
                                             int m0, int n0,
                                             uint32_t* Af, uint32_t* Bf,
                                             float acc[4][4][4])
{
    const int tid  = threadIdx.x;
    const int lane = tid & 31;
    const int wid  = tid >> 5;
    const int wm   = wid >> 2;
    const int wn   = wid & 3;

    for (int kt = 0; kt < DM_; kt += GBK) {
        float4 av[4], wv[4];
#pragma unroll
        for (int i = 0; i < 4; i++) {
            int f4  = tid + (i << 8);
            int row = f4 >> 3;
            int kc  = (f4 & 7) << 2;
            av[i] = *(const float4*)(A + (size_t)(m0 + row) * DM_ + kt + kc);
            wv[i] = *(const float4*)(W + (size_t)(n0 + row) * DM_ + kt + kc);
        }
        __syncthreads();
#pragma unroll
        for (int i = 0; i < 4; i++) {
            int f4  = tid + (i << 8);
            int row = f4 >> 3;
            int kc  = (f4 & 7) << 2;
            int ks  = kc >> 3;
            int chi = (kc & 7) >> 2;
            const float* pa = (const float*)&av[i];
            const float* pw = (const float*)&wv[i];
            {
                int mt = row >> 4, rr = row & 15;
                int lb = (rr & 7) << 2;
                int rg = (rr >> 3) + (chi << 1);
                uint32_t* dst = Af + ((mt << 2) + ks) * AF_STRIDE;
#pragma unroll
                for (int j = 0; j < 4; j++)
                    dst[((lb + j) << 2) + rg] = __float_as_uint(tf32r(pa[j]));
            }
            {
                int nt = row >> 3, ln = row & 7;
                int lb = ln << 2;
                uint32_t* dst = Bf + ((nt << 2) + ks) * BF_STRIDE;
#pragma unroll
                for (int j = 0; j < 4; j++)
                    dst[((lb + j) << 1) + chi] = __float_as_uint(tf32r(pw[j]));
            }
        }
        __syncthreads();
#pragma unroll
        for (int ks = 0; ks < 4; ks++) {
            uint4 a[4]; uint2 b[4];
#pragma unroll
            for (int mi = 0; mi < 4; mi++)
                a[mi] = *(const uint4*)(Af + (((wm * 4 + mi) << 2) + ks) * AF_STRIDE + (lane << 2));
#pragma unroll
            for (int ni = 0; ni < 4; ni++)
                b[ni] = *(const uint2*)(Bf + (((wn * 4 + ni) << 2) + ks) * BF_STRIDE + (lane << 1));
#pragma unroll
            for (int mi = 0; mi < 4; mi++)
#pragma unroll
                for (int ni = 0; ni < 4; ni++)
                    mma_tf32(acc[mi][ni], a[mi].x, a[mi].y, a[mi].z, a[mi].w,
                             b[ni].x, b[ni].y);
        }
    }
}

// ---------------- Kernel 1: fused QKV projection (EXACT R9 — proven) ----------------
__global__ void __launch_bounds__(256, 2) qkv_tc_kernel(
    const float* __restrict__ x,
    const float* __restrict__ Wq, const float* __restrict__ Wk,
    const float* __restrict__ Wv,
    const float* __restrict__ bq, const float* __restrict__ bk,
    const float* __restrict__ bv)
{
    __shared__ __align__(16) uint32_t SBUF[GEMM_SMEM_WORDS];
    uint32_t* Af = SBUF;
    uint32_t* Bf = SBUF + AF_TILES * AF_STRIDE;

    const int which = blockIdx.z;
    const float* W    = (which == 0) ? Wq : (which == 1) ? Wk : Wv;
    const float* bias = (which == 0) ? bq : (which == 1) ? bk : bv;

    const int m0 = blockIdx.x * 128;
    const int n0 = blockIdx.y * 128;
    float acc[4][4][4] = {};
    tc_gemm_core(x, W, m0, n0, Af, Bf, acc);

    const int lane = threadIdx.x & 31;
    const int wid  = threadIdx.x >> 5;
    const int wm = wid >> 2, wn = wid & 3;
    const int r = lane >> 2, c2 = (lane & 3) * 2;
    const int bb = m0 >> 10;                  // batch constant per block
    const int s0 = m0 & 1023;                 // batch-local base row

    if (which == 0) {
        // Q a-frag: tile (mt=s/16, kt=d/8) of 128 words
        const int b0w = ((r << 2) + (c2 & 3)) * 4 + ((c2 >> 2) << 1);
#pragma unroll
        for (int mi = 0; mi < 4; mi++) {
            int s = s0 + wm * 64 + mi * 16;
#pragma unroll
            for (int ni = 0; ni < 4; ni++) {
                int n   = n0 + wn * 32 + ni * 8 + c2;
                int h   = n >> 6;
                int ktl = (n >> 3) & 7;
                float bi0 = bias[n], bi1 = bias[n + 1];
                float* dst = g_q + (size_t)(bb * H_ + h) * HSZ
                                 + ((size_t)(s >> 4) * 8 + ktl) * 128;
                *(float2*)(dst + b0w) =
                    make_float2(tf32r(acc[mi][ni][0] + bi0), tf32r(acc[mi][ni][2] + bi0));
                *(float2*)(dst + b0w + 4) =
                    make_float2(tf32r(acc[mi][ni][1] + bi1), tf32r(acc[mi][ni][3] + bi1));
            }
        }
    } else if (which == 1) {
        // K b-frag affine scatter (batch-local sl)
#pragma unroll
        for (int mi = 0; mi < 4; mi++) {
            int sl = s0 + wm * 64 + mi * 16 + r;
            int slp = ((sl >> 6) << 12) + (((sl >> 3) & 7) << 9) + (r << 3);
#pragma unroll
            for (int ni = 0; ni < 4; ni++) {
                int nf = n0 + wn * 32 + ni * 8 + c2;
                int h = nf >> 6, d = nf & 63;
                float bi0 = bias[nf], bi1 = bias[nf + 1];
                float* dst = g_k + (size_t)(bb * H_ + h) * HSZ + slp
                                 + ((d >> 3) << 6) + ((d & 3) << 1) + ((d >> 2) & 1);
                dst[0]   = tf32r(acc[mi][ni][0] + bi0);
                dst[2]   = tf32r(acc[mi][ni][1] + bi1);
                dst[512] = tf32r(acc[mi][ni][2] + bi0);
                dst[514] = tf32r(acc[mi][ni][3] + bi1);
            }
        }
    } else {
        // V b-frag affine scatter (batch-local sl)
#pragma unroll
        for (int mi = 0; mi < 4; mi++) {
            int sl = s0 + wm * 64 + mi * 16 + r;
            int slp = ((sl >> 6) << 12) + (((sl >> 3) & 7) << 6) + ((r & 3) << 1) + ((r >> 2) & 1);
#pragma unroll
            for (int ni = 0; ni < 4; ni++) {
                int nf = n0 + wn * 32 + ni * 8 + c2;
                int h = nf >> 6, d = nf & 63;
                float bi0 = bias[nf], bi1 = bias[nf + 1];
                float* dst = g_v + (size_t)(bb * H_ + h) * HSZ + slp
                                 + ((d >> 3) << 9) + ((d & 7) << 3);
                dst[0]  = tf32r(acc[mi][ni][0] + bi0);
                dst[8]  = tf32r(acc[mi][ni][1] + bi1);
                dst[64] = tf32r(acc[mi][ni][2] + bi0);
                dst[72] = tf32r(acc[mi][ni][3] + bi1);
            }
        }
    }
}

// ---------------- Kernel 3: output projection (proven) ----------------
__global__ void __launch_bounds__(256, 2) proj_tc_kernel(
    const float* __restrict__ Wc, const float* __restrict__ bc,
    float* __restrict__ out)
{
    __shared__ __align__(16) uint32_t SBUF[GEMM_SMEM_WORDS];
    uint32_t* Af = SBUF;
    uint32_t* Bf = SBUF + AF_TILES * AF_STRIDE;

    const int m0 = blockIdx.x * 128;
    const int n0 = blockIdx.y * 128;
    float acc[4][4][4] = {};
    tc_gemm_core(g_ctx, Wc, m0, n0, Af, Bf, acc);

    const int lane = threadIdx.x & 31;
    const int wid  = threadIdx.x >> 5;
    const int wm = wid >> 2, wn = wid & 3;
    const int r = lane >> 2, c2 = (lane & 3) * 2;
#pragma unroll
    for (int mi = 0; mi < 4; mi++) {
        int r0 = m0 + wm * 64 + mi * 16 + r;
#pragma unroll
        for (int ni = 0; ni < 4; ni++) {
            int n  = n0 + wn * 32 + ni * 8 + c2;
            float b0 = bc[n], b1 = bc[n + 1];
#pragma unroll
            for (int rr = 0; rr < 2; rr++) {
                int m = r0 + rr * 8;
                float2 o = make_float2(acc[mi][ni][rr * 2 + 0] + b0,
                                       acc[mi][ni][rr * 2 + 1] + b1);
                *(float2*)(out + (size_t)m * DM_ + n) = o;
            }
        }
    }
}

// ---------------- Kernel 2: flash attention (2 m-tiles/warp) ----------------
// 256 queries of one (b,h), 256 threads / 8 warps; warp owns 32 queries
// (2 m-tiles) so each K/V b-frag LDS.64 feeds TWO MMAs (halves smem traffic).
// Q in smem (a-frag, loaded once via cp.async). K/V b-frag, double-buffered.
#define QW   16384                      // Q smem words (16 mtiles * 8 kt * 128)
#define KVS  8192                       // words per stage: 4096 K + 4096 V
#define PFW2 2112                       // per-warp P: 16 tiles * 132 words
#define ATT_WORDS (QW + 2 * KVS + 8 * PFW2)  // 49664
#define ATT_SMEM  (ATT_WORDS * 4)            // 198656 bytes

__global__ void __launch_bounds__(256) attn_tc_kernel()
{
    extern __shared__ float sm[];
    const int tid  = threadIdx.x;
    const int lane = tid & 31, w = tid >> 5;
    const int r = lane >> 2, c = lane & 3;
    const int q0   = blockIdx.x * 256;
    const int head = blockIdx.y, batch = blockIdx.z;
    const size_t base = (size_t)(batch * H_ + head) * HSZ;
    const float* kbf = g_k + base;
    const float* vbf = g_v + base;
    const uint32_t sb = (uint32_t)__cvta_generic_to_shared(sm);

    auto stage = [&](int t, int buf) {
        const float* ksrc = kbf + (size_t)t * 4096;
        const float* vsrc = vbf + (size_t)t * 4096;
#pragma unroll
        for (int i = 0; i < 4; i++) {
            int g = (tid + (i << 8)) << 2;
            uint32_t dst = sb + (uint32_t)(QW + buf * KVS + g) * 4u;
            asm volatile("cp.async.cg.shared.global [%0], [%1], 16;"
                         :: "r"(dst), "l"(ksrc + g));
        }
#pragma unroll
        for (int i = 0; i < 4; i++) {
            int g = (tid + (i << 8)) << 2;
            uint32_t dst = sb + (uint32_t)(QW + buf * KVS + 4096 + g) * 4u;
            asm volatile("cp.async.cg.shared.global [%0], [%1], 16;"
                         :: "r"(dst), "l"(vsrc + g));
        }
        asm volatile("cp.async.commit_group;" ::: "memory");
    };

    // Q tile (contiguous a-frag chunk) + first K/V stage in one async group
    {
        const float* qsrc = g_q + base + (size_t)blockIdx.x * QW;
#pragma unroll
        for (int i = 0; i < 16; i++) {
            int g = (tid + (i << 8)) << 2;
            uint32_t dst = sb + (uint32_t)g * 4u;
            asm volatile("cp.async.cg.shared.global [%0], [%1], 16;"
                         :: "r"(dst), "l"(qsrc + g));
        }
    }
    stage(0, 0);

    float o[2][8][4];
#pragma unroll
    for (int mt = 0; mt < 2; mt++)
#pragma unroll
        for (int a = 0; a < 8; a++)
#pragma unroll
            for (int j = 0; j < 4; j++) o[mt][a][j] = 0.f;
    float mi_[2][2] = {{-1e30f, -1e30f}, {-1e30f, -1e30f}};
    float li_[2][2] = {{0.f, 0.f}, {0.f, 0.f}};

    float* Pw = sm + QW + 2 * KVS + w * PFW2;
    const float* Qs = sm + w * 2048;          // this warp's 2 m-tiles
    const int lc    = (2 * c) & 3;
    const int slotb = (c & 2) ? 2 : 0;

    for (int t = 0; t < S_ / 64; t++) {
        asm volatile("cp.async.wait_group 0;" ::: "memory");
        __syncthreads();
        if (t + 1 < S_ / 64) stage(t + 1, (t + 1) & 1);

        const float* Kb = sm + QW + (t & 1) * KVS;
        const float* Vb = Kb + 4096;

        // ---- S = Q @ K^T (K b-frag reused across both m-tiles) ----
        float s[2][8][4];
#pragma unroll
        for (int mt = 0; mt < 2; mt++)
#pragma unroll
            for (int a = 0; a < 8; a++)
#pragma unroll
                for (int j = 0; j < 4; j++) s[mt][a][j] = 0.f;
#pragma unroll
        for (int ks = 0; ks < 8; ks++) {
            uint4 qa0 = *(const uint4*)(Qs + ks * 128 + (lane << 2));
            uint4 qa1 = *(const uint4*)(Qs + 1024 + ks * 128 + (lane << 2));
#pragma unroll
            for (int a = 0; a < 8; a++) {
                uint2 kb2 = *(const uint2*)(Kb + (((a << 3) + ks) << 6) + (lane << 1));
                mma_tf32(s[0][a], qa0.x, qa0.y, qa0.z, qa0.w, kb2.x, kb2.y);
                mma_tf32(s[1][a], qa1.x, qa1.y, qa1.z, qa1.w, kb2.x, kb2.y);
            }
        }

        // ---- online softmax + P scatter per m-tile ----
#pragma unroll
        for (int mt = 0; mt < 2; mt++) {
            float mx0 = -1e30f, mx1 = -1e30f;
#pragma unroll
            for (int a = 0; a < 8; a++) {
                s[mt][a][0] *= 0.125f; s[mt][a][1] *= 0.125f;
                s[mt][a][2] *= 0.125f; s[mt][a][3] *= 0.125f;
                mx0 = fmaxf(mx0, fmaxf(s[mt][a][0], s[mt][a][1]));
                mx1 = fmaxf(mx1, fmaxf(s[mt][a][2], s[mt][a][3]));
            }
            mx0 = fmaxf(mx0, __shfl_xor_sync(0xffffffffu, mx0, 1));
            mx0 = fmaxf(mx0, __shfl_xor_sync(0xffffffffu, mx0, 2));
            mx1 = fmaxf(mx1, __shfl_xor_sync(0xffffffffu, mx1, 1));
            mx1 = fmaxf(mx1, __shfl_xor_sync(0xffffffffu, mx1, 2));
            float mn0 = fmaxf(mi_[mt][0], mx0), mn1 = fmaxf(mi_[mt][1], mx1);
            float cr0 = __expf(mi_[mt][0] - mn0), cr1 = __expf(mi_[mt][1] - mn1);
            float sum0 = 0.f, sum1 = 0.f;
#pragma unroll
            for (int a = 0; a < 8; a++) {
                s[mt][a][0] = __expf(s[mt][a][0] - mn0);
                s[mt][a][1] = __expf(s[mt][a][1] - mn0);
                s[mt][a][2] = __expf(s[mt][a][2] - mn1);
                s[mt][a][3] = __expf(s[mt][a][3] - mn1);
                sum0 += s[mt][a][0] + s[mt][a][1];
                sum1 += s[mt][a][2] + s[mt][a][3];
            }
            sum0 += __shfl_xor_sync(0xffffffffu, sum0, 1);
            sum0 += __shfl_xor_sync(0xffffffffu, sum0, 2);
            sum1 += __shfl_xor_sync(0xffffffffu, sum1, 1);
            sum1 += __shfl_xor_sync(0xffffffffu, sum1, 2);
            li_[mt][0] = li_[mt][0] * cr0 + sum0;  mi_[mt][0] = mn0;
            li_[mt][1] = li_[mt][1] * cr1 + sum1;  mi_[mt][1] = mn1;
#pragma unroll
            for (int a = 0; a < 8; a++) {
                o[mt][a][0] *= cr0; o[mt][a][1] *= cr0;
                o[mt][a][2] *= cr1; o[mt][a][3] *= cr1;
            }
#pragma unroll
            for (int a = 0; a < 8; a++) {
                float* pe = Pw + ((mt << 3) + a) * 132 + ((r << 2) + lc) * 4 + slotb;
                *(float2*)(pe)     = make_float2(tf32r(s[mt][a][0]), tf32r(s[mt][a][2]));
                *(float2*)(pe + 4) = make_float2(tf32r(s[mt][a][1]), tf32r(s[mt][a][3]));
            }
        }
        __syncwarp();

        // ---- O += P @ V (V b-frag reused across both m-tiles) ----
#pragma unroll
        for (int ks = 0; ks < 8; ks++) {
            uint4 pa0 = *(const uint4*)(Pw + ks * 132 + (lane << 2));
            uint4 pa1 = *(const uint4*)(Pw + (8 + ks) * 132 + (lane << 2));
#pragma unroll
            for (int a = 0; a < 8; a++) {
                uint2 vb2 = *(const uint2*)(Vb + (((a << 3) + ks) << 6) + (lane << 1));
                mma_tf32(o[0][a], pa0.x, pa0.y, pa0.z, pa0.w, vb2.x, vb2.y);
                mma_tf32(o[1][a], pa1.x, pa1.y, pa1.z, pa1.w, vb2.x, vb2.y);
            }
        }
    }

    // ---- epilogue: normalize, tf32-round, write ctx row-major [B,S,H*Dh] ----
#pragma unroll
    for (int mt = 0; mt < 2; mt++) {
        float inv0 = 1.f / li_[mt][0], inv1 = 1.f / li_[mt][1];
        const int q_lo = q0 + w * 32 + mt * 16 + r;
        float* out_lo = g_ctx + ((size_t)batch * S_ + q_lo) * DM_ + head * DH_;
        float* out_hi = out_lo + (size_t)8 * DM_;
#pragma unroll
        for (int a = 0; a < 8; a++) {
            int d = a * 8 + 2 * c;
            *(float2*)(out_lo + d) = make_float2(tf32r(o[mt][a][0] * inv0),
                                                 tf32r(o[mt][a][1] * inv0));
            *(float2*)(out_hi + d) = make_float2(tf32r(o[mt][a][2] * inv1),
                                                 tf32r(o[mt][a][3] * inv1));
        }
    }
}

// ---------------- Launch ----------------
extern "C" void kernel_launch(void* const* d_in, const int* in_sizes, int n_in,
                              void* d_out, int out_size)
{
    const float* x  = (const float*)d_in[0];
    const float* Wq = (const float*)d_in[1];
    const float* bq = (const float*)d_in[2];
    const float* Wk = (const float*)d_in[3];
    const float* bk = (const float*)d_in[4];
    const float* Wv = (const float*)d_in[5];
    const float* bv = (const float*)d_in[6];
    const float* Wc = (const float*)d_in[7];
    const float* bc = (const float*)d_in[8];
    float* out = (float*)d_out;

    cudaFuncSetAttribute(attn_tc_kernel,
                         cudaFuncAttributeMaxDynamicSharedMemorySize, ATT_SMEM);

    dim3 gq(MTOT / 128, DM_ / 128, 3);     // 128 x 6 x 3
    qkv_tc_kernel<<<gq, 256>>>(x, Wq, Wk, Wv, bq, bk, bv);

    dim3 ga(S_ / 256, H_, B_);             // 4 x 12 x 16
    attn_tc_kernel<<<ga, 256, ATT_SMEM>>>();

    dim3 gp(MTOT / 128, DM_ / 128);        // 128 x 6
    proj_tc_kernel<<<gp, 256>>>(Wc, bc, out);
}

// round 11
// speedup vs baseline: 1.5660x; 1.0949x over previous
#include <cuda_runtime.h>
#include <cstdint>

#define B_   16
#define S_   1024
#define DM_  768
#define H_   12
#define DH_  64
#define MTOT (B_ * S_)   // 16384
#define HSZ  (S_ * DH_)  // 65536 floats per (b,h)
#define WSZ  589824      // 768*768

// Scratch (allocation-free rule: __device__ globals)
__device__ __align__(16) float g_q[(size_t)B_ * H_ * HSZ];   // a-frag per (b,h)
__device__ __align__(16) float g_k[(size_t)B_ * H_ * HSZ];   // b-frag per (b,h)
__device__ __align__(16) float g_v[(size_t)B_ * H_ * HSZ];   // b-frag per (b,h)
__device__ __align__(16) float g_ctx[(size_t)B_ * S_ * DM_]; // row-major
__device__ __align__(16) float g_xf[(size_t)MTOT * DM_];     // a-frag x (tf32-RN)
__device__ __align__(16) float g_wf[(size_t)3 * WSZ];        // b-frag Wq,Wk,Wv (tf32-RN)

// ---------------- helpers ----------------
__device__ __forceinline__ float tf32r(float x) {
    uint32_t u;
    asm("cvt.rna.tf32.f32 %0, %1;" : "=r"(u) : "f"(x));
    return __uint_as_float(u);
}

__device__ __forceinline__ void mma_tf32(float c[4],
                                         uint32_t a0, uint32_t a1, uint32_t a2, uint32_t a3,
                                         uint32_t b0, uint32_t b1) {
    asm volatile(
        "mma.sync.aligned.m16n8k8.row.col.f32.tf32.tf32.f32 "
        "{%0,%1,%2,%3}, {%4,%5,%6,%7}, {%8,%9}, {%0,%1,%2,%3};"
        : "+f"(c[0]), "+f"(c[1]), "+f"(c[2]), "+f"(c[3])
        : "r"(a0), "r"(a1), "r"(a2), "r"(a3), "r"(b0), "r"(b1));
}

// ---------------- pre-swizzle kernels (R5-proven, tf32-RN fused) ----------------
__global__ void swizzle_a_kernel(const float4* __restrict__ src, float* __restrict__ dst) {
    int i = blockIdx.x * 256 + threadIdx.x;          // one float4 of [M][768]
    float4 v = src[i];
    int row = i / (DM_ / 4);
    int kc  = (i % (DM_ / 4)) * 4;
    int mt = row >> 4, rowt = row & 15, kt = kc >> 3, chi = (kc >> 2) & 1;
    float* d = dst + ((size_t)mt * 96 + kt) * 128
                   + ((rowt & 7) << 4) + (rowt >> 3) + (chi << 1);
    d[0]  = tf32r(v.x);
    d[4]  = tf32r(v.y);
    d[8]  = tf32r(v.z);
    d[12] = tf32r(v.w);
}

__global__ void swizzle_b_kernel(const float4* __restrict__ W0,
                                 const float4* __restrict__ W1,
                                 const float4* __restrict__ W2) {
    int w = blockIdx.y;
    const float4* src = (w == 0) ? W0 : (w == 1) ? W1 : W2;
    int i = blockIdx.x * 256 + threadIdx.x;          // one float4 of [768][768]
    float4 v = src[i];
    int n  = i / (DM_ / 4);
    int kc = (i % (DM_ / 4)) * 4;
    int nt = n >> 3, kt = kc >> 3, chi = (kc >> 2) & 1;
    float* d = g_wf + (size_t)w * WSZ + ((size_t)nt * 96 + kt) * 64
                    + ((n & 7) << 3) + chi;
    d[0] = tf32r(v.x);
    d[2] = tf32r(v.y);
    d[4] = tf32r(v.z);
    d[6] = tf32r(v.w);
}

// ---------------- fragment-direct pipelined GEMM core (qkv only) ----------------
// A (g_xf) and B (g_wf) already in frag layout in gmem. Block 128x128, BK=32,
// 3-stage cp.async (32KB/stage, 96KB), 256 threads, 1 sync per k-step.
#define STGW 8192                        // words/stage: 4096 A + 4096 B
#define QKV_SMEM (3 * STGW * 4)          // 98304 bytes

__device__ __forceinline__ void tc_gemm_frag(const float* __restrict__ Ag,
                                             const float* __restrict__ Bg,
                                             int m0, int n0, float* smem,
                                             float acc[4][4][4])
{
    const int tid  = threadIdx.x;
    const int lane = tid & 31;
    const int wid  = tid >> 5;
    const int wm   = wid >> 2;
    const int wn   = wid & 3;
    const uint32_t sb = (uint32_t)__cvta_generic_to_shared(smem);

    // Per-thread source pointers (advance by constant stride per stage)
    const float* srcA[4];
    const float* srcB[4];
    uint32_t dstA[4], dstB[4];
#pragma unroll
    for (int i = 0; i < 4; i++) {
        int idx = tid + (i << 8);                    // 0..1023 float4s
        srcA[i] = Ag + ((size_t)((m0 >> 4) + (idx >> 7)) * 96) * 128 + ((idx & 127) << 2);
        dstA[i] = (uint32_t)(((idx >> 7) << 9) + ((idx & 127) << 2));
        srcB[i] = Bg + ((size_t)((n0 >> 3) + (idx >> 6)) * 96) * 64 + ((idx & 63) << 2);
        dstB[i] = (uint32_t)(4096 + ((idx >> 6) << 8) + ((idx & 63) << 2));
    }

    auto pf = [&](int kt, int buf) {
        uint32_t bbase = sb + (uint32_t)(buf * STGW) * 4u;
#pragma unroll
        for (int i = 0; i < 4; i++) {
            asm volatile("cp.async.cg.shared.global [%0], [%1], 16;"
                         :: "r"(bbase + dstA[i] * 4u), "l"(srcA[i] + (size_t)kt * 512));
            asm volatile("cp.async.cg.shared.global [%0], [%1], 16;"
                         :: "r"(bbase + dstB[i] * 4u), "l"(srcB[i] + (size_t)kt * 256));
        }
        asm volatile("cp.async.commit_group;" ::: "memory");
    };

    pf(0, 0); pf(1, 1);
    for (int kt = 0; kt < 24; kt++) {
        if (kt < 23) asm volatile("cp.async.wait_group 1;" ::: "memory");
        else         asm volatile("cp.async.wait_group 0;" ::: "memory");
        __syncthreads();                 // stage kt ready; also fences reuse of buf (kt+2)%3
        if (kt + 2 < 24) pf(kt + 2, (kt + 2) % 3);

        const uint32_t* sA = (const uint32_t*)smem + (kt % 3) * STGW;
        const uint32_t* sB = sA + 4096;
#pragma unroll
        for (int ks = 0; ks < 4; ks++) {
            uint4 a[4]; uint2 b[4];
#pragma unroll
            for (int mi = 0; mi < 4; mi++)
                a[mi] = *(const uint4*)(sA + (((wm * 4 + mi) << 2) + ks) * 128 + (lane << 2));
#pragma unroll
            for (int ni = 0; ni < 4; ni++)
                b[ni] = *(const uint2*)(sB + (((wn * 4 + ni) << 2) + ks) * 64 + (lane << 1));
#pragma unroll
            for (int mi = 0; mi < 4; mi++)
#pragma unroll
                for (int ni = 0; ni < 4; ni++)
                    mma_tf32(acc[mi][ni], a[mi].x, a[mi].y, a[mi].z, a[mi].w,
                             b[ni].x, b[ni].y);
        }
    }
}

// ---------------- Kernel 1: fused QKV projection (epilogues = R10-proven) ----------------
__global__ void __launch_bounds__(256, 2) qkv_tc_kernel(
    const float* __restrict__ bq, const float* __restrict__ bk,
    const float* __restrict__ bv)
{
    extern __shared__ float smem[];
    const int which = blockIdx.z;
    const float* bias = (which == 0) ? bq : (which == 1) ? bk : bv;

    const int m0 = blockIdx.x * 128;
    const int n0 = blockIdx.y * 128;
    float acc[4][4][4] = {};
    tc_gemm_frag(g_xf, g_wf + (size_t)which * WSZ, m0, n0, smem, acc);

    const int lane = threadIdx.x & 31;
    const int wid  = threadIdx.x >> 5;
    const int wm = wid >> 2, wn = wid & 3;
    const int r = lane >> 2, c2 = (lane & 3) * 2;
    const int bb = m0 >> 10;                  // batch constant per block
    const int s0 = m0 & 1023;                 // batch-local base row

    if (which == 0) {
        // Q a-frag: tile (mt=s/16, kt=d/8) of 128 words
        const int b0w = ((r << 2) + (c2 & 3)) * 4 + ((c2 >> 2) << 1);
#pragma unroll
        for (int mi = 0; mi < 4; mi++) {
            int s = s0 + wm * 64 + mi * 16;
#pragma unroll
            for (int ni = 0; ni < 4; ni++) {
                int n   = n0 + wn * 32 + ni * 8 + c2;
                int h   = n >> 6;
                int ktl = (n >> 3) & 7;
                float bi0 = bias[n], bi1 = bias[n + 1];
                float* dst = g_q + (size_t)(bb * H_ + h) * HSZ
                                 + ((size_t)(s >> 4) * 8 + ktl) * 128;
                *(float2*)(dst + b0w) =
                    make_float2(tf32r(acc[mi][ni][0] + bi0), tf32r(acc[mi][ni][2] + bi0));
                *(float2*)(dst + b0w + 4) =
                    make_float2(tf32r(acc[mi][ni][1] + bi1), tf32r(acc[mi][ni][3] + bi1));
            }
        }
    } else if (which == 1) {
        // K b-frag affine scatter (batch-local sl)
#pragma unroll
        for (int mi = 0; mi < 4; mi++) {
            int sl = s0 + wm * 64 + mi * 16 + r;
            int slp = ((sl >> 6) << 12) + (((sl >> 3) & 7) << 9) + (r << 3);
#pragma unroll
            for (int ni = 0; ni < 4; ni++) {
                int nf = n0 + wn * 32 + ni * 8 + c2;
                int h = nf >> 6, d = nf & 63;
                float bi0 = bias[nf], bi1 = bias[nf + 1];
                float* dst = g_k + (size_t)(bb * H_ + h) * HSZ + slp
                                 + ((d >> 3) << 6) + ((d & 3) << 1) + ((d >> 2) & 1);
                dst[0]   = tf32r(acc[mi][ni][0] + bi0);
                dst[2]   = tf32r(acc[mi][ni][1] + bi1);
                dst[512] = tf32r(acc[mi][ni][2] + bi0);
                dst[514] = tf32r(acc[mi][ni][3] + bi1);
            }
        }
    } else {
        // V b-frag affine scatter (batch-local sl)
#pragma unroll
        for (int mi = 0; mi < 4; mi++) {
            int sl = s0 + wm * 64 + mi * 16 + r;
            int slp = ((sl >> 6) << 12) + (((sl >> 3) & 7) << 6) + ((r & 3) << 1) + ((r >> 2) & 1);
#pragma unroll
            for (int ni = 0; ni < 4; ni++) {
                int nf = n0 + wn * 32 + ni * 8 + c2;
                int h = nf >> 6, d = nf & 63;
                float bi0 = bias[nf], bi1 = bias[nf + 1];
                float* dst = g_v + (size_t)(bb * H_ + h) * HSZ + slp
                                 + ((d >> 3) << 9) + ((d & 7) << 3);
                dst[0]  = tf32r(acc[mi][ni][0] + bi0);
                dst[8]  = tf32r(acc[mi][ni][1] + bi1);
                dst[64] = tf32r(acc[mi][ni][2] + bi0);
                dst[72] = tf32r(acc[mi][ni][3] + bi1);
            }
        }
    }
}

// ---------------- Kernel 3: output projection (EXACT R10 — proven) ----------------
#define GBK 32
#define AF_TILES 32
#define BF_TILES 64
#define AF_STRIDE 132
#define BF_STRIDE 68
#define GEMM_SMEM_WORDS (AF_TILES * AF_STRIDE + BF_TILES * BF_STRIDE)  // 8576

__device__ __forceinline__ void tc_gemm_core(const float* __restrict__ A,
                                             const float* __restrict__ W,
                                             int m0, int n0,
                                             uint32_t* Af, uint32_t* Bf,
                                             float acc[4][4][4])
{
    const int tid  = threadIdx.x;
    const int lane = tid & 31;
    const int wid  = tid >> 5;
    const int wm   = wid >> 2;
    const int wn   = wid & 3;

    for (int kt = 0; kt < DM_; kt += GBK) {
        float4 av[4], wv[4];
#pragma unroll
        for (int i = 0; i < 4; i++) {
            int f4  = tid + (i << 8);
            int row = f4 >> 3;
            int kc  = (f4 & 7) << 2;
            av[i] = *(const float4*)(A + (size_t)(m0 + row) * DM_ + kt + kc);
            wv[i] = *(const float4*)(W + (size_t)(n0 + row) * DM_ + kt + kc);
        }
        __syncthreads();
#pragma unroll
        for (int i = 0; i < 4; i++) {
            int f4  = tid + (i << 8);
            int row = f4 >> 3;
            int kc  = (f4 & 7) << 2;
            int ks  = kc >> 3;
            int chi = (kc & 7) >> 2;
            const float* pa = (const float*)&av[i];
            const float* pw = (const float*)&wv[i];
            {
                int mt = row >> 4, rr = row & 15;
                int lb = (rr & 7) << 2;
                int rg = (rr >> 3) + (chi << 1);
                uint32_t* dst = Af + ((mt << 2) + ks) * AF_STRIDE;
#pragma unroll
                for (int j = 0; j < 4; j++)
                    dst[((lb + j) << 2) + rg] = __float_as_uint(tf32r(pa[j]));
            }
            {
                int nt = row >> 3, ln = row & 7;
                int lb = ln << 2;
                uint32_t* dst = Bf + ((nt << 2) + ks) * BF_STRIDE;
#pragma unroll
                for (int j = 0; j < 4; j++)
                    dst[((lb + j) << 1) + chi] = __float_as_uint(tf32r(pw[j]));
            }
        }
        __syncthreads();
#pragma unroll
        for (int ks = 0; ks < 4; ks++) {
            uint4 a[4]; uint2 b[4];
#pragma unroll
            for (int mi = 0; mi < 4; mi++)
                a[mi] = *(const uint4*)(Af + (((wm * 4 + mi) << 2) + ks) * AF_STRIDE + (lane << 2));
#pragma unroll
            for (int ni = 0; ni < 4; ni++)
                b[ni] = *(const uint2*)(Bf + (((wn * 4 + ni) << 2) + ks) * BF_STRIDE + (lane << 1));
#pragma unroll
            for (int mi = 0; mi < 4; mi++)
#pragma unroll
                for (int ni = 0; ni < 4; ni++)
                    mma_tf32(acc[mi][ni], a[mi].x, a[mi].y, a[mi].z, a[mi].w,
                             b[ni].x, b[ni].y);
        }
    }
}

__global__ void __launch_bounds__(256, 2) proj_tc_kernel(
    const float* __restrict__ Wc, const float* __restrict__ bc,
    float* __restrict__ out)
{
    __shared__ __align__(16) uint32_t SBUF[GEMM_SMEM_WORDS];
    uint32_t* Af = SBUF;
    uint32_t* Bf = SBUF + AF_TILES * AF_STRIDE;

    const int m0 = blockIdx.x * 128;
    const int n0 = blockIdx.y * 128;
    float acc[4][4][4] = {};
    tc_gemm_core(g_ctx, Wc, m0, n0, Af, Bf, acc);

    const int lane = threadIdx.x & 31;
    const int wid  = threadIdx.x >> 5;
    const int wm = wid >> 2, wn = wid & 3;
    const int r = lane >> 2, c2 = (lane & 3) * 2;
#pragma unroll
    for (int mi = 0; mi < 4; mi++) {
        int r0 = m0 + wm * 64 + mi * 16 + r;
#pragma unroll
        for (int ni = 0; ni < 4; ni++) {
            int n  = n0 + wn * 32 + ni * 8 + c2;
            float b0 = bc[n], b1 = bc[n + 1];
#pragma unroll
            for (int rr = 0; rr < 2; rr++) {
                int m = r0 + rr * 8;
                float2 o = make_float2(acc[mi][ni][rr * 2 + 0] + b0,
                                       acc[mi][ni][rr * 2 + 1] + b1);
                *(float2*)(out + (size_t)m * DM_ + n) = o;
            }
        }
    }
}

// ---------------- Kernel 2: flash attention (EXACT R10 — proven) ----------------
#define QW   16384
#define KVS  8192
#define PFW2 2112
#define ATT_WORDS (QW + 2 * KVS + 8 * PFW2)  // 49664
#define ATT_SMEM  (ATT_WORDS * 4)            // 198656 bytes

__global__ void __launch_bounds__(256) attn_tc_kernel()
{
    extern __shared__ float sm[];
    const int tid  = threadIdx.x;
    const int lane = tid & 31, w = tid >> 5;
    const int r = lane >> 2, c = lane & 3;
    const int q0   = blockIdx.x * 256;
    const int head = blockIdx.y, batch = blockIdx.z;
    const size_t base = (size_t)(batch * H_ + head) * HSZ;
    const float* kbf = g_k + base;
    const float* vbf = g_v + base;
    const uint32_t sb = (uint32_t)__cvta_generic_to_shared(sm);

    auto stage = [&](int t, int buf) {
        const float* ksrc = kbf + (size_t)t * 4096;
        const float* vsrc = vbf + (size_t)t * 4096;
#pragma unroll
        for (int i = 0; i < 4; i++) {
            int g = (tid + (i << 8)) << 2;
            uint32_t dst = sb + (uint32_t)(QW + buf * KVS + g) * 4u;
            asm volatile("cp.async.cg.shared.global [%0], [%1], 16;"
                         :: "r"(dst), "l"(ksrc + g));
        }
#pragma unroll
        for (int i = 0; i < 4; i++) {
            int g = (tid + (i << 8)) << 2;
            uint32_t dst = sb + (uint32_t)(QW + buf * KVS + 4096 + g) * 4u;
            asm volatile("cp.async.cg.shared.global [%0], [%1], 16;"
                         :: "r"(dst), "l"(vsrc + g));
        }
        asm volatile("cp.async.commit_group;" ::: "memory");
    };

    {
        const float* qsrc = g_q + base + (size_t)blockIdx.x * QW;
#pragma unroll
        for (int i = 0; i < 16; i++) {
            int g = (tid + (i << 8)) << 2;
            uint32_t dst = sb + (uint32_t)g * 4u;
            asm volatile("cp.async.cg.shared.global [%0], [%1], 16;"
                         :: "r"(dst), "l"(qsrc + g));
        }
    }
    stage(0, 0);

    float o[2][8][4];
#pragma unroll
    for (int mt = 0; mt < 2; mt++)
#pragma unroll
        for (int a = 0; a < 8; a++)
#pragma unroll
            for (int j = 0; j < 4; j++) o[mt][a][j] = 0.f;
    float mi_[2][2] = {{-1e30f, -1e30f}, {-1e30f, -1e30f}};
    float li_[2][2] = {{0.f, 0.f}, {0.f, 0.f}};

    float* Pw = sm + QW + 2 * KVS + w * PFW2;
    const float* Qs = sm + w * 2048;
    const int lc    = (2 * c) & 3;
    const int slotb = (c & 2) ? 2 : 0;

    for (int t = 0; t < S_ / 64; t++) {
        asm volatile("cp.async.wait_group 0;" ::: "memory");
        __syncthreads();
        if (t + 1 < S_ / 64) stage(t + 1, (t + 1) & 1);

        const float* Kb = sm + QW + (t & 1) * KVS;
        const float* Vb = Kb + 4096;

        float s[2][8][4];
#pragma unroll
        for (int mt = 0; mt < 2; mt++)
#pragma unroll
            for (int a = 0; a < 8; a++)
#pragma unroll
                for (int j = 0; j < 4; j++) s[mt][a][j] = 0.f;
#pragma unroll
        for (int ks = 0; ks < 8; ks++) {
            uint4 qa0 = *(const uint4*)(Qs + ks * 128 + (lane << 2));
            uint4 qa1 = *(const uint4*)(Qs + 1024 + ks * 128 + (lane << 2));
#pragma unroll
            for (int a = 0; a < 8; a++) {
                uint2 kb2 = *(const uint2*)(Kb + (((a << 3) + ks) << 6) + (lane << 1));
                mma_tf32(s[0][a], qa0.x, qa0.y, qa0.z, qa0.w, kb2.x, kb2.y);
                mma_tf32(s[1][a], qa1.x, qa1.y, qa1.z, qa1.w, kb2.x, kb2.y);
            }
        }

#pragma unroll
        for (int mt = 0; mt < 2; mt++) {
            float mx0 = -1e30f, mx1 = -1e30f;
#pragma unroll
            for (int a = 0; a < 8; a++) {
                s[mt][a][0] *= 0.125f; s[mt][a][1] *= 0.125f;
                s[mt][a][2] *= 0.125f; s[mt][a][3] *= 0.125f;
                mx0 = fmaxf(mx0, fmaxf(s[mt][a][0], s[mt][a][1]));
                mx1 = fmaxf(mx1, fmaxf(s[mt][a][2], s[mt][a][3]));
            }
            mx0 = fmaxf(mx0, __shfl_xor_sync(0xffffffffu, mx0, 1));
            mx0 = fmaxf(mx0, __shfl_xor_sync(0xffffffffu, mx0, 2));
            mx1 = fmaxf(mx1, __shfl_xor_sync(0xffffffffu, mx1, 1));
            mx1 = fmaxf(mx1, __shfl_xor_sync(0xffffffffu, mx1, 2));
            float mn0 = fmaxf(mi_[mt][0], mx0), mn1 = fmaxf(mi_[mt][1], mx1);
            float cr0 = __expf(mi_[mt][0] - mn0), cr1 = __expf(mi_[mt][1] - mn1);
            float sum0 = 0.f, sum1 = 0.f;
#pragma unroll
            for (int a = 0; a < 8; a++) {
                s[mt][a][0] = __expf(s[mt][a][0] - mn0);
                s[mt][a][1] = __expf(s[mt][a][1] - mn0);
                s[mt][a][2] = __expf(s[mt][a][2] - mn1);
                s[mt][a][3] = __expf(s[mt][a][3] - mn1);
                sum0 += s[mt][a][0] + s[mt][a][1];
                sum1 += s[mt][a][2] + s[mt][a][3];
            }
            sum0 += __shfl_xor_sync(0xffffffffu, sum0, 1);
            sum0 += __shfl_xor_sync(0xffffffffu, sum0, 2);
            sum1 += __shfl_xor_sync(0xffffffffu, sum1, 1);
            sum1 += __shfl_xor_sync(0xffffffffu, sum1, 2);
            li_[mt][0] = li_[mt][0] * cr0 + sum0;  mi_[mt][0] = mn0;
            li_[mt][1] = li_[mt][1] * cr1 + sum1;  mi_[mt][1] = mn1;
#pragma unroll
            for (int a = 0; a < 8; a++) {
                o[mt][a][0] *= cr0; o[mt][a][1] *= cr0;
                o[mt][a][2] *= cr1; o[mt][a][3] *= cr1;
            }
#pragma unroll
            for (int a = 0; a < 8; a++) {
                float* pe = Pw + ((mt << 3) + a) * 132 + ((r << 2) + lc) * 4 + slotb;
                *(float2*)(pe)     = make_float2(tf32r(s[mt][a][0]), tf32r(s[mt][a][2]));
                *(float2*)(pe + 4) = make_float2(tf32r(s[mt][a][1]), tf32r(s[mt][a][3]));
            }
        }
        __syncwarp();

#pragma unroll
        for (int ks = 0; ks < 8; ks++) {
            uint4 pa0 = *(const uint4*)(Pw + ks * 132 + (lane << 2));
            uint4 pa1 = *(const uint4*)(Pw + (8 + ks) * 132 + (lane << 2));
#pragma unroll
            for (int a = 0; a < 8; a++) {
                uint2 vb2 = *(const uint2*)(Vb + (((a << 3) + ks) << 6) + (lane << 1));
                mma_tf32(o[0][a], pa0.x, pa0.y, pa0.z, pa0.w, vb2.x, vb2.y);
                mma_tf32(o[1][a], pa1.x, pa1.y, pa1.z, pa1.w, vb2.x, vb2.y);
            }
        }
    }

#pragma unroll
    for (int mt = 0; mt < 2; mt++) {
        float inv0 = 1.f / li_[mt][0], inv1 = 1.f / li_[mt][1];
        const int q_lo = q0 + w * 32 + mt * 16 + r;
        float* out_lo = g_ctx + ((size_t)batch * S_ + q_lo) * DM_ + head * DH_;
        float* out_hi = out_lo + (size_t)8 * DM_;
#pragma unroll
        for (int a = 0; a < 8; a++) {
            int d = a * 8 + 2 * c;
            *(float2*)(out_lo + d) = make_float2(tf32r(o[mt][a][0] * inv0),
                                                 tf32r(o[mt][a][1] * inv0));
            *(float2*)(out_hi + d) = make_float2(tf32r(o[mt][a][2] * inv1),
                                                 tf32r(o[mt][a][3] * inv1));
        }
    }
}

// ---------------- Launch ----------------
extern "C" void kernel_launch(void* const* d_in, const int* in_sizes, int n_in,
                              void* d_out, int out_size)
{
    const float* x  = (const float*)d_in[0];
    const float* Wq = (const float*)d_in[1];
    const float* bq = (const float*)d_in[2];
    const float* Wk = (const float*)d_in[3];
    const float* bk = (const float*)d_in[4];
    const float* Wv = (const float*)d_in[5];
    const float* bv = (const float*)d_in[6];
    const float* Wc = (const float*)d_in[7];
    const float* bc = (const float*)d_in[8];
    float* out = (float*)d_out;

    float* xf; cudaGetSymbolAddress((void**)&xf, g_xf);

    cudaFuncSetAttribute(attn_tc_kernel,
                         cudaFuncAttributeMaxDynamicSharedMemorySize, ATT_SMEM);
    cudaFuncSetAttribute(qkv_tc_kernel,
                         cudaFuncAttributeMaxDynamicSharedMemorySize, QKV_SMEM);

    // pre-swizzle x and Wq/Wk/Wv into fragment layouts (tf32-RN fused)
    swizzle_a_kernel<<<MTOT * DM_ / 4 / 256, 256>>>((const float4*)x, xf);
    dim3 gw(WSZ / 4 / 256, 3);
    swizzle_b_kernel<<<gw, 256>>>((const float4*)Wq, (const float4*)Wk,
                                  (const float4*)Wv);

    dim3 gq(MTOT / 128, DM_ / 128, 3);     // 128 x 6 x 3
    qkv_tc_kernel<<<gq, 256, QKV_SMEM>>>(bq, bk, bv);

    dim3 ga(S_ / 256, H_, B_);             // 4 x 12 x 16
    attn_tc_kernel<<<ga, 256, ATT_SMEM>>>();

    dim3 gp(MTOT / 128, DM_ / 128);        // 128 x 6
    proj_tc_kernel<<<gp, 256>>>(Wc, bc, out);
}

// round 12
// speedup vs baseline: 1.7123x; 1.0934x over previous
#include <cuda_runtime.h>
#include <cstdint>

#define B_   16
#define S_   1024
#define DM_  768
#define H_   12
#define DH_  64
#define MTOT (B_ * S_)   // 16384
#define HSZ  (S_ * DH_)  // 65536 floats per (b,h)
#define WSZ  589824      // 768*768
#define SCALE_C 0.1803368801111204f   // 0.125 * log2(e)

// Scratch (allocation-free rule: __device__ globals)
__device__ __align__(16) float g_q[(size_t)B_ * H_ * HSZ];   // a-frag per (b,h), pre-scaled by SCALE_C
__device__ __align__(16) float g_k[(size_t)B_ * H_ * HSZ];   // b-frag per (b,h)
__device__ __align__(16) float g_v[(size_t)B_ * H_ * HSZ];   // b-frag per (b,h)
__device__ __align__(16) float g_ctx[(size_t)B_ * S_ * DM_]; // a-frag [16384 x 768]
__device__ __align__(16) float g_xf[(size_t)MTOT * DM_];     // a-frag x (tf32-RN)
__device__ __align__(16) float g_wf[(size_t)4 * WSZ];        // b-frag Wq,Wk,Wv,Wc (tf32-RN)

// ---------------- helpers ----------------
__device__ __forceinline__ float tf32r(float x) {
    uint32_t u;
    asm("cvt.rna.tf32.f32 %0, %1;" : "=r"(u) : "f"(x));
    return __uint_as_float(u);
}

__device__ __forceinline__ float ex2f(float x) {
    float y;
    asm("ex2.approx.ftz.f32 %0, %1;" : "=f"(y) : "f"(x));
    return y;
}

__device__ __forceinline__ void mma_tf32(float c[4],
                                         uint32_t a0, uint32_t a1, uint32_t a2, uint32_t a3,
                                         uint32_t b0, uint32_t b1) {
    asm volatile(
        "mma.sync.aligned.m16n8k8.row.col.f32.tf32.tf32.f32 "
        "{%0,%1,%2,%3}, {%4,%5,%6,%7}, {%8,%9}, {%0,%1,%2,%3};"
        : "+f"(c[0]), "+f"(c[1]), "+f"(c[2]), "+f"(c[3])
        : "r"(a0), "r"(a1), "r"(a2), "r"(a3), "r"(b0), "r"(b1));
}

// ---------------- pre-swizzle kernels (R5/R11-proven, tf32-RN fused) ----------------
__global__ void swizzle_a_kernel(const float4* __restrict__ src, float* __restrict__ dst) {
    int i = blockIdx.x * 256 + threadIdx.x;          // one float4 of [M][768]
    float4 v = src[i];
    int row = i / (DM_ / 4);
    int kc  = (i % (DM_ / 4)) * 4;
    int mt = row >> 4, rowt = row & 15, kt = kc >> 3, chi = (kc >> 2) & 1;
    float* d = dst + ((size_t)mt * 96 + kt) * 128
                   + ((rowt & 7) << 4) + (rowt >> 3) + (chi << 1);
    d[0]  = tf32r(v.x);
    d[4]  = tf32r(v.y);
    d[8]  = tf32r(v.z);
    d[12] = tf32r(v.w);
}

__global__ void swizzle_b_kernel(const float4* __restrict__ W0,
                                 const float4* __restrict__ W1,
                                 const float4* __restrict__ W2,
                                 const float4* __restrict__ W3) {
    int w = blockIdx.y;
    const float4* src = (w == 0) ? W0 : (w == 1) ? W1 : (w == 2) ? W2 : W3;
    int i = blockIdx.x * 256 + threadIdx.x;          // one float4 of [768][768]
    float4 v = src[i];
    int n  = i / (DM_ / 4);
    int kc = (i % (DM_ / 4)) * 4;
    int nt = n >> 3, kt = kc >> 3, chi = (kc >> 2) & 1;
    float* d = g_wf + (size_t)w * WSZ + ((size_t)nt * 96 + kt) * 64
                    + ((n & 7) << 3) + chi;
    d[0] = tf32r(v.x);
    d[2] = tf32r(v.y);
    d[4] = tf32r(v.z);
    d[6] = tf32r(v.w);
}

// ---------------- fragment-direct pipelined GEMM core (R11-proven) ----------------
#define STGW 8192                        // words/stage: 4096 A + 4096 B
#define QKV_SMEM (3 * STGW * 4)          // 98304 bytes

__device__ __forceinline__ void tc_gemm_frag(const float* __restrict__ Ag,
                                             const float* __restrict__ Bg,
                                             int m0, int n0, float* smem,
                                             float acc[4][4][4])
{
    const int tid  = threadIdx.x;
    const int lane = tid & 31;
    const int wid  = tid >> 5;
    const int wm   = wid >> 2;
    const int wn   = wid & 3;
    const uint32_t sb = (uint32_t)__cvta_generic_to_shared(smem);

    const float* srcA[4];
    const float* srcB[4];
    uint32_t dstA[4], dstB[4];
#pragma unroll
    for (int i = 0; i < 4; i++) {
        int idx = tid + (i << 8);                    // 0..1023 float4s
        srcA[i] = Ag + ((size_t)((m0 >> 4) + (idx >> 7)) * 96) * 128 + ((idx & 127) << 2);
        dstA[i] = (uint32_t)(((idx >> 7) << 9) + ((idx & 127) << 2));
        srcB[i] = Bg + ((size_t)((n0 >> 3) + (idx >> 6)) * 96) * 64 + ((idx & 63) << 2);
        dstB[i] = (uint32_t)(4096 + ((idx >> 6) << 8) + ((idx & 63) << 2));
    }

    auto pf = [&](int kt, int buf) {
        uint32_t bbase = sb + (uint32_t)(buf * STGW) * 4u;
#pragma unroll
        for (int i = 0; i < 4; i++) {
            asm volatile("cp.async.cg.shared.global [%0], [%1], 16;"
                         :: "r"(bbase + dstA[i] * 4u), "l"(srcA[i] + (size_t)kt * 512));
            asm volatile("cp.async.cg.shared.global [%0], [%1], 16;"
                         :: "r"(bbase + dstB[i] * 4u), "l"(srcB[i] + (size_t)kt * 256));
        }
        asm volatile("cp.async.commit_group;" ::: "memory");
    };

    pf(0, 0); pf(1, 1);
    for (int kt = 0; kt < 24; kt++) {
        if (kt < 23) asm volatile("cp.async.wait_group 1;" ::: "memory");
        else         asm volatile("cp.async.wait_group 0;" ::: "memory");
        __syncthreads();
        if (kt + 2 < 24) pf(kt + 2, (kt + 2) % 3);

        const uint32_t* sA = (const uint32_t*)smem + (kt % 3) * STGW;
        const uint32_t* sB = sA + 4096;
#pragma unroll
        for (int ks = 0; ks < 4; ks++) {
            uint4 a[4]; uint2 b[4];
#pragma unroll
            for (int mi = 0; mi < 4; mi++)
                a[mi] = *(const uint4*)(sA + (((wm * 4 + mi) << 2) + ks) * 128 + (lane << 2));
#pragma unroll
            for (int ni = 0; ni < 4; ni++)
                b[ni] = *(const uint2*)(sB + (((wn * 4 + ni) << 2) + ks) * 64 + (lane << 1));
#pragma unroll
            for (int mi = 0; mi < 4; mi++)
#pragma unroll
                for (int ni = 0; ni < 4; ni++)
                    mma_tf32(acc[mi][ni], a[mi].x, a[mi].y, a[mi].z, a[mi].w,
                             b[ni].x, b[ni].y);
        }
    }
}

// ---------------- Kernel 1: fused QKV projection ----------------
// Q -> a-frag pre-scaled by SCALE_C; K,V -> b-frag affine scatter (R9-proven).
__global__ void __launch_bounds__(256, 2) qkv_tc_kernel(
    const float* __restrict__ bq, const float* __restrict__ bk,
    const float* __restrict__ bv)
{
    extern __shared__ float smem[];
    const int which = blockIdx.z;
    const float* bias = (which == 0) ? bq : (which == 1) ? bk : bv;

    const int m0 = blockIdx.x * 128;
    const int n0 = blockIdx.y * 128;
    float acc[4][4][4] = {};
    tc_gemm_frag(g_xf, g_wf + (size_t)which * WSZ, m0, n0, smem, acc);

    const int lane = threadIdx.x & 31;
    const int wid  = threadIdx.x >> 5;
    const int wm = wid >> 2, wn = wid & 3;
    const int r = lane >> 2, c2 = (lane & 3) * 2;
    const int bb = m0 >> 10;                  // batch constant per block
    const int s0 = m0 & 1023;                 // batch-local base row

    if (which == 0) {
        // Q a-frag, pre-scaled by SCALE_C (exp2-domain softmax)
        const int b0w = ((r << 2) + (c2 & 3)) * 4 + ((c2 >> 2) << 1);
#pragma unroll
        for (int mi = 0; mi < 4; mi++) {
            int s = s0 + wm * 64 + mi * 16;
#pragma unroll
            for (int ni = 0; ni < 4; ni++) {
                int n   = n0 + wn * 32 + ni * 8 + c2;
                int h   = n >> 6;
                int ktl = (n >> 3) & 7;
                float bi0 = bias[n], bi1 = bias[n + 1];
                float* dst = g_q + (size_t)(bb * H_ + h) * HSZ
                                 + ((size_t)(s >> 4) * 8 + ktl) * 128;
                *(float2*)(dst + b0w) =
                    make_float2(tf32r((acc[mi][ni][0] + bi0) * SCALE_C),
                                tf32r((acc[mi][ni][2] + bi0) * SCALE_C));
                *(float2*)(dst + b0w + 4) =
                    make_float2(tf32r((acc[mi][ni][1] + bi1) * SCALE_C),
                                tf32r((acc[mi][ni][3] + bi1) * SCALE_C));
            }
        }
    } else if (which == 1) {
        // K b-frag affine scatter (batch-local sl)
#pragma unroll
        for (int mi = 0; mi < 4; mi++) {
            int sl = s0 + wm * 64 + mi * 16 + r;
            int slp = ((sl >> 6) << 12) + (((sl >> 3) & 7) << 9) + (r << 3);
#pragma unroll
            for (int ni = 0; ni < 4; ni++) {
                int nf = n0 + wn * 32 + ni * 8 + c2;
                int h = nf >> 6, d = nf & 63;
                float bi0 = bias[nf], bi1 = bias[nf + 1];
                float* dst = g_k + (size_t)(bb * H_ + h) * HSZ + slp
                                 + ((d >> 3) << 6) + ((d & 3) << 1) + ((d >> 2) & 1);
                dst[0]   = tf32r(acc[mi][ni][0] + bi0);
                dst[2]   = tf32r(acc[mi][ni][1] + bi1);
                dst[512] = tf32r(acc[mi][ni][2] + bi0);
                dst[514] = tf32r(acc[mi][ni][3] + bi1);
            }
        }
    } else {
        // V b-frag affine scatter (batch-local sl)
#pragma unroll
        for (int mi = 0; mi < 4; mi++) {
            int sl = s0 + wm * 64 + mi * 16 + r;
            int slp = ((sl >> 6) << 12) + (((sl >> 3) & 7) << 6) + ((r & 3) << 1) + ((r >> 2) & 1);
#pragma unroll
            for (int ni = 0; ni < 4; ni++) {
                int nf = n0 + wn * 32 + ni * 8 + c2;
                int h = nf >> 6, d = nf & 63;
                float bi0 = bias[nf], bi1 = bias[nf + 1];
                float* dst = g_v + (size_t)(bb * H_ + h) * HSZ + slp
                                 + ((d >> 3) << 9) + ((d & 7) << 3);
                dst[0]  = tf32r(acc[mi][ni][0] + bi0);
                dst[8]  = tf32r(acc[mi][ni][1] + bi1);
                dst[64] = tf32r(acc[mi][ni][2] + bi0);
                dst[72] = tf32r(acc[mi][ni][3] + bi1);
            }
        }
    }
}

// ---------------- Kernel 3: output projection (fragment pipeline, R5-proven path) ----------------
__global__ void __launch_bounds__(256, 2) proj_tc_kernel(
    const float* __restrict__ bc, float* __restrict__ out)
{
    extern __shared__ float smem[];
    const int m0 = blockIdx.x * 128;
    const int n0 = blockIdx.y * 128;
    float acc[4][4][4] = {};
    tc_gemm_frag(g_ctx, g_wf + (size_t)3 * WSZ, m0, n0, smem, acc);

    const int lane = threadIdx.x & 31;
    const int wid  = threadIdx.x >> 5;
    const int wm = wid >> 2, wn = wid & 3;
    const int r = lane >> 2, c2 = (lane & 3) * 2;
#pragma unroll
    for (int mi = 0; mi < 4; mi++) {
        int r0 = m0 + wm * 64 + mi * 16 + r;
#pragma unroll
        for (int ni = 0; ni < 4; ni++) {
            int n  = n0 + wn * 32 + ni * 8 + c2;
            float b0 = bc[n], b1 = bc[n + 1];
#pragma unroll
            for (int rr = 0; rr < 2; rr++) {
                int m = r0 + rr * 8;
                float2 o = make_float2(acc[mi][ni][rr * 2 + 0] + b0,
                                       acc[mi][ni][rr * 2 + 1] + b1);
                *(float2*)(out + (size_t)m * DM_ + n) = o;
            }
        }
    }
}

// ---------------- Kernel 2: flash attention (R10 structure + exp2 softmax + a-frag ctx) ----------------
#define QW   16384
#define KVS  8192
#define PFW2 2112
#define ATT_WORDS (QW + 2 * KVS + 8 * PFW2)  // 49664
#define ATT_SMEM  (ATT_WORDS * 4)            // 198656 bytes

__global__ void __launch_bounds__(256) attn_tc_kernel()
{
    extern __shared__ float sm[];
    const int tid  = threadIdx.x;
    const int lane = tid & 31, w = tid >> 5;
    const int r = lane >> 2, c = lane & 3;
    const int q0   = blockIdx.x * 256;
    const int head = blockIdx.y, batch = blockIdx.z;
    const size_t base = (size_t)(batch * H_ + head) * HSZ;
    const float* kbf = g_k + base;
    const float* vbf = g_v + base;
    const uint32_t sb = (uint32_t)__cvta_generic_to_shared(sm);

    auto stage = [&](int t, int buf) {
        const float* ksrc = kbf + (size_t)t * 4096;
        const float* vsrc = vbf + (size_t)t * 4096;
#pragma unroll
        for (int i = 0; i < 4; i++) {
            int g = (tid + (i << 8)) << 2;
            uint32_t dst = sb + (uint32_t)(QW + buf * KVS + g) * 4u;
            asm volatile("cp.async.cg.shared.global [%0], [%1], 16;"
                         :: "r"(dst), "l"(ksrc + g));
        }
#pragma unroll
        for (int i = 0; i < 4; i++) {
            int g = (tid + (i << 8)) << 2;
            uint32_t dst = sb + (uint32_t)(QW + buf * KVS + 4096 + g) * 4u;
            asm volatile("cp.async.cg.shared.global [%0], [%1], 16;"
                         :: "r"(dst), "l"(vsrc + g));
        }
        asm volatile("cp.async.commit_group;" ::: "memory");
    };

    {
        const float* qsrc = g_q + base + (size_t)blockIdx.x * QW;
#pragma unroll
        for (int i = 0; i < 16; i++) {
            int g = (tid + (i << 8)) << 2;
            uint32_t dst = sb + (uint32_t)g * 4u;
            asm volatile("cp.async.cg.shared.global [%0], [%1], 16;"
                         :: "r"(dst), "l"(qsrc + g));
        }
    }
    stage(0, 0);

    float o[2][8][4];
#pragma unroll
    for (int mt = 0; mt < 2; mt++)
#pragma unroll
        for (int a = 0; a < 8; a++)
#pragma unroll
            for (int j = 0; j < 4; j++) o[mt][a][j] = 0.f;
    float mi_[2][2] = {{-1e30f, -1e30f}, {-1e30f, -1e30f}};
    float li_[2][2] = {{0.f, 0.f}, {0.f, 0.f}};

    float* Pw = sm + QW + 2 * KVS + w * PFW2;
    const float* Qs = sm + w * 2048;
    const int lc    = (2 * c) & 3;
    const int slotb = (c & 2) ? 2 : 0;

    for (int t = 0; t < S_ / 64; t++) {
        asm volatile("cp.async.wait_group 0;" ::: "memory");
        __syncthreads();
        if (t + 1 < S_ / 64) stage(t + 1, (t + 1) & 1);

        const float* Kb = sm + QW + (t & 1) * KVS;
        const float* Vb = Kb + 4096;

        float s[2][8][4];
#pragma unroll
        for (int mt = 0; mt < 2; mt++)
#pragma unroll
            for (int a = 0; a < 8; a++)
#pragma unroll
                for (int j = 0; j < 4; j++) s[mt][a][j] = 0.f;
#pragma unroll
        for (int ks = 0; ks < 8; ks++) {
            uint4 qa0 = *(const uint4*)(Qs + ks * 128 + (lane << 2));
            uint4 qa1 = *(const uint4*)(Qs + 1024 + ks * 128 + (lane << 2));
#pragma unroll
            for (int a = 0; a < 8; a++) {
                uint2 kb2 = *(const uint2*)(Kb + (((a << 3) + ks) << 6) + (lane << 1));
                mma_tf32(s[0][a], qa0.x, qa0.y, qa0.z, qa0.w, kb2.x, kb2.y);
                mma_tf32(s[1][a], qa1.x, qa1.y, qa1.z, qa1.w, kb2.x, kb2.y);
            }
        }

        // ---- online softmax in exp2 domain (scores pre-scaled by SCALE_C) ----
#pragma unroll
        for (int mt = 0; mt < 2; mt++) {
            float mx0 = -1e30f, mx1 = -1e30f;
#pragma unroll
            for (int a = 0; a < 8; a++) {
                mx0 = fmaxf(mx0, fmaxf(s[mt][a][0], s[mt][a][1]));
                mx1 = fmaxf(mx1, fmaxf(s[mt][a][2], s[mt][a][3]));
            }
            mx0 = fmaxf(mx0, __shfl_xor_sync(0xffffffffu, mx0, 1));
            mx0 = fmaxf(mx0, __shfl_xor_sync(0xffffffffu, mx0, 2));
            mx1 = fmaxf(mx1, __shfl_xor_sync(0xffffffffu, mx1, 1));
            mx1 = fmaxf(mx1, __shfl_xor_sync(0xffffffffu, mx1, 2));
            float mn0 = fmaxf(mi_[mt][0], mx0), mn1 = fmaxf(mi_[mt][1], mx1);
            float cr0 = ex2f(mi_[mt][0] - mn0), cr1 = ex2f(mi_[mt][1] - mn1);
            float sum0 = 0.f, sum1 = 0.f;
#pragma unroll
            for (int a = 0; a < 8; a++) {
                s[mt][a][0] = ex2f(s[mt][a][0] - mn0);
                s[mt][a][1] = ex2f(s[mt][a][1] - mn0);
                s[mt][a][2] = ex2f(s[mt][a][2] - mn1);
                s[mt][a][3] = ex2f(s[mt][a][3] - mn1);
                sum0 += s[mt][a][0] + s[mt][a][1];
                sum1 += s[mt][a][2] + s[mt][a][3];
            }
            sum0 += __shfl_xor_sync(0xffffffffu, sum0, 1);
            sum0 += __shfl_xor_sync(0xffffffffu, sum0, 2);
            sum1 += __shfl_xor_sync(0xffffffffu, sum1, 1);
            sum1 += __shfl_xor_sync(0xffffffffu, sum1, 2);
            li_[mt][0] = li_[mt][0] * cr0 + sum0;  mi_[mt][0] = mn0;
            li_[mt][1] = li_[mt][1] * cr1 + sum1;  mi_[mt][1] = mn1;
#pragma unroll
            for (int a = 0; a < 8; a++) {
                o[mt][a][0] *= cr0; o[mt][a][1] *= cr0;
                o[mt][a][2] *= cr1; o[mt][a][3] *= cr1;
            }
#pragma unroll
            for (int a = 0; a < 8; a++) {
                float* pe = Pw + ((mt << 3) + a) * 132 + ((r << 2) + lc) * 4 + slotb;
                *(float2*)(pe)     = make_float2(tf32r(s[mt][a][0]), tf32r(s[mt][a][2]));
                *(float2*)(pe + 4) = make_float2(tf32r(s[mt][a][1]), tf32r(s[mt][a][3]));
            }
        }
        __syncwarp();

#pragma unroll
        for (int ks = 0; ks < 8; ks++) {
            uint4 pa0 = *(const uint4*)(Pw + ks * 132 + (lane << 2));
            uint4 pa1 = *(const uint4*)(Pw + (8 + ks) * 132 + (lane << 2));
#pragma unroll
            for (int a = 0; a < 8; a++) {
                uint2 vb2 = *(const uint2*)(Vb + (((a << 3) + ks) << 6) + (lane << 1));
                mma_tf32(o[0][a], pa0.x, pa0.y, pa0.z, pa0.w, vb2.x, vb2.y);
                mma_tf32(o[1][a], pa1.x, pa1.y, pa1.z, pa1.w, vb2.x, vb2.y);
            }
        }
    }

    // ---- epilogue: normalize, tf32-round, write ctx in a-frag layout (R5-proven) ----
    const int c2 = 2 * c;
    const int b0w = ((r << 2) + (c2 & 3)) * 4 + ((c2 >> 2) << 1);
#pragma unroll
    for (int mt = 0; mt < 2; mt++) {
        float inv0 = 1.f / li_[mt][0], inv1 = 1.f / li_[mt][1];
        const int mtg = batch * 64 + (q0 >> 4) + w * 2 + mt;   // global 16-row tile
        float* cf = g_ctx + ((size_t)mtg * 96 + head * 8) * 128;
#pragma unroll
        for (int a = 0; a < 8; a++) {
            *(float2*)(cf + a * 128 + b0w) =
                make_float2(tf32r(o[mt][a][0] * inv0), tf32r(o[mt][a][2] * inv1));
            *(float2*)(cf + a * 128 + b0w + 4) =
                make_float2(tf32r(o[mt][a][1] * inv0), tf32r(o[mt][a][3] * inv1));
        }
    }
}

// ---------------- Launch ----------------
extern "C" void kernel_launch(void* const* d_in, const int* in_sizes, int n_in,
                              void* d_out, int out_size)
{
    const float* x  = (const float*)d_in[0];
    const float* Wq = (const float*)d_in[1];
    const float* bq = (const float*)d_in[2];
    const float* Wk = (const float*)d_in[3];
    const float* bk = (const float*)d_in[4];
    const float* Wv = (const float*)d_in[5];
    const float* bv = (const float*)d_in[6];
    const float* Wc = (const float*)d_in[7];
    const float* bc = (const float*)d_in[8];
    float* out = (float*)d_out;

    float* xf; cudaGetSymbolAddress((void**)&xf, g_xf);

    cudaFuncSetAttribute(attn_tc_kernel,
                         cudaFuncAttributeMaxDynamicSharedMemorySize, ATT_SMEM);
    cudaFuncSetAttribute(qkv_tc_kernel,
                         cudaFuncAttributeMaxDynamicSharedMemorySize, QKV_SMEM);
    cudaFuncSetAttribute(proj_tc_kernel,
                         cudaFuncAttributeMaxDynamicSharedMemorySize, QKV_SMEM);

    // pre-swizzle x and all four W into fragment layouts (tf32-RN fused)
    swizzle_a_kernel<<<MTOT * DM_ / 4 / 256, 256>>>((const float4*)x, xf);
    dim3 gw(WSZ / 4 / 256, 4);
    swizzle_b_kernel<<<gw, 256>>>((const float4*)Wq, (const float4*)Wk,
                                  (const float4*)Wv, (const float4*)Wc);

    dim3 gq(MTOT / 128, DM_ / 128, 3);     // 128 x 6 x 3
    qkv_tc_kernel<<<gq, 256, QKV_SMEM>>>(bq, bk, bv);

    dim3 ga(S_ / 256, H_, B_);             // 4 x 12 x 16
    attn_tc_kernel<<<ga, 256, ATT_SMEM>>>();

    dim3 gp(MTOT / 128, DM_ / 128);        // 128 x 6
    proj_tc_kernel<<<gp, 256, QKV_SMEM>>>(bc, out);
}

// round 13
// speedup vs baseline: 2.1041x; 1.2288x over previous
#include <cuda_runtime.h>
#include <cuda_fp16.h>
#include <cstdint>

#define B_   16
#define S_   1024
#define DM_  768
#define H_   12
#define DH_  64
#define MTOT (B_ * S_)   // 16384
#define HSZ  (S_ * DH_)  // 65536 elems per (b,h)
#define WSZ  589824      // 768*768
#define SCALE_C 0.1803368801111204f   // 0.125 * log2(e)

// Scratch (allocation-free rule: __device__ globals)
__device__ __align__(16) __half g_qh[(size_t)B_ * H_ * HSZ];  // fp16 a-frag (m16n8k16), pre-scaled
__device__ __align__(16) __half g_kh[(size_t)B_ * H_ * HSZ];  // fp16 b-frag (m16n8k16)
__device__ __align__(16) __half g_vh[(size_t)B_ * H_ * HSZ];  // fp16 b-frag (m16n8k16)
__device__ __align__(16) float g_ctx[(size_t)B_ * S_ * DM_];  // tf32 a-frag for proj
__device__ __align__(16) float g_xf[(size_t)MTOT * DM_];      // a-frag x (tf32-RN)
__device__ __align__(16) float g_wf[(size_t)4 * WSZ];         // b-frag Wq,Wk,Wv,Wc (tf32-RN)

// ---------------- helpers ----------------
__device__ __forceinline__ float tf32r(float x) {
    uint32_t u;
    asm("cvt.rna.tf32.f32 %0, %1;" : "=r"(u) : "f"(x));
    return __uint_as_float(u);
}

__device__ __forceinline__ float ex2f(float x) {
    float y;
    asm("ex2.approx.ftz.f32 %0, %1;" : "=f"(y) : "f"(x));
    return y;
}

__device__ __forceinline__ void mma_tf32(float c[4],
                                         uint32_t a0, uint32_t a1, uint32_t a2, uint32_t a3,
                                         uint32_t b0, uint32_t b1) {
    asm volatile(
        "mma.sync.aligned.m16n8k8.row.col.f32.tf32.tf32.f32 "
        "{%0,%1,%2,%3}, {%4,%5,%6,%7}, {%8,%9}, {%0,%1,%2,%3};"
        : "+f"(c[0]), "+f"(c[1]), "+f"(c[2]), "+f"(c[3])
        : "r"(a0), "r"(a1), "r"(a2), "r"(a3), "r"(b0), "r"(b1));
}

__device__ __forceinline__ void mma_f16(float c[4],
                                        uint32_t a0, uint32_t a1, uint32_t a2, uint32_t a3,
                                        uint32_t b0, uint32_t b1) {
    asm volatile(
        "mma.sync.aligned.m16n8k16.row.col.f32.f16.f16.f32 "
        "{%0,%1,%2,%3}, {%4,%5,%6,%7}, {%8,%9}, {%0,%1,%2,%3};"
        : "+f"(c[0]), "+f"(c[1]), "+f"(c[2]), "+f"(c[3])
        : "r"(a0), "r"(a1), "r"(a2), "r"(a3), "r"(b0), "r"(b1));
}

// ---------------- pre-swizzle kernels (R11/R12-proven, tf32-RN fused) ----------------
__global__ void swizzle_a_kernel(const float4* __restrict__ src, float* __restrict__ dst) {
    int i = blockIdx.x * 256 + threadIdx.x;
    float4 v = src[i];
    int row = i / (DM_ / 4);
    int kc  = (i % (DM_ / 4)) * 4;
    int mt = row >> 4, rowt = row & 15, kt = kc >> 3, chi = (kc >> 2) & 1;
    float* d = dst + ((size_t)mt * 96 + kt) * 128
                   + ((rowt & 7) << 4) + (rowt >> 3) + (chi << 1);
    d[0]  = tf32r(v.x);
    d[4]  = tf32r(v.y);
    d[8]  = tf32r(v.z);
    d[12] = tf32r(v.w);
}

__global__ void swizzle_b_kernel(const float4* __restrict__ W0,
                                 const float4* __restrict__ W1,
                                 const float4* __restrict__ W2,
                                 const float4* __restrict__ W3) {
    int w = blockIdx.y;
    const float4* src = (w == 0) ? W0 : (w == 1) ? W1 : (w == 2) ? W2 : W3;
    int i = blockIdx.x * 256 + threadIdx.x;
    float4 v = src[i];
    int n  = i / (DM_ / 4);
    int kc = (i % (DM_ / 4)) * 4;
    int nt = n >> 3, kt = kc >> 3, chi = (kc >> 2) & 1;
    float* d = g_wf + (size_t)w * WSZ + ((size_t)nt * 96 + kt) * 64
                    + ((n & 7) << 3) + chi;
    d[0] = tf32r(v.x);
    d[2] = tf32r(v.y);
    d[4] = tf32r(v.z);
    d[6] = tf32r(v.w);
}

// ---------------- fragment-direct pipelined GEMM core (R11-proven) ----------------
#define STGW 8192
#define QKV_SMEM (3 * STGW * 4)          // 98304 bytes

__device__ __forceinline__ void tc_gemm_frag(const float* __restrict__ Ag,
                                             const float* __restrict__ Bg,
                                             int m0, int n0, float* smem,
                                             float acc[4][4][4])
{
    const int tid  = threadIdx.x;
    const int lane = tid & 31;
    const int wid  = tid >> 5;
    const int wm   = wid >> 2;
    const int wn   = wid & 3;
    const uint32_t sb = (uint32_t)__cvta_generic_to_shared(smem);

    const float* srcA[4];
    const float* srcB[4];
    uint32_t dstA[4], dstB[4];
#pragma unroll
    for (int i = 0; i < 4; i++) {
        int idx = tid + (i << 8);
        srcA[i] = Ag + ((size_t)((m0 >> 4) + (idx >> 7)) * 96) * 128 + ((idx & 127) << 2);
        dstA[i] = (uint32_t)(((idx >> 7) << 9) + ((idx & 127) << 2));
        srcB[i] = Bg + ((size_t)((n0 >> 3) + (idx >> 6)) * 96) * 64 + ((idx & 63) << 2);
        dstB[i] = (uint32_t)(4096 + ((idx >> 6) << 8) + ((idx & 63) << 2));
    }

    auto pf = [&](int kt, int buf) {
        uint32_t bbase = sb + (uint32_t)(buf * STGW) * 4u;
#pragma unroll
        for (int i = 0; i < 4; i++) {
            asm volatile("cp.async.cg.shared.global [%0], [%1], 16;"
                         :: "r"(bbase + dstA[i] * 4u), "l"(srcA[i] + (size_t)kt * 512));
            asm volatile("cp.async.cg.shared.global [%0], [%1], 16;"
                         :: "r"(bbase + dstB[i] * 4u), "l"(srcB[i] + (size_t)kt * 256));
        }
        asm volatile("cp.async.commit_group;" ::: "memory");
    };

    pf(0, 0); pf(1, 1);
    for (int kt = 0; kt < 24; kt++) {
        if (kt < 23) asm volatile("cp.async.wait_group 1;" ::: "memory");
        else         asm volatile("cp.async.wait_group 0;" ::: "memory");
        __syncthreads();
        if (kt + 2 < 24) pf(kt + 2, (kt + 2) % 3);

        const uint32_t* sA = (const uint32_t*)smem + (kt % 3) * STGW;
        const uint32_t* sB = sA + 4096;
#pragma unroll
        for (int ks = 0; ks < 4; ks++) {
            uint4 a[4]; uint2 b[4];
#pragma unroll
            for (int mi = 0; mi < 4; mi++)
                a[mi] = *(const uint4*)(sA + (((wm * 4 + mi) << 2) + ks) * 128 + (lane << 2));
#pragma unroll
            for (int ni = 0; ni < 4; ni++)
                b[ni] = *(const uint2*)(sB + (((wn * 4 + ni) << 2) + ks) * 64 + (lane << 1));
#pragma unroll
            for (int mi = 0; mi < 4; mi++)
#pragma unroll
                for (int ni = 0; ni < 4; ni++)
                    mma_tf32(acc[mi][ni], a[mi].x, a[mi].y, a[mi].z, a[mi].w,
                             b[ni].x, b[ni].y);
        }
    }
}

// ---------------- Kernel 1: fused QKV projection (fp16 frag epilogues) ----------------
__global__ void __launch_bounds__(256, 2) qkv_tc_kernel(
    const float* __restrict__ bq, const float* __restrict__ bk,
    const float* __restrict__ bv)
{
    extern __shared__ float smem[];
    const int which = blockIdx.z;
    const float* bias = (which == 0) ? bq : (which == 1) ? bk : bv;

    const int m0 = blockIdx.x * 128;
    const int n0 = blockIdx.y * 128;
    float acc[4][4][4] = {};
    tc_gemm_frag(g_xf, g_wf + (size_t)which * WSZ, m0, n0, smem, acc);

    const int lane = threadIdx.x & 31;
    const int wid  = threadIdx.x >> 5;
    const int wm = wid >> 2, wn = wid & 3;
    const int r = lane >> 2, c = lane & 3;
    const int c2 = 2 * c;
    const int bb = m0 >> 10;                  // batch constant per block
    const int s0 = m0 & 1023;                 // batch-local base row

    if (which == 0) {
        // Q fp16 a-frag (m16n8k16): one 8B store of 4 consecutive halves per (mi,ni)
#pragma unroll
        for (int mi = 0; mi < 4; mi++) {
            int s  = s0 + wm * 64 + mi * 16;
            int mt = s >> 4;
#pragma unroll
            for (int ni = 0; ni < 4; ni++) {
                int n   = n0 + wn * 32 + ni * 8 + c2;
                int h   = n >> 6;
                int kt2 = (n >> 4) & 3;
                float bi0 = bias[n], bi1 = bias[n + 1];
                __half* dst = g_qh + (size_t)(bb * H_ + h) * HSZ
                                   + ((size_t)(mt * 4 + kt2)) * 256
                                   + (r * 4 + c) * 8 + (ni & 1) * 4;
                __half2 lo = __floats2half2_rn((acc[mi][ni][0] + bi0) * SCALE_C,
                                               (acc[mi][ni][1] + bi1) * SCALE_C);
                __half2 hi = __floats2half2_rn((acc[mi][ni][2] + bi0) * SCALE_C,
                                               (acc[mi][ni][3] + bi1) * SCALE_C);
                *(__half2*)(dst)     = lo;
                *(__half2*)(dst + 2) = hi;
            }
        }
    } else if (which == 1) {
        // K fp16 b-frag: half2 at +0 (row r) and +512 (row r+8)
#pragma unroll
        for (int mi = 0; mi < 4; mi++) {
            int sl = s0 + wm * 64 + mi * 16 + r;
            int slp = (sl >> 6) * 4096 + (((sl >> 3) & 7) << 9) + (r << 4);
#pragma unroll
            for (int ni = 0; ni < 4; ni++) {
                int nf = n0 + wn * 32 + ni * 8 + c2;
                int h = nf >> 6, d = nf & 63;
                float bi0 = bias[nf], bi1 = bias[nf + 1];
                __half* dst = g_kh + (size_t)(bb * H_ + h) * HSZ + slp
                                   + ((d >> 4) << 7) + (c << 2) + ((ni & 1) << 1);
                *(__half2*)(dst)       = __floats2half2_rn(acc[mi][ni][0] + bi0,
                                                           acc[mi][ni][1] + bi1);
                *(__half2*)(dst + 512) = __floats2half2_rn(acc[mi][ni][2] + bi0,
                                                           acc[mi][ni][3] + bi1);
            }
        }
    } else {
        // V fp16 b-frag: 4 scalar half stores at +0, +16, +2, +18
#pragma unroll
        for (int mi = 0; mi < 4; mi++) {
            int sl = s0 + wm * 64 + mi * 16 + r;
            int slp = (sl >> 6) * 4096 + ((mi & 3) << 7) + ((r >> 1) << 2) + (r & 1);
#pragma unroll
            for (int ni = 0; ni < 4; ni++) {
                int nf = n0 + wn * 32 + ni * 8 + c2;
                int h = nf >> 6, d = nf & 63;
                float bi0 = bias[nf], bi1 = bias[nf + 1];
                __half* dst = g_vh + (size_t)(bb * H_ + h) * HSZ + slp
                                   + (((d >> 3) & 7) << 9) + ((d & 7) << 4);
                dst[0]  = __float2half_rn(acc[mi][ni][0] + bi0);
                dst[16] = __float2half_rn(acc[mi][ni][1] + bi1);
                dst[2]  = __float2half_rn(acc[mi][ni][2] + bi0);
                dst[18] = __float2half_rn(acc[mi][ni][3] + bi1);
            }
        }
    }
}

// ---------------- Kernel 3: output projection (R12-proven frag pipeline) ----------------
__global__ void __launch_bounds__(256, 2) proj_tc_kernel(
    const float* __restrict__ bc, float* __restrict__ out)
{
    extern __shared__ float smem[];
    const int m0 = blockIdx.x * 128;
    const int n0 = blockIdx.y * 128;
    float acc[4][4][4] = {};
    tc_gemm_frag(g_ctx, g_wf + (size_t)3 * WSZ, m0, n0, smem, acc);

    const int lane = threadIdx.x & 31;
    const int wid  = threadIdx.x >> 5;
    const int wm = wid >> 2, wn = wid & 3;
    const int r = lane >> 2, c2 = (lane & 3) * 2;
#pragma unroll
    for (int mi = 0; mi < 4; mi++) {
        int r0 = m0 + wm * 64 + mi * 16 + r;
#pragma unroll
        for (int ni = 0; ni < 4; ni++) {
            int n  = n0 + wn * 32 + ni * 8 + c2;
            float b0 = bc[n], b1 = bc[n + 1];
#pragma unroll
            for (int rr = 0; rr < 2; rr++) {
                int m = r0 + rr * 8;
                float2 o = make_float2(acc[mi][ni][rr * 2 + 0] + b0,
                                       acc[mi][ni][rr * 2 + 1] + b1);
                *(float2*)(out + (size_t)m * DM_ + n) = o;
            }
        }
    }
}

// ---------------- Kernel 2: flash attention (fp16 m16n8k16) ----------------
// Smem words: Q 8192 | KV 2 x 4096 (K 2048 + V 2048) | P 8 x 1056
#define QWW   8192
#define KVSW  4096
#define PFWW  1056
#define ATT_WORDS (QWW + 2 * KVSW + 8 * PFWW)  // 24832
#define ATT_SMEM  (ATT_WORDS * 4)              // 99328 bytes

__global__ void __launch_bounds__(256) attn_tc_kernel()
{
    extern __shared__ float sm[];
    uint32_t* smw = (uint32_t*)sm;
    const int tid  = threadIdx.x;
    const int lane = tid & 31, w = tid >> 5;
    const int r = lane >> 2, c = lane & 3;
    const int q0   = blockIdx.x * 256;
    const int head = blockIdx.y, batch = blockIdx.z;
    const size_t base = (size_t)(batch * H_ + head) * HSZ;
    const __half* kbf = g_kh + base;
    const __half* vbf = g_vh + base;
    const uint32_t sb = (uint32_t)__cvta_generic_to_shared(sm);

    auto stage = [&](int t, int buf) {
        const __half* ksrc = kbf + (size_t)t * 4096;
        const __half* vsrc = vbf + (size_t)t * 4096;
#pragma unroll
        for (int i = 0; i < 2; i++) {            // K: 512 16B chunks / 256 thr
            int g = (tid + (i << 8)) << 3;       // half offset
            uint32_t dst = sb + (uint32_t)(QWW + buf * KVSW) * 4u + (uint32_t)g * 2u;
            asm volatile("cp.async.cg.shared.global [%0], [%1], 16;"
                         :: "r"(dst), "l"(ksrc + g));
        }
#pragma unroll
        for (int i = 0; i < 2; i++) {            // V
            int g = (tid + (i << 8)) << 3;
            uint32_t dst = sb + (uint32_t)(QWW + buf * KVSW + 2048) * 4u + (uint32_t)g * 2u;
            asm volatile("cp.async.cg.shared.global [%0], [%1], 16;"
                         :: "r"(dst), "l"(vsrc + g));
        }
        asm volatile("cp.async.commit_group;" ::: "memory");
    };

    // Q tile (16384 halves, contiguous) + first K/V stage
    {
        const __half* qsrc = g_qh + base + (size_t)blockIdx.x * 16384;
#pragma unroll
        for (int i = 0; i < 8; i++) {
            int g = (tid + (i << 8)) << 3;
            uint32_t dst = sb + (uint32_t)g * 2u;
            asm volatile("cp.async.cg.shared.global [%0], [%1], 16;"
                         :: "r"(dst), "l"(qsrc + g));
        }
    }
    stage(0, 0);

    float o[2][8][4];
#pragma unroll
    for (int mt = 0; mt < 2; mt++)
#pragma unroll
        for (int a = 0; a < 8; a++)
#pragma unroll
            for (int j = 0; j < 4; j++) o[mt][a][j] = 0.f;
    float mi_[2][2] = {{-1e30f, -1e30f}, {-1e30f, -1e30f}};
    float li_[2][2] = {{0.f, 0.f}, {0.f, 0.f}};

    uint32_t* Pw = smw + QWW + 2 * KVSW + w * PFWW;
    const uint32_t* Qs = smw + (w * 2) * 512;     // warp's 2 m-tiles, 512 words each

    for (int t = 0; t < S_ / 64; t++) {
        asm volatile("cp.async.wait_group 0;" ::: "memory");
        __syncthreads();
        if (t + 1 < S_ / 64) stage(t + 1, (t + 1) & 1);

        const uint32_t* Kb = smw + QWW + (t & 1) * KVSW;
        const uint32_t* Vb = Kb + 2048;

        // ---- S = Q @ K^T (fp16 m16n8k16; 4 k-steps over d=64) ----
        float s[2][8][4];
#pragma unroll
        for (int mt = 0; mt < 2; mt++)
#pragma unroll
            for (int a = 0; a < 8; a++)
#pragma unroll
                for (int j = 0; j < 4; j++) s[mt][a][j] = 0.f;
#pragma unroll
        for (int ks = 0; ks < 4; ks++) {
            uint4 qa0 = *(const uint4*)(Qs + ks * 128 + (lane << 2));
            uint4 qa1 = *(const uint4*)(Qs + 512 + ks * 128 + (lane << 2));
#pragma unroll
            for (int a = 0; a < 8; a++) {
                uint2 kb2 = *(const uint2*)(Kb + ((a * 4 + ks) << 6) + (lane << 1));
                mma_f16(s[0][a], qa0.x, qa0.y, qa0.z, qa0.w, kb2.x, kb2.y);
                mma_f16(s[1][a], qa1.x, qa1.y, qa1.z, qa1.w, kb2.x, kb2.y);
            }
        }

        // ---- online softmax in exp2 domain (c-frag layout unchanged) ----
#pragma unroll
        for (int mt = 0; mt < 2; mt++) {
            float mx0 = -1e30f, mx1 = -1e30f;
#pragma unroll
            for (int a = 0; a < 8; a++) {
                mx0 = fmaxf(mx0, fmaxf(s[mt][a][0], s[mt][a][1]));
                mx1 = fmaxf(mx1, fmaxf(s[mt][a][2], s[mt][a][3]));
            }
            mx0 = fmaxf(mx0, __shfl_xor_sync(0xffffffffu, mx0, 1));
            mx0 = fmaxf(mx0, __shfl_xor_sync(0xffffffffu, mx0, 2));
            mx1 = fmaxf(mx1, __shfl_xor_sync(0xffffffffu, mx1, 1));
            mx1 = fmaxf(mx1, __shfl_xor_sync(0xffffffffu, mx1, 2));
            float mn0 = fmaxf(mi_[mt][0], mx0), mn1 = fmaxf(mi_[mt][1], mx1);
            float cr0 = ex2f(mi_[mt][0] - mn0), cr1 = ex2f(mi_[mt][1] - mn1);
            float sum0 = 0.f, sum1 = 0.f;
#pragma unroll
            for (int a = 0; a < 8; a++) {
                s[mt][a][0] = ex2f(s[mt][a][0] - mn0);
                s[mt][a][1] = ex2f(s[mt][a][1] - mn0);
                s[mt][a][2] = ex2f(s[mt][a][2] - mn1);
                s[mt][a][3] = ex2f(s[mt][a][3] - mn1);
                sum0 += s[mt][a][0] + s[mt][a][1];
                sum1 += s[mt][a][2] + s[mt][a][3];
            }
            sum0 += __shfl_xor_sync(0xffffffffu, sum0, 1);
            sum0 += __shfl_xor_sync(0xffffffffu, sum0, 2);
            sum1 += __shfl_xor_sync(0xffffffffu, sum1, 1);
            sum1 += __shfl_xor_sync(0xffffffffu, sum1, 2);
            li_[mt][0] = li_[mt][0] * cr0 + sum0;  mi_[mt][0] = mn0;
            li_[mt][1] = li_[mt][1] * cr1 + sum1;  mi_[mt][1] = mn1;
#pragma unroll
            for (int a = 0; a < 8; a++) {
                o[mt][a][0] *= cr0; o[mt][a][1] *= cr0;
                o[mt][a][2] *= cr1; o[mt][a][3] *= cr1;
            }
            // P -> fp16 a-frag scatter (warp-local): tile (mt, a>>1), kk = (a&1)*8 + 2c
#pragma unroll
            for (int a = 0; a < 8; a++) {
                uint32_t* pe = Pw + (mt * 4 + (a >> 1)) * 132 + (lane << 2) + ((a & 1) << 1);
                __half2 lo = __floats2half2_rn(s[mt][a][0], s[mt][a][1]);
                __half2 hi = __floats2half2_rn(s[mt][a][2], s[mt][a][3]);
                pe[0] = *(uint32_t*)&lo;
                pe[1] = *(uint32_t*)&hi;
            }
        }
        __syncwarp();

        // ---- O += P @ V (fp16 m16n8k16; 4 k-steps over 64 keys) ----
#pragma unroll
        for (int ks = 0; ks < 4; ks++) {
            uint4 pa0 = *(const uint4*)(Pw + ks * 132 + (lane << 2));
            uint4 pa1 = *(const uint4*)(Pw + (4 + ks) * 132 + (lane << 2));
#pragma unroll
            for (int a = 0; a < 8; a++) {
                uint2 vb2 = *(const uint2*)(Vb + ((a * 4 + ks) << 6) + (lane << 1));
                mma_f16(o[0][a], pa0.x, pa0.y, pa0.z, pa0.w, vb2.x, vb2.y);
                mma_f16(o[1][a], pa1.x, pa1.y, pa1.z, pa1.w, vb2.x, vb2.y);
            }
        }
    }

    // ---- epilogue: normalize, tf32-round, write ctx in a-frag layout (R12-proven) ----
    const int c2 = 2 * c;
    const int b0w = ((r << 2) + (c2 & 3)) * 4 + ((c2 >> 2) << 1);
#pragma unroll
    for (int mt = 0; mt < 2; mt++) {
        float inv0 = 1.f / li_[mt][0], inv1 = 1.f / li_[mt][1];
        const int mtg = batch * 64 + (q0 >> 4) + w * 2 + mt;
        float* cf = g_ctx + ((size_t)mtg * 96 + head * 8) * 128;
#pragma unroll
        for (int a = 0; a < 8; a++) {
            *(float2*)(cf + a * 128 + b0w) =
                make_float2(tf32r(o[mt][a][0] * inv0), tf32r(o[mt][a][2] * inv1));
            *(float2*)(cf + a * 128 + b0w + 4) =
                make_float2(tf32r(o[mt][a][1] * inv0), tf32r(o[mt][a][3] * inv1));
        }
    }
}

// ---------------- Launch ----------------
extern "C" void kernel_launch(void* const* d_in, const int* in_sizes, int n_in,
                              void* d_out, int out_size)
{
    const float* x  = (const float*)d_in[0];
    const float* Wq = (const float*)d_in[1];
    const float* bq = (const float*)d_in[2];
    const float* Wk = (const float*)d_in[3];
    const float* bk = (const float*)d_in[4];
    const float* Wv = (const float*)d_in[5];
    const float* bv = (const float*)d_in[6];
    const float* Wc = (const float*)d_in[7];
    const float* bc = (const float*)d_in[8];
    float* out = (float*)d_out;

    float* xf; cudaGetSymbolAddress((void**)&xf, g_xf);

    cudaFuncSetAttribute(attn_tc_kernel,
                         cudaFuncAttributeMaxDynamicSharedMemorySize, ATT_SMEM);
    cudaFuncSetAttribute(qkv_tc_kernel,
                         cudaFuncAttributeMaxDynamicSharedMemorySize, QKV_SMEM);
    cudaFuncSetAttribute(proj_tc_kernel,
                         cudaFuncAttributeMaxDynamicSharedMemorySize, QKV_SMEM);

    swizzle_a_kernel<<<MTOT * DM_ / 4 / 256, 256>>>((const float4*)x, xf);
    dim3 gw(WSZ / 4 / 256, 4);
    swizzle_b_kernel<<<gw, 256>>>((const float4*)Wq, (const float4*)Wk,
                                  (const float4*)Wv, (const float4*)Wc);

    dim3 gq(MTOT / 128, DM_ / 128, 3);     // 128 x 6 x 3
    qkv_tc_kernel<<<gq, 256, QKV_SMEM>>>(bq, bk, bv);

    dim3 ga(S_ / 256, H_, B_);             // 4 x 12 x 16
    attn_tc_kernel<<<ga, 256, ATT_SMEM>>>();

    dim3 gp(MTOT / 128, DM_ / 128);        // 128 x 6
    proj_tc_kernel<<<gp, 256, QKV_SMEM>>>(bc, out);
}

// round 14
// speedup vs baseline: 3.0938x; 1.4704x over previous
#include <cuda_runtime.h>
#include <cuda_fp16.h>
#include <cstdint>

#define B_   16
#define S_   1024
#define DM_  768
#define H_   12
#define DH_  64
#define MTOT (B_ * S_)   // 16384
#define HSZ  (S_ * DH_)  // 65536 elems per (b,h)
#define WSZ  589824      // 768*768
#define SCALE_C 0.1803368801111204f   // 0.125 * log2(e)

// Scratch (allocation-free rule: __device__ globals)
__device__ __align__(16) __half g_qh[(size_t)B_ * H_ * HSZ];  // fp16 a-frag, pre-scaled
__device__ __align__(16) __half g_kh[(size_t)B_ * H_ * HSZ];  // fp16 b-frag
__device__ __align__(16) __half g_vh[(size_t)B_ * H_ * HSZ];  // fp16 b-frag
__device__ __align__(16) __half g_ch[(size_t)MTOT * DM_];     // fp16 a-frag ctx
__device__ __align__(16) __half g_xh[(size_t)MTOT * DM_];     // fp16 a-frag x
__device__ __align__(16) __half g_wh[(size_t)4 * WSZ];        // fp16 b-frag Wq,Wk,Wv,Wc

// ---------------- helpers ----------------
__device__ __forceinline__ float ex2f(float x) {
    float y;
    asm("ex2.approx.ftz.f32 %0, %1;" : "=f"(y) : "f"(x));
    return y;
}

__device__ __forceinline__ void mma_f16(float c[4],
                                        uint32_t a0, uint32_t a1, uint32_t a2, uint32_t a3,
                                        uint32_t b0, uint32_t b1) {
    asm volatile(
        "mma.sync.aligned.m16n8k16.row.col.f32.f16.f16.f32 "
        "{%0,%1,%2,%3}, {%4,%5,%6,%7}, {%8,%9}, {%0,%1,%2,%3};"
        : "+f"(c[0]), "+f"(c[1]), "+f"(c[2]), "+f"(c[3])
        : "r"(a0), "r"(a1), "r"(a2), "r"(a3), "r"(b0), "r"(b1));
}

// ---------------- pre-swizzle kernels (fp16 frag layouts, RN fused) ----------------
// a-frag tile (16m x 16k = 256 halves): h = ((row%8)*4 + (k%8)/2)*8 + (k/8%2)*4
//                                           + (row/8%2)*2 + k%2
__global__ void swizzle_a_kernel(const float4* __restrict__ src, __half* __restrict__ dst) {
    int i = blockIdx.x * 256 + threadIdx.x;          // one float4 of [M][768]
    float4 v = src[i];
    int row = i / (DM_ / 4);
    int kc  = (i % (DM_ / 4)) * 4;
    int mt = row >> 4, rr = row & 15;
    int kt2 = kc >> 4, cc = kc & 15;
    int h0 = ((rr & 7) * 4 + ((cc & 7) >> 1)) * 8 + (cc >> 3) * 4 + (rr >> 3) * 2;
    __half* d = dst + ((size_t)mt * 48 + kt2) * 256 + h0;
    *(__half2*)(d)     = __floats2half2_rn(v.x, v.y);
    *(__half2*)(d + 8) = __floats2half2_rn(v.z, v.w);   // next c slot
}

// b-frag tile (8n x 16k = 128 halves): h = (n%8)*16 + ((k%8)/2)*4 + (k/8%2)*2 + k%2
__global__ void swizzle_b_kernel(const float4* __restrict__ W0,
                                 const float4* __restrict__ W1,
                                 const float4* __restrict__ W2,
                                 const float4* __restrict__ W3) {
    int w = blockIdx.y;
    const float4* src = (w == 0) ? W0 : (w == 1) ? W1 : (w == 2) ? W2 : W3;
    int i = blockIdx.x * 256 + threadIdx.x;          // one float4 of [768][768]
    float4 v = src[i];
    int n  = i / (DM_ / 4);
    int kc = (i % (DM_ / 4)) * 4;
    int nt = n >> 3, kt2 = kc >> 4, cc = kc & 15;
    int h0 = (n & 7) * 16 + ((cc & 7) >> 1) * 4 + (cc >> 3) * 2;
    __half* d = g_wh + (size_t)w * WSZ + ((size_t)nt * 48 + kt2) * 128 + h0;
    *(__half2*)(d)     = __floats2half2_rn(v.x, v.y);
    *(__half2*)(d + 4) = __floats2half2_rn(v.z, v.w);   // next c slot
}

// ---------------- fp16 fragment-direct pipelined GEMM core ----------------
// Block 128x128, BK=64 (4 kt2-tiles/stage), 3-stage cp.async, 256 threads.
#define STGW 8192                        // words/stage: A 4096 + B 4096 (32KB)
#define GEMM_SMEM (3 * STGW * 4)         // 98304 bytes

__device__ __forceinline__ void tc_gemm_f16(const __half* __restrict__ Ag,
                                            const __half* __restrict__ Bg,
                                            int m0, int n0, float* smem,
                                            float acc[4][4][4])
{
    const int tid  = threadIdx.x;
    const int lane = tid & 31;
    const int wid  = tid >> 5;
    const int wm   = wid >> 2;
    const int wn   = wid & 3;
    const uint32_t sb = (uint32_t)__cvta_generic_to_shared(smem);

    const __half* srcA[4];
    const __half* srcB[4];
    uint32_t dstA[4], dstB[4];
#pragma unroll
    for (int i = 0; i < 4; i++) {
        int idx = tid + (i << 8);                    // 0..1023 16B chunks
        int mt = idx >> 7, k2a = (idx >> 5) & 3, cha = idx & 31;
        srcA[i] = Ag + (size_t)((m0 >> 4) + mt) * 12288 + k2a * 256 + cha * 8;
        dstA[i] = (uint32_t)((mt * 4 + k2a) * 128 + cha * 4);
        int nt = idx >> 6, k2b = (idx >> 4) & 3, chb = idx & 15;
        srcB[i] = Bg + (size_t)((n0 >> 3) + nt) * 6144 + k2b * 128 + chb * 8;
        dstB[i] = (uint32_t)(4096 + (nt * 4 + k2b) * 64 + chb * 4);
    }

    auto pf = [&](int kt, int buf) {
        uint32_t bbase = sb + (uint32_t)(buf * STGW) * 4u;
#pragma unroll
        for (int i = 0; i < 4; i++) {
            asm volatile("cp.async.cg.shared.global [%0], [%1], 16;"
                         :: "r"(bbase + dstA[i] * 4u), "l"(srcA[i] + (size_t)kt * 1024));
            asm volatile("cp.async.cg.shared.global [%0], [%1], 16;"
                         :: "r"(bbase + dstB[i] * 4u), "l"(srcB[i] + (size_t)kt * 512));
        }
        asm volatile("cp.async.commit_group;" ::: "memory");
    };

    pf(0, 0); pf(1, 1);
    for (int kt = 0; kt < 12; kt++) {
        if (kt < 11) asm volatile("cp.async.wait_group 1;" ::: "memory");
        else         asm volatile("cp.async.wait_group 0;" ::: "memory");
        __syncthreads();
        if (kt + 2 < 12) pf(kt + 2, (kt + 2) % 3);

        const uint32_t* sA = (const uint32_t*)smem + (kt % 3) * STGW;
        const uint32_t* sB = sA + 4096;
#pragma unroll
        for (int ks = 0; ks < 4; ks++) {
            uint4 a[4]; uint2 b[4];
#pragma unroll
            for (int mi = 0; mi < 4; mi++)
                a[mi] = *(const uint4*)(sA + (((wm * 4 + mi) << 2) + ks) * 128 + (lane << 2));
#pragma unroll
            for (int ni = 0; ni < 4; ni++)
                b[ni] = *(const uint2*)(sB + (((wn * 4 + ni) << 2) + ks) * 64 + (lane << 1));
#pragma unroll
            for (int mi = 0; mi < 4; mi++)
#pragma unroll
                for (int ni = 0; ni < 4; ni++)
                    mma_f16(acc[mi][ni], a[mi].x, a[mi].y, a[mi].z, a[mi].w,
                            b[ni].x, b[ni].y);
        }
    }
}

// ---------------- Kernel 1: fused QKV projection (R13-proven fp16 epilogues) ----------------
__global__ void __launch_bounds__(256, 2) qkv_tc_kernel(
    const float* __restrict__ bq, const float* __restrict__ bk,
    const float* __restrict__ bv)
{
    extern __shared__ float smem[];
    const int which = blockIdx.z;
    const float* bias = (which == 0) ? bq : (which == 1) ? bk : bv;

    const int m0 = blockIdx.x * 128;
    const int n0 = blockIdx.y * 128;
    float acc[4][4][4] = {};
    tc_gemm_f16(g_xh, g_wh + (size_t)which * WSZ, m0, n0, smem, acc);

    const int lane = threadIdx.x & 31;
    const int wid  = threadIdx.x >> 5;
    const int wm = wid >> 2, wn = wid & 3;
    const int r = lane >> 2, c = lane & 3;
    const int c2 = 2 * c;
    const int bb = m0 >> 10;                  // batch constant per block
    const int s0 = m0 & 1023;                 // batch-local base row

    if (which == 0) {
        // Q fp16 a-frag, pre-scaled by SCALE_C
#pragma unroll
        for (int mi = 0; mi < 4; mi++) {
            int s  = s0 + wm * 64 + mi * 16;
            int mt = s >> 4;
#pragma unroll
            for (int ni = 0; ni < 4; ni++) {
                int n   = n0 + wn * 32 + ni * 8 + c2;
                int h   = n >> 6;
                int kt2 = (n >> 4) & 3;
                float bi0 = bias[n], bi1 = bias[n + 1];
                __half* dst = g_qh + (size_t)(bb * H_ + h) * HSZ
                                   + ((size_t)(mt * 4 + kt2)) * 256
                                   + (r * 4 + c) * 8 + (ni & 1) * 4;
                *(__half2*)(dst)     = __floats2half2_rn((acc[mi][ni][0] + bi0) * SCALE_C,
                                                         (acc[mi][ni][1] + bi1) * SCALE_C);
                *(__half2*)(dst + 2) = __floats2half2_rn((acc[mi][ni][2] + bi0) * SCALE_C,
                                                         (acc[mi][ni][3] + bi1) * SCALE_C);
            }
        }
    } else if (which == 1) {
        // K fp16 b-frag
#pragma unroll
        for (int mi = 0; mi < 4; mi++) {
            int sl = s0 + wm * 64 + mi * 16 + r;
            int slp = (sl >> 6) * 4096 + (((sl >> 3) & 7) << 9) + (r << 4);
#pragma unroll
            for (int ni = 0; ni < 4; ni++) {
                int nf = n0 + wn * 32 + ni * 8 + c2;
                int h = nf >> 6, d = nf & 63;
                float bi0 = bias[nf], bi1 = bias[nf + 1];
                __half* dst = g_kh + (size_t)(bb * H_ + h) * HSZ + slp
                                   + ((d >> 4) << 7) + (c << 2) + ((ni & 1) << 1);
                *(__half2*)(dst)       = __floats2half2_rn(acc[mi][ni][0] + bi0,
                                                           acc[mi][ni][1] + bi1);
                *(__half2*)(dst + 512) = __floats2half2_rn(acc[mi][ni][2] + bi0,
                                                           acc[mi][ni][3] + bi1);
            }
        }
    } else {
        // V fp16 b-frag
#pragma unroll
        for (int mi = 0; mi < 4; mi++) {
            int sl = s0 + wm * 64 + mi * 16 + r;
            int slp = (sl >> 6) * 4096 + ((mi & 3) << 7) + ((r >> 1) << 2) + (r & 1);
#pragma unroll
            for (int ni = 0; ni < 4; ni++) {
                int nf = n0 + wn * 32 + ni * 8 + c2;
                int h = nf >> 6, d = nf & 63;
                float bi0 = bias[nf], bi1 = bias[nf + 1];
                __half* dst = g_vh + (size_t)(bb * H_ + h) * HSZ + slp
                                   + (((d >> 3) & 7) << 9) + ((d & 7) << 4);
                dst[0]  = __float2half_rn(acc[mi][ni][0] + bi0);
                dst[16] = __float2half_rn(acc[mi][ni][1] + bi1);
                dst[2]  = __float2half_rn(acc[mi][ni][2] + bi0);
                dst[18] = __float2half_rn(acc[mi][ni][3] + bi1);
            }
        }
    }
}

// ---------------- Kernel 3: output projection (fp16 core) ----------------
__global__ void __launch_bounds__(256, 2) proj_tc_kernel(
    const float* __restrict__ bc, float* __restrict__ out)
{
    extern __shared__ float smem[];
    const int m0 = blockIdx.x * 128;
    const int n0 = blockIdx.y * 128;
    float acc[4][4][4] = {};
    tc_gemm_f16(g_ch, g_wh + (size_t)3 * WSZ, m0, n0, smem, acc);

    const int lane = threadIdx.x & 31;
    const int wid  = threadIdx.x >> 5;
    const int wm = wid >> 2, wn = wid & 3;
    const int r = lane >> 2, c2 = (lane & 3) * 2;
#pragma unroll
    for (int mi = 0; mi < 4; mi++) {
        int r0 = m0 + wm * 64 + mi * 16 + r;
#pragma unroll
        for (int ni = 0; ni < 4; ni++) {
            int n  = n0 + wn * 32 + ni * 8 + c2;
            float b0 = bc[n], b1 = bc[n + 1];
#pragma unroll
            for (int rr = 0; rr < 2; rr++) {
                int m = r0 + rr * 8;
                float2 o = make_float2(acc[mi][ni][rr * 2 + 0] + b0,
                                       acc[mi][ni][rr * 2 + 1] + b1);
                *(float2*)(out + (size_t)m * DM_ + n) = o;
            }
        }
    }
}

// ---------------- Kernel 2: flash attention (R13-proven, fp16 ctx epilogue) ----------------
#define QWW   8192
#define KVSW  4096
#define PFWW  1056
#define ATT_WORDS (QWW + 2 * KVSW + 8 * PFWW)  // 24832
#define ATT_SMEM  (ATT_WORDS * 4)              // 99328 bytes

__global__ void __launch_bounds__(256) attn_tc_kernel()
{
    extern __shared__ float sm[];
    uint32_t* smw = (uint32_t*)sm;
    const int tid  = threadIdx.x;
    const int lane = tid & 31, w = tid >> 5;
    const int r = lane >> 2, c = lane & 3;
    const int q0   = blockIdx.x * 256;
    const int head = blockIdx.y, batch = blockIdx.z;
    const size_t base = (size_t)(batch * H_ + head) * HSZ;
    const __half* kbf = g_kh + base;
    const __half* vbf = g_vh + base;
    const uint32_t sb = (uint32_t)__cvta_generic_to_shared(sm);

    auto stage = [&](int t, int buf) {
        const __half* ksrc = kbf + (size_t)t * 4096;
        const __half* vsrc = vbf + (size_t)t * 4096;
#pragma unroll
        for (int i = 0; i < 2; i++) {
            int g = (tid + (i << 8)) << 3;
            uint32_t dst = sb + (uint32_t)(QWW + buf * KVSW) * 4u + (uint32_t)g * 2u;
            asm volatile("cp.async.cg.shared.global [%0], [%1], 16;"
                         :: "r"(dst), "l"(ksrc + g));
        }
#pragma unroll
        for (int i = 0; i < 2; i++) {
            int g = (tid + (i << 8)) << 3;
            uint32_t dst = sb + (uint32_t)(QWW + buf * KVSW + 2048) * 4u + (uint32_t)g * 2u;
            asm volatile("cp.async.cg.shared.global [%0], [%1], 16;"
                         :: "r"(dst), "l"(vsrc + g));
        }
        asm volatile("cp.async.commit_group;" ::: "memory");
    };

    {
        const __half* qsrc = g_qh + base + (size_t)blockIdx.x * 16384;
#pragma unroll
        for (int i = 0; i < 8; i++) {
            int g = (tid + (i << 8)) << 3;
            uint32_t dst = sb + (uint32_t)g * 2u;
            asm volatile("cp.async.cg.shared.global [%0], [%1], 16;"
                         :: "r"(dst), "l"(qsrc + g));
        }
    }
    stage(0, 0);

    float o[2][8][4];
#pragma unroll
    for (int mt = 0; mt < 2; mt++)
#pragma unroll
        for (int a = 0; a < 8; a++)
#pragma unroll
            for (int j = 0; j < 4; j++) o[mt][a][j] = 0.f;
    float mi_[2][2] = {{-1e30f, -1e30f}, {-1e30f, -1e30f}};
    float li_[2][2] = {{0.f, 0.f}, {0.f, 0.f}};

    uint32_t* Pw = smw + QWW + 2 * KVSW + w * PFWW;
    const uint32_t* Qs = smw + (w * 2) * 512;

    for (int t = 0; t < S_ / 64; t++) {
        asm volatile("cp.async.wait_group 0;" ::: "memory");
        __syncthreads();
        if (t + 1 < S_ / 64) stage(t + 1, (t + 1) & 1);

        const uint32_t* Kb = smw + QWW + (t & 1) * KVSW;
        const uint32_t* Vb = Kb + 2048;

        float s[2][8][4];
#pragma unroll
        for (int mt = 0; mt < 2; mt++)
#pragma unroll
            for (int a = 0; a < 8; a++)
#pragma unroll
                for (int j = 0; j < 4; j++) s[mt][a][j] = 0.f;
#pragma unroll
        for (int ks = 0; ks < 4; ks++) {
            uint4 qa0 = *(const uint4*)(Qs + ks * 128 + (lane << 2));
            uint4 qa1 = *(const uint4*)(Qs + 512 + ks * 128 + (lane << 2));
#pragma unroll
            for (int a = 0; a < 8; a++) {
                uint2 kb2 = *(const uint2*)(Kb + ((a * 4 + ks) << 6) + (lane << 1));
                mma_f16(s[0][a], qa0.x, qa0.y, qa0.z, qa0.w, kb2.x, kb2.y);
                mma_f16(s[1][a], qa1.x, qa1.y, qa1.z, qa1.w, kb2.x, kb2.y);
            }
        }

#pragma unroll
        for (int mt = 0; mt < 2; mt++) {
            float mx0 = -1e30f, mx1 = -1e30f;
#pragma unroll
            for (int a = 0; a < 8; a++) {
                mx0 = fmaxf(mx0, fmaxf(s[mt][a][0], s[mt][a][1]));
                mx1 = fmaxf(mx1, fmaxf(s[mt][a][2], s[mt][a][3]));
            }
            mx0 = fmaxf(mx0, __shfl_xor_sync(0xffffffffu, mx0, 1));
            mx0 = fmaxf(mx0, __shfl_xor_sync(0xffffffffu, mx0, 2));
            mx1 = fmaxf(mx1, __shfl_xor_sync(0xffffffffu, mx1, 1));
            mx1 = fmaxf(mx1, __shfl_xor_sync(0xffffffffu, mx1, 2));
            float mn0 = fmaxf(mi_[mt][0], mx0), mn1 = fmaxf(mi_[mt][1], mx1);
            float cr0 = ex2f(mi_[mt][0] - mn0), cr1 = ex2f(mi_[mt][1] - mn1);
            float sum0 = 0.f, sum1 = 0.f;
#pragma unroll
            for (int a = 0; a < 8; a++) {
                s[mt][a][0] = ex2f(s[mt][a][0] - mn0);
                s[mt][a][1] = ex2f(s[mt][a][1] - mn0);
                s[mt][a][2] = ex2f(s[mt][a][2] - mn1);
                s[mt][a][3] = ex2f(s[mt][a][3] - mn1);
                sum0 += s[mt][a][0] + s[mt][a][1];
                sum1 += s[mt][a][2] + s[mt][a][3];
            }
            sum0 += __shfl_xor_sync(0xffffffffu, sum0, 1);
            sum0 += __shfl_xor_sync(0xffffffffu, sum0, 2);
            sum1 += __shfl_xor_sync(0xffffffffu, sum1, 1);
            sum1 += __shfl_xor_sync(0xffffffffu, sum1, 2);
            li_[mt][0] = li_[mt][0] * cr0 + sum0;  mi_[mt][0] = mn0;
            li_[mt][1] = li_[mt][1] * cr1 + sum1;  mi_[mt][1] = mn1;
#pragma unroll
            for (int a = 0; a < 8; a++) {
                o[mt][a][0] *= cr0; o[mt][a][1] *= cr0;
                o[mt][a][2] *= cr1; o[mt][a][3] *= cr1;
            }
#pragma unroll
            for (int a = 0; a < 8; a++) {
                uint32_t* pe = Pw + (mt * 4 + (a >> 1)) * 132 + (lane << 2) + ((a & 1) << 1);
                __half2 lo = __floats2half2_rn(s[mt][a][0], s[mt][a][1]);
                __half2 hi = __floats2half2_rn(s[mt][a][2], s[mt][a][3]);
                pe[0] = *(uint32_t*)&lo;
                pe[1] = *(uint32_t*)&hi;
            }
        }
        __syncwarp();

#pragma unroll
        for (int ks = 0; ks < 4; ks++) {
            uint4 pa0 = *(const uint4*)(Pw + ks * 132 + (lane << 2));
            uint4 pa1 = *(const uint4*)(Pw + (4 + ks) * 132 + (lane << 2));
#pragma unroll
            for (int a = 0; a < 8; a++) {
                uint2 vb2 = *(const uint2*)(Vb + ((a * 4 + ks) << 6) + (lane << 1));
                mma_f16(o[0][a], pa0.x, pa0.y, pa0.z, pa0.w, vb2.x, vb2.y);
                mma_f16(o[1][a], pa1.x, pa1.y, pa1.z, pa1.w, vb2.x, vb2.y);
            }
        }
    }

    // ---- epilogue: normalize, write ctx as fp16 a-frag (same mapping as Q store) ----
#pragma unroll
    for (int mt = 0; mt < 2; mt++) {
        float inv0 = 1.f / li_[mt][0], inv1 = 1.f / li_[mt][1];
        const int mtg = batch * 64 + (q0 >> 4) + w * 2 + mt;
        __half* cf = g_ch + (size_t)mtg * 12288 + (size_t)head * 4 * 256;
#pragma unroll
        for (int a = 0; a < 8; a++) {
            __half* dst = cf + (a >> 1) * 256 + (r * 4 + c) * 8 + (a & 1) * 4;
            *(__half2*)(dst)     = __floats2half2_rn(o[mt][a][0] * inv0,
                                                     o[mt][a][1] * inv0);
            *(__half2*)(dst + 2) = __floats2half2_rn(o[mt][a][2] * inv1,
                                                     o[mt][a][3] * inv1);
        }
    }
}

// ---------------- Launch ----------------
extern "C" void kernel_launch(void* const* d_in, const int* in_sizes, int n_in,
                              void* d_out, int out_size)
{
    const float* x  = (const float*)d_in[0];
    const float* Wq = (const float*)d_in[1];
    const float* bq = (const float*)d_in[2];
    const float* Wk = (const float*)d_in[3];
    const float* bk = (const float*)d_in[4];
    const float* Wv = (const float*)d_in[5];
    const float* bv = (const float*)d_in[6];
    const float* Wc = (const float*)d_in[7];
    const float* bc = (const float*)d_in[8];
    float* out = (float*)d_out;

    __half* xh; cudaGetSymbolAddress((void**)&xh, g_xh);

    cudaFuncSetAttribute(attn_tc_kernel,
                         cudaFuncAttributeMaxDynamicSharedMemorySize, ATT_SMEM);
    cudaFuncSetAttribute(qkv_tc_kernel,
                         cudaFuncAttributeMaxDynamicSharedMemorySize, GEMM_SMEM);
    cudaFuncSetAttribute(proj_tc_kernel,
                         cudaFuncAttributeMaxDynamicSharedMemorySize, GEMM_SMEM);

    swizzle_a_kernel<<<MTOT * DM_ / 4 / 256, 256>>>((const float4*)x, xh);
    dim3 gw(WSZ / 4 / 256, 4);
    swizzle_b_kernel<<<gw, 256>>>((const float4*)Wq, (const float4*)Wk,
                                  (const float4*)Wv, (const float4*)Wc);

    dim3 gq(MTOT / 128, DM_ / 128, 3);     // 128 x 6 x 3
    qkv_tc_kernel<<<gq, 256, GEMM_SMEM>>>(bq, bk, bv);

    dim3 ga(S_ / 256, H_, B_);             // 4 x 12 x 16
    attn_tc_kernel<<<ga, 256, ATT_SMEM>>>();

    dim3 gp(MTOT / 128, DM_ / 128);        // 128 x 6
    proj_tc_kernel<<<gp, 256, GEMM_SMEM>>>(bc, out);
}

// round 15
// speedup vs baseline: 3.3087x; 1.0694x over previous
#include <cuda_runtime.h>
#include <cuda_fp16.h>
#include <cstdint>

#define B_   16
#define S_   1024
#define DM_  768
#define H_   12
#define DH_  64
#define MTOT (B_ * S_)   // 16384
#define HSZ  (S_ * DH_)  // 65536 elems per (b,h)
#define WSZ  589824      // 768*768
#define SCALE_C 0.1803368801111204f   // 0.125 * log2(e)

// Scratch (allocation-free rule: __device__ globals)
__device__ __align__(16) __half g_qh[(size_t)B_ * H_ * HSZ];  // fp16 a-frag, pre-scaled
__device__ __align__(16) __half g_kh[(size_t)B_ * H_ * HSZ];  // fp16 b-frag
__device__ __align__(16) __half g_vh[(size_t)B_ * H_ * HSZ];  // fp16 b-frag
__device__ __align__(16) __half g_ch[(size_t)MTOT * DM_];     // fp16 a-frag ctx
__device__ __align__(16) __half g_xh[(size_t)MTOT * DM_];     // fp16 a-frag x
__device__ __align__(16) __half g_wh[(size_t)4 * WSZ];        // fp16 b-frag Wq,Wk,Wv,Wc

// ---------------- helpers ----------------
__device__ __forceinline__ float ex2f(float x) {
    float y;
    asm("ex2.approx.ftz.f32 %0, %1;" : "=f"(y) : "f"(x));
    return y;
}

__device__ __forceinline__ void mma_f16(float c[4],
                                        uint32_t a0, uint32_t a1, uint32_t a2, uint32_t a3,
                                        uint32_t b0, uint32_t b1) {
    asm volatile(
        "mma.sync.aligned.m16n8k16.row.col.f32.f16.f16.f32 "
        "{%0,%1,%2,%3}, {%4,%5,%6,%7}, {%8,%9}, {%0,%1,%2,%3};"
        : "+f"(c[0]), "+f"(c[1]), "+f"(c[2]), "+f"(c[3])
        : "r"(a0), "r"(a1), "r"(a2), "r"(a3), "r"(b0), "r"(b1));
}

// ---------------- pre-swizzle kernels (R14-proven) ----------------
__global__ void swizzle_a_kernel(const float4* __restrict__ src, __half* __restrict__ dst) {
    int i = blockIdx.x * 256 + threadIdx.x;
    float4 v = src[i];
    int row = i / (DM_ / 4);
    int kc  = (i % (DM_ / 4)) * 4;
    int mt = row >> 4, rr = row & 15;
    int kt2 = kc >> 4, cc = kc & 15;
    int h0 = ((rr & 7) * 4 + ((cc & 7) >> 1)) * 8 + (cc >> 3) * 4 + (rr >> 3) * 2;
    __half* d = dst + ((size_t)mt * 48 + kt2) * 256 + h0;
    *(__half2*)(d)     = __floats2half2_rn(v.x, v.y);
    *(__half2*)(d + 8) = __floats2half2_rn(v.z, v.w);
}

__global__ void swizzle_b_kernel(const float4* __restrict__ W0,
                                 const float4* __restrict__ W1,
                                 const float4* __restrict__ W2,
                                 const float4* __restrict__ W3) {
    int w = blockIdx.y;
    const float4* src = (w == 0) ? W0 : (w == 1) ? W1 : (w == 2) ? W2 : W3;
    int i = blockIdx.x * 256 + threadIdx.x;
    float4 v = src[i];
    int n  = i / (DM_ / 4);
    int kc = (i % (DM_ / 4)) * 4;
    int nt = n >> 3, kt2 = kc >> 4, cc = kc & 15;
    int h0 = (n & 7) * 16 + ((cc & 7) >> 1) * 4 + (cc >> 3) * 2;
    __half* d = g_wh + (size_t)w * WSZ + ((size_t)nt * 48 + kt2) * 128 + h0;
    *(__half2*)(d)     = __floats2half2_rn(v.x, v.y);
    *(__half2*)(d + 4) = __floats2half2_rn(v.z, v.w);
}

// ---------------- fp16 fragment-direct pipelined GEMM core (R14-proven) ----------------
#define STGW 8192
#define GEMM_SMEM (3 * STGW * 4)         // 98304 bytes

__device__ __forceinline__ void tc_gemm_f16(const __half* __restrict__ Ag,
                                            const __half* __restrict__ Bg,
                                            int m0, int n0, float* smem,
                                            float acc[4][4][4])
{
    const int tid  = threadIdx.x;
    const int lane = tid & 31;
    const int wid  = tid >> 5;
    const int wm   = wid >> 2;
    const int wn   = wid & 3;
    const uint32_t sb = (uint32_t)__cvta_generic_to_shared(smem);

    const __half* srcA[4];
    const __half* srcB[4];
    uint32_t dstA[4], dstB[4];
#pragma unroll
    for (int i = 0; i < 4; i++) {
        int idx = tid + (i << 8);
        int mt = idx >> 7, k2a = (idx >> 5) & 3, cha = idx & 31;
        srcA[i] = Ag + (size_t)((m0 >> 4) + mt) * 12288 + k2a * 256 + cha * 8;
        dstA[i] = (uint32_t)((mt * 4 + k2a) * 128 + cha * 4);
        int nt = idx >> 6, k2b = (idx >> 4) & 3, chb = idx & 15;
        srcB[i] = Bg + (size_t)((n0 >> 3) + nt) * 6144 + k2b * 128 + chb * 8;
        dstB[i] = (uint32_t)(4096 + (nt * 4 + k2b) * 64 + chb * 4);
    }

    auto pf = [&](int kt, int buf) {
        uint32_t bbase = sb + (uint32_t)(buf * STGW) * 4u;
#pragma unroll
        for (int i = 0; i < 4; i++) {
            asm volatile("cp.async.cg.shared.global [%0], [%1], 16;"
                         :: "r"(bbase + dstA[i] * 4u), "l"(srcA[i] + (size_t)kt * 1024));
            asm volatile("cp.async.cg.shared.global [%0], [%1], 16;"
                         :: "r"(bbase + dstB[i] * 4u), "l"(srcB[i] + (size_t)kt * 512));
        }
        asm volatile("cp.async.commit_group;" ::: "memory");
    };

    pf(0, 0); pf(1, 1);
    for (int kt = 0; kt < 12; kt++) {
        if (kt < 11) asm volatile("cp.async.wait_group 1;" ::: "memory");
        else         asm volatile("cp.async.wait_group 0;" ::: "memory");
        __syncthreads();
        if (kt + 2 < 12) pf(kt + 2, (kt + 2) % 3);

        const uint32_t* sA = (const uint32_t*)smem + (kt % 3) * STGW;
        const uint32_t* sB = sA + 4096;
#pragma unroll
        for (int ks = 0; ks < 4; ks++) {
            uint4 a[4]; uint2 b[4];
#pragma unroll
            for (int mi = 0; mi < 4; mi++)
                a[mi] = *(const uint4*)(sA + (((wm * 4 + mi) << 2) + ks) * 128 + (lane << 2));
#pragma unroll
            for (int ni = 0; ni < 4; ni++)
                b[ni] = *(const uint2*)(sB + (((wn * 4 + ni) << 2) + ks) * 64 + (lane << 1));
#pragma unroll
            for (int mi = 0; mi < 4; mi++)
#pragma unroll
                for (int ni = 0; ni < 4; ni++)
                    mma_f16(acc[mi][ni], a[mi].x, a[mi].y, a[mi].z, a[mi].w,
                            b[ni].x, b[ni].y);
        }
    }
}

// ---------------- Kernel 1: fused QKV projection (EXACT R14 — proven) ----------------
__global__ void __launch_bounds__(256, 2) qkv_tc_kernel(
    const float* __restrict__ bq, const float* __restrict__ bk,
    const float* __restrict__ bv)
{
    extern __shared__ float smem[];
    const int which = blockIdx.z;
    const float* bias = (which == 0) ? bq : (which == 1) ? bk : bv;

    const int m0 = blockIdx.x * 128;
    const int n0 = blockIdx.y * 128;
    float acc[4][4][4] = {};
    tc_gemm_f16(g_xh, g_wh + (size_t)which * WSZ, m0, n0, smem, acc);

    const int lane = threadIdx.x & 31;
    const int wid  = threadIdx.x >> 5;
    const int wm = wid >> 2, wn = wid & 3;
    const int r = lane >> 2, c = lane & 3;
    const int c2 = 2 * c;
    const int bb = m0 >> 10;
    const int s0 = m0 & 1023;

    if (which == 0) {
#pragma unroll
        for (int mi = 0; mi < 4; mi++) {
            int s  = s0 + wm * 64 + mi * 16;
            int mt = s >> 4;
#pragma unroll
            for (int ni = 0; ni < 4; ni++) {
                int n   = n0 + wn * 32 + ni * 8 + c2;
                int h   = n >> 6;
                int kt2 = (n >> 4) & 3;
                float bi0 = bias[n], bi1 = bias[n + 1];
                __half* dst = g_qh + (size_t)(bb * H_ + h) * HSZ
                                   + ((size_t)(mt * 4 + kt2)) * 256
                                   + (r * 4 + c) * 8 + (ni & 1) * 4;
                *(__half2*)(dst)     = __floats2half2_rn((acc[mi][ni][0] + bi0) * SCALE_C,
                                                         (acc[mi][ni][1] + bi1) * SCALE_C);
                *(__half2*)(dst + 2) = __floats2half2_rn((acc[mi][ni][2] + bi0) * SCALE_C,
                                                         (acc[mi][ni][3] + bi1) * SCALE_C);
            }
        }
    } else if (which == 1) {
#pragma unroll
        for (int mi = 0; mi < 4; mi++) {
            int sl = s0 + wm * 64 + mi * 16 + r;
            int slp = (sl >> 6) * 4096 + (((sl >> 3) & 7) << 9) + (r << 4);
#pragma unroll
            for (int ni = 0; ni < 4; ni++) {
                int nf = n0 + wn * 32 + ni * 8 + c2;
                int h = nf >> 6, d = nf & 63;
                float bi0 = bias[nf], bi1 = bias[nf + 1];
                __half* dst = g_kh + (size_t)(bb * H_ + h) * HSZ + slp
                                   + ((d >> 4) << 7) + (c << 2) + ((ni & 1) << 1);
                *(__half2*)(dst)       = __floats2half2_rn(acc[mi][ni][0] + bi0,
                                                           acc[mi][ni][1] + bi1);
                *(__half2*)(dst + 512) = __floats2half2_rn(acc[mi][ni][2] + bi0,
                                                           acc[mi][ni][3] + bi1);
            }
        }
    } else {
#pragma unroll
        for (int mi = 0; mi < 4; mi++) {
            int sl = s0 + wm * 64 + mi * 16 + r;
            int slp = (sl >> 6) * 4096 + ((mi & 3) << 7) + ((r >> 1) << 2) + (r & 1);
#pragma unroll
            for (int ni = 0; ni < 4; ni++) {
                int nf = n0 + wn * 32 + ni * 8 + c2;
                int h = nf >> 6, d = nf & 63;
                float bi0 = bias[nf], bi1 = bias[nf + 1];
                __half* dst = g_vh + (size_t)(bb * H_ + h) * HSZ + slp
                                   + (((d >> 3) & 7) << 9) + ((d & 7) << 4);
                dst[0]  = __float2half_rn(acc[mi][ni][0] + bi0);
                dst[16] = __float2half_rn(acc[mi][ni][1] + bi1);
                dst[2]  = __float2half_rn(acc[mi][ni][2] + bi0);
                dst[18] = __float2half_rn(acc[mi][ni][3] + bi1);
            }
        }
    }
}

// ---------------- Kernel 3: output projection (EXACT R14 — proven) ----------------
__global__ void __launch_bounds__(256, 2) proj_tc_kernel(
    const float* __restrict__ bc, float* __restrict__ out)
{
    extern __shared__ float smem[];
    const int m0 = blockIdx.x * 128;
    const int n0 = blockIdx.y * 128;
    float acc[4][4][4] = {};
    tc_gemm_f16(g_ch, g_wh + (size_t)3 * WSZ, m0, n0, smem, acc);

    const int lane = threadIdx.x & 31;
    const int wid  = threadIdx.x >> 5;
    const int wm = wid >> 2, wn = wid & 3;
    const int r = lane >> 2, c2 = (lane & 3) * 2;
#pragma unroll
    for (int mi = 0; mi < 4; mi++) {
        int r0 = m0 + wm * 64 + mi * 16 + r;
#pragma unroll
        for (int ni = 0; ni < 4; ni++) {
            int n  = n0 + wn * 32 + ni * 8 + c2;
            float b0 = bc[n], b1 = bc[n + 1];
#pragma unroll
            for (int rr = 0; rr < 2; rr++) {
                int m = r0 + rr * 8;
                float2 o = make_float2(acc[mi][ni][rr * 2 + 0] + b0,
                                       acc[mi][ni][rr * 2 + 1] + b1);
                *(float2*)(out + (size_t)m * DM_ + n) = o;
            }
        }
    }
}

// ---------------- Kernel 2: flash attention (fp16, 1 m-tile/warp, 2 blocks/SM) ----------------
// 128 queries of one (b,h), 256 threads / 8 warps; warp owns 16 query rows.
// Q in registers (16 regs). K/V fp16 b-frag, double-buffered. 48.5KB smem.
#define KVSW  4096                      // words/stage: K 2048 + V 2048
#define PFW1  528                       // per-warp P: 4 tiles * 132 words
#define ATT_WORDS (2 * KVSW + 8 * PFW1) // 12416
#define ATT_SMEM  (ATT_WORDS * 4)       // 49664 bytes

__global__ void __launch_bounds__(256, 2) attn_tc_kernel()
{
    extern __shared__ float sm[];
    uint32_t* smw = (uint32_t*)sm;
    const int tid  = threadIdx.x;
    const int lane = tid & 31, w = tid >> 5;
    const int r = lane >> 2, c = lane & 3;
    const int head = blockIdx.y, batch = blockIdx.z;
    const size_t base = (size_t)(batch * H_ + head) * HSZ;
    const __half* kbf = g_kh + base;
    const __half* vbf = g_vh + base;
    const uint32_t sb = (uint32_t)__cvta_generic_to_shared(sm);

    auto stage = [&](int t, int buf) {
        const __half* ksrc = kbf + (size_t)t * 4096;
        const __half* vsrc = vbf + (size_t)t * 4096;
        {
            int g = tid << 3;                                // 256 chunks x 16B = K tile
            uint32_t dst = sb + (uint32_t)(buf * KVSW) * 4u + (uint32_t)g * 2u;
            asm volatile("cp.async.cg.shared.global [%0], [%1], 16;"
                         :: "r"(dst), "l"(ksrc + g));
            int g2 = (tid + 256) << 3;
            uint32_t dst2 = sb + (uint32_t)(buf * KVSW) * 4u + (uint32_t)g2 * 2u;
            asm volatile("cp.async.cg.shared.global [%0], [%1], 16;"
                         :: "r"(dst2), "l"(ksrc + g2));
        }
        {
            int g = tid << 3;
            uint32_t dst = sb + (uint32_t)(buf * KVSW + 2048) * 4u + (uint32_t)g * 2u;
            asm volatile("cp.async.cg.shared.global [%0], [%1], 16;"
                         :: "r"(dst), "l"(vsrc + g));
            int g2 = (tid + 256) << 3;
            uint32_t dst2 = sb + (uint32_t)(buf * KVSW + 2048) * 4u + (uint32_t)g2 * 2u;
            asm volatile("cp.async.cg.shared.global [%0], [%1], 16;"
                         :: "r"(dst2), "l"(vsrc + g2));
        }
        asm volatile("cp.async.commit_group;" ::: "memory");
    };

    stage(0, 0);

    // Q a-fragments in registers: m-tile = blockIdx.x*8 + w (1024 halves)
    uint4 qa[4];
    {
        const __half* qf = g_qh + base + (size_t)(blockIdx.x * 8 + w) * 1024;
#pragma unroll
        for (int ks = 0; ks < 4; ks++)
            qa[ks] = *(const uint4*)(qf + ks * 256 + lane * 8);
    }

    float o[8][4];
#pragma unroll
    for (int a = 0; a < 8; a++)
#pragma unroll
        for (int j = 0; j < 4; j++) o[a][j] = 0.f;
    float mi0 = -1e30f, mi1 = -1e30f, li0 = 0.f, li1 = 0.f;

    uint32_t* Pw = smw + 2 * KVSW + w * PFW1;

    for (int t = 0; t < S_ / 64; t++) {
        asm volatile("cp.async.wait_group 0;" ::: "memory");
        __syncthreads();
        if (t + 1 < S_ / 64) stage(t + 1, (t + 1) & 1);

        const uint32_t* Kb = smw + (t & 1) * KVSW;
        const uint32_t* Vb = Kb + 2048;

        // ---- S = Q @ K^T ----
        float s[8][4];
#pragma unroll
        for (int a = 0; a < 8; a++)
#pragma unroll
            for (int j = 0; j < 4; j++) s[a][j] = 0.f;
#pragma unroll
        for (int ks = 0; ks < 4; ks++) {
#pragma unroll
            for (int a = 0; a < 8; a++) {
                uint2 kb2 = *(const uint2*)(Kb + ((a * 4 + ks) << 6) + (lane << 1));
                mma_f16(s[a], qa[ks].x, qa[ks].y, qa[ks].z, qa[ks].w, kb2.x, kb2.y);
            }
        }

        // ---- online softmax (exp2 domain; rows r, r+8) ----
        float mx0 = -1e30f, mx1 = -1e30f;
#pragma unroll
        for (int a = 0; a < 8; a++) {
            mx0 = fmaxf(mx0, fmaxf(s[a][0], s[a][1]));
            mx1 = fmaxf(mx1, fmaxf(s[a][2], s[a][3]));
        }
        mx0 = fmaxf(mx0, __shfl_xor_sync(0xffffffffu, mx0, 1));
        mx0 = fmaxf(mx0, __shfl_xor_sync(0xffffffffu, mx0, 2));
        mx1 = fmaxf(mx1, __shfl_xor_sync(0xffffffffu, mx1, 1));
        mx1 = fmaxf(mx1, __shfl_xor_sync(0xffffffffu, mx1, 2));
        float mn0 = fmaxf(mi0, mx0), mn1 = fmaxf(mi1, mx1);
        float cr0 = ex2f(mi0 - mn0), cr1 = ex2f(mi1 - mn1);
        float sum0 = 0.f, sum1 = 0.f;
#pragma unroll
        for (int a = 0; a < 8; a++) {
            s[a][0] = ex2f(s[a][0] - mn0);
            s[a][1] = ex2f(s[a][1] - mn0);
            s[a][2] = ex2f(s[a][2] - mn1);
            s[a][3] = ex2f(s[a][3] - mn1);
            sum0 += s[a][0] + s[a][1];
            sum1 += s[a][2] + s[a][3];
        }
        sum0 += __shfl_xor_sync(0xffffffffu, sum0, 1);
        sum0 += __shfl_xor_sync(0xffffffffu, sum0, 2);
        sum1 += __shfl_xor_sync(0xffffffffu, sum1, 1);
        sum1 += __shfl_xor_sync(0xffffffffu, sum1, 2);
        li0 = li0 * cr0 + sum0;  mi0 = mn0;
        li1 = li1 * cr1 + sum1;  mi1 = mn1;
#pragma unroll
        for (int a = 0; a < 8; a++) {
            o[a][0] *= cr0; o[a][1] *= cr0;
            o[a][2] *= cr1; o[a][3] *= cr1;
        }

        // ---- P -> fp16 a-frag scatter (warp-local; R13-proven mapping) ----
#pragma unroll
        for (int a = 0; a < 8; a++) {
            uint32_t* pe = Pw + (a >> 1) * 132 + (lane << 2) + ((a & 1) << 1);
            __half2 lo = __floats2half2_rn(s[a][0], s[a][1]);
            __half2 hi = __floats2half2_rn(s[a][2], s[a][3]);
            pe[0] = *(uint32_t*)&lo;
            pe[1] = *(uint32_t*)&hi;
        }
        __syncwarp();

        // ---- O += P @ V ----
#pragma unroll
        for (int ks = 0; ks < 4; ks++) {
            uint4 pa = *(const uint4*)(Pw + ks * 132 + (lane << 2));
#pragma unroll
            for (int a = 0; a < 8; a++) {
                uint2 vb2 = *(const uint2*)(Vb + ((a * 4 + ks) << 6) + (lane << 1));
                mma_f16(o[a], pa.x, pa.y, pa.z, pa.w, vb2.x, vb2.y);
            }
        }
    }

    // ---- epilogue: normalize, write ctx as fp16 a-frag (R14-proven mapping) ----
    float inv0 = 1.f / li0, inv1 = 1.f / li1;
    const int mtg = batch * 64 + blockIdx.x * 8 + w;
    __half* cf = g_ch + (size_t)mtg * 12288 + (size_t)head * 1024;
#pragma unroll
    for (int a = 0; a < 8; a++) {
        __half* dst = cf + (a >> 1) * 256 + (r * 4 + c) * 8 + (a & 1) * 4;
        *(__half2*)(dst)     = __floats2half2_rn(o[a][0] * inv0, o[a][1] * inv0);
        *(__half2*)(dst + 2) = __floats2half2_rn(o[a][2] * inv1, o[a][3] * inv1);
    }
}

// ---------------- Launch ----------------
extern "C" void kernel_launch(void* const* d_in, const int* in_sizes, int n_in,
                              void* d_out, int out_size)
{
    const float* x  = (const float*)d_in[0];
    const float* Wq = (const float*)d_in[1];
    const float* bq = (const float*)d_in[2];
    const float* Wk = (const float*)d_in[3];
    const float* bk = (const float*)d_in[4];
    const float* Wv = (const float*)d_in[5];
    const float* bv = (const float*)d_in[6];
    const float* Wc = (const float*)d_in[7];
    const float* bc = (const float*)d_in[8];
    float* out = (float*)d_out;

    __half* xh; cudaGetSymbolAddress((void**)&xh, g_xh);

    cudaFuncSetAttribute(attn_tc_kernel,
                         cudaFuncAttributeMaxDynamicSharedMemorySize, ATT_SMEM);
    cudaFuncSetAttribute(qkv_tc_kernel,
                         cudaFuncAttributeMaxDynamicSharedMemorySize, GEMM_SMEM);
    cudaFuncSetAttribute(proj_tc_kernel,
                         cudaFuncAttributeMaxDynamicSharedMemorySize, GEMM_SMEM);

    swizzle_a_kernel<<<MTOT * DM_ / 4 / 256, 256>>>((const float4*)x, xh);
    dim3 gw(WSZ / 4 / 256, 4);
    swizzle_b_kernel<<<gw, 256>>>((const float4*)Wq, (const float4*)Wk,
                                  (const float4*)Wv, (const float4*)Wc);

    dim3 gq(MTOT / 128, DM_ / 128, 3);     // 128 x 6 x 3
    qkv_tc_kernel<<<gq, 256, GEMM_SMEM>>>(bq, bk, bv);

    dim3 ga(S_ / 128, H_, B_);             // 8 x 12 x 16
    attn_tc_kernel<<<ga, 256, ATT_SMEM>>>();

    dim3 gp(MTOT / 128, DM_ / 128);        // 128 x 6
    proj_tc_kernel<<<gp, 256, GEMM_SMEM>>>(bc, out);
}

// round 16
// speedup vs baseline: 3.4318x; 1.0372x over previous
#include <cuda_runtime.h>
#include <cuda_fp16.h>
#include <cstdint>

#define B_   16
#define S_   1024
#define DM_  768
#define H_   12
#define DH_  64
#define MTOT (B_ * S_)   // 16384
#define HSZ  (S_ * DH_)  // 65536 elems per (b,h)
#define WSZ  589824      // 768*768
#define SCALE_C 0.1803368801111204f   // 0.125 * log2(e)

// Scratch (allocation-free rule: __device__ globals)
__device__ __align__(16) __half g_qh[(size_t)B_ * H_ * HSZ];  // fp16 a-frag, pre-scaled
__device__ __align__(16) __half g_kh[(size_t)B_ * H_ * HSZ];  // fp16 b-frag
__device__ __align__(16) __half g_vh[(size_t)B_ * H_ * HSZ];  // fp16 b-frag
__device__ __align__(16) __half g_ch[(size_t)MTOT * DM_];     // fp16 a-frag ctx
__device__ __align__(16) __half g_xh[(size_t)MTOT * DM_];     // fp16 a-frag x
__device__ __align__(16) __half g_wh[(size_t)4 * WSZ];        // fp16 b-frag Wq,Wk,Wv,Wc

// ---------------- helpers ----------------
__device__ __forceinline__ float ex2f(float x) {
    float y;
    asm("ex2.approx.ftz.f32 %0, %1;" : "=f"(y) : "f"(x));
    return y;
}

__device__ __forceinline__ uint32_t packh2(float a, float b) {
    __half2 h = __floats2half2_rn(a, b);
    return *(uint32_t*)&h;
}

__device__ __forceinline__ void mma_f16(float c[4],
                                        uint32_t a0, uint32_t a1, uint32_t a2, uint32_t a3,
                                        uint32_t b0, uint32_t b1) {
    asm volatile(
        "mma.sync.aligned.m16n8k16.row.col.f32.f16.f16.f32 "
        "{%0,%1,%2,%3}, {%4,%5,%6,%7}, {%8,%9}, {%0,%1,%2,%3};"
        : "+f"(c[0]), "+f"(c[1]), "+f"(c[2]), "+f"(c[3])
        : "r"(a0), "r"(a1), "r"(a2), "r"(a3), "r"(b0), "r"(b1));
}

// ---------------- pre-swizzle kernels (R14-proven) ----------------
__global__ void swizzle_a_kernel(const float4* __restrict__ src, __half* __restrict__ dst) {
    int i = blockIdx.x * 256 + threadIdx.x;
    float4 v = src[i];
    int row = i / (DM_ / 4);
    int kc  = (i % (DM_ / 4)) * 4;
    int mt = row >> 4, rr = row & 15;
    int kt2 = kc >> 4, cc = kc & 15;
    int h0 = ((rr & 7) * 4 + ((cc & 7) >> 1)) * 8 + (cc >> 3) * 4 + (rr >> 3) * 2;
    __half* d = dst + ((size_t)mt * 48 + kt2) * 256 + h0;
    *(__half2*)(d)     = __floats2half2_rn(v.x, v.y);
    *(__half2*)(d + 8) = __floats2half2_rn(v.z, v.w);
}

__global__ void swizzle_b_kernel(const float4* __restrict__ W0,
                                 const float4* __restrict__ W1,
                                 const float4* __restrict__ W2,
                                 const float4* __restrict__ W3) {
    int w = blockIdx.y;
    const float4* src = (w == 0) ? W0 : (w == 1) ? W1 : (w == 2) ? W2 : W3;
    int i = blockIdx.x * 256 + threadIdx.x;
    float4 v = src[i];
    int n  = i / (DM_ / 4);
    int kc = (i % (DM_ / 4)) * 4;
    int nt = n >> 3, kt2 = kc >> 4, cc = kc & 15;
    int h0 = (n & 7) * 16 + ((cc & 7) >> 1) * 4 + (cc >> 3) * 2;
    __half* d = g_wh + (size_t)w * WSZ + ((size_t)nt * 48 + kt2) * 128 + h0;
    *(__half2*)(d)     = __floats2half2_rn(v.x, v.y);
    *(__half2*)(d + 4) = __floats2half2_rn(v.z, v.w);
}

// ---------------- fp16 fragment-direct pipelined GEMM core (R14-proven) ----------------
#define STGW 8192
#define GEMM_SMEM (3 * STGW * 4)         // 98304 bytes

__device__ __forceinline__ void tc_gemm_f16(const __half* __restrict__ Ag,
                                            const __half* __restrict__ Bg,
                                            int m0, int n0, float* smem,
                                            float acc[4][4][4])
{
    const int tid  = threadIdx.x;
    const int lane = tid & 31;
    const int wid  = tid >> 5;
    const int wm   = wid >> 2;
    const int wn   = wid & 3;
    const uint32_t sb = (uint32_t)__cvta_generic_to_shared(smem);

    const __half* srcA[4];
    const __half* srcB[4];
    uint32_t dstA[4], dstB[4];
#pragma unroll
    for (int i = 0; i < 4; i++) {
        int idx = tid + (i << 8);
        int mt = idx >> 7, k2a = (idx >> 5) & 3, cha = idx & 31;
        srcA[i] = Ag + (size_t)((m0 >> 4) + mt) * 12288 + k2a * 256 + cha * 8;
        dstA[i] = (uint32_t)((mt * 4 + k2a) * 128 + cha * 4);
        int nt = idx >> 6, k2b = (idx >> 4) & 3, chb = idx & 15;
        srcB[i] = Bg + (size_t)((n0 >> 3) + nt) * 6144 + k2b * 128 + chb * 8;
        dstB[i] = (uint32_t)(4096 + (nt * 4 + k2b) * 64 + chb * 4);
    }

    auto pf = [&](int kt, int buf) {
        uint32_t bbase = sb + (uint32_t)(buf * STGW) * 4u;
#pragma unroll
        for (int i = 0; i < 4; i++) {
            asm volatile("cp.async.cg.shared.global [%0], [%1], 16;"
                         :: "r"(bbase + dstA[i] * 4u), "l"(srcA[i] + (size_t)kt * 1024));
            asm volatile("cp.async.cg.shared.global [%0], [%1], 16;"
                         :: "r"(bbase + dstB[i] * 4u), "l"(srcB[i] + (size_t)kt * 512));
        }
        asm volatile("cp.async.commit_group;" ::: "memory");
    };

    pf(0, 0); pf(1, 1);
    for (int kt = 0; kt < 12; kt++) {
        if (kt < 11) asm volatile("cp.async.wait_group 1;" ::: "memory");
        else         asm volatile("cp.async.wait_group 0;" ::: "memory");
        __syncthreads();
        if (kt + 2 < 12) pf(kt + 2, (kt + 2) % 3);

        const uint32_t* sA = (const uint32_t*)smem + (kt % 3) * STGW;
        const uint32_t* sB = sA + 4096;
#pragma unroll
        for (int ks = 0; ks < 4; ks++) {
            uint4 a[4]; uint2 b[4];
#pragma unroll
            for (int mi = 0; mi < 4; mi++)
                a[mi] = *(const uint4*)(sA + (((wm * 4 + mi) << 2) + ks) * 128 + (lane << 2));
#pragma unroll
            for (int ni = 0; ni < 4; ni++)
                b[ni] = *(const uint2*)(sB + (((wn * 4 + ni) << 2) + ks) * 64 + (lane << 1));
#pragma unroll
            for (int mi = 0; mi < 4; mi++)
#pragma unroll
                for (int ni = 0; ni < 4; ni++)
                    mma_f16(acc[mi][ni], a[mi].x, a[mi].y, a[mi].z, a[mi].w,
                            b[ni].x, b[ni].y);
        }
    }
}

// ---------------- Kernel 1: fused QKV projection (EXACT R14/R15 — proven) ----------------
__global__ void __launch_bounds__(256, 2) qkv_tc_kernel(
    const float* __restrict__ bq, const float* __restrict__ bk,
    const float* __restrict__ bv)
{
    extern __shared__ float smem[];
    const int which = blockIdx.z;
    const float* bias = (which == 0) ? bq : (which == 1) ? bk : bv;

    const int m0 = blockIdx.x * 128;
    const int n0 = blockIdx.y * 128;
    float acc[4][4][4] = {};
    tc_gemm_f16(g_xh, g_wh + (size_t)which * WSZ, m0, n0, smem, acc);

    const int lane = threadIdx.x & 31;
    const int wid  = threadIdx.x >> 5;
    const int wm = wid >> 2, wn = wid & 3;
    const int r = lane >> 2, c = lane & 3;
    const int c2 = 2 * c;
    const int bb = m0 >> 10;
    const int s0 = m0 & 1023;

    if (which == 0) {
#pragma unroll
        for (int mi = 0; mi < 4; mi++) {
            int s  = s0 + wm * 64 + mi * 16;
            int mt = s >> 4;
#pragma unroll
            for (int ni = 0; ni < 4; ni++) {
                int n   = n0 + wn * 32 + ni * 8 + c2;
                int h   = n >> 6;
                int kt2 = (n >> 4) & 3;
                float bi0 = bias[n], bi1 = bias[n + 1];
                __half* dst = g_qh + (size_t)(bb * H_ + h) * HSZ
                                   + ((size_t)(mt * 4 + kt2)) * 256
                                   + (r * 4 + c) * 8 + (ni & 1) * 4;
                *(__half2*)(dst)     = __floats2half2_rn((acc[mi][ni][0] + bi0) * SCALE_C,
                                                         (acc[mi][ni][1] + bi1) * SCALE_C);
                *(__half2*)(dst + 2) = __floats2half2_rn((acc[mi][ni][2] + bi0) * SCALE_C,
                                                         (acc[mi][ni][3] + bi1) * SCALE_C);
            }
        }
    } else if (which == 1) {
#pragma unroll
        for (int mi = 0; mi < 4; mi++) {
            int sl = s0 + wm * 64 + mi * 16 + r;
            int slp = (sl >> 6) * 4096 + (((sl >> 3) & 7) << 9) + (r << 4);
#pragma unroll
            for (int ni = 0; ni < 4; ni++) {
                int nf = n0 + wn * 32 + ni * 8 + c2;
                int h = nf >> 6, d = nf & 63;
                float bi0 = bias[nf], bi1 = bias[nf + 1];
                __half* dst = g_kh + (size_t)(bb * H_ + h) * HSZ + slp
                                   + ((d >> 4) << 7) + (c << 2) + ((ni & 1) << 1);
                *(__half2*)(dst)       = __floats2half2_rn(acc[mi][ni][0] + bi0,
                                                           acc[mi][ni][1] + bi1);
                *(__half2*)(dst + 512) = __floats2half2_rn(acc[mi][ni][2] + bi0,
                                                           acc[mi][ni][3] + bi1);
            }
        }
    } else {
#pragma unroll
        for (int mi = 0; mi < 4; mi++) {
            int sl = s0 + wm * 64 + mi * 16 + r;
            int slp = (sl >> 6) * 4096 + ((mi & 3) << 7) + ((r >> 1) << 2) + (r & 1);
#pragma unroll
            for (int ni = 0; ni < 4; ni++) {
                int nf = n0 + wn * 32 + ni * 8 + c2;
                int h = nf >> 6, d = nf & 63;
                float bi0 = bias[nf], bi1 = bias[nf + 1];
                __half* dst = g_vh + (size_t)(bb * H_ + h) * HSZ + slp
                                   + (((d >> 3) & 7) << 9) + ((d & 7) << 4);
                dst[0]  = __float2half_rn(acc[mi][ni][0] + bi0);
                dst[16] = __float2half_rn(acc[mi][ni][1] + bi1);
                dst[2]  = __float2half_rn(acc[mi][ni][2] + bi0);
                dst[18] = __float2half_rn(acc[mi][ni][3] + bi1);
            }
        }
    }
}

// ---------------- Kernel 3: output projection (EXACT R14/R15 — proven) ----------------
__global__ void __launch_bounds__(256, 2) proj_tc_kernel(
    const float* __restrict__ bc, float* __restrict__ out)
{
    extern __shared__ float smem[];
    const int m0 = blockIdx.x * 128;
    const int n0 = blockIdx.y * 128;
    float acc[4][4][4] = {};
    tc_gemm_f16(g_ch, g_wh + (size_t)3 * WSZ, m0, n0, smem, acc);

    const int lane = threadIdx.x & 31;
    const int wid  = threadIdx.x >> 5;
    const int wm = wid >> 2, wn = wid & 3;
    const int r = lane >> 2, c2 = (lane & 3) * 2;
#pragma unroll
    for (int mi = 0; mi < 4; mi++) {
        int r0 = m0 + wm * 64 + mi * 16 + r;
#pragma unroll
        for (int ni = 0; ni < 4; ni++) {
            int n  = n0 + wn * 32 + ni * 8 + c2;
            float b0 = bc[n], b1 = bc[n + 1];
#pragma unroll
            for (int rr = 0; rr < 2; rr++) {
                int m = r0 + rr * 8;
                float2 o = make_float2(acc[mi][ni][rr * 2 + 0] + b0,
                                       acc[mi][ni][rr * 2 + 1] + b1);
                *(float2*)(out + (size_t)m * DM_ + n) = o;
            }
        }
    }
}

// ---------------- Kernel 2: flash attention (P kept in registers — no smem round-trip) ----------------
// 128 queries of one (b,h), 256 threads / 8 warps; warp owns 16 query rows.
// Q in registers. K/V fp16 b-frag double-buffered. 32KB smem, 2 blocks/SM.
// KEY: the S c-fragment layout IS the PV a-fragment layout (verified identity
// of the R15 smem round-trip), so P never touches smem.
#define KVSW  4096                      // words/stage: K 2048 + V 2048
#define ATT_WORDS (2 * KVSW)            // 8192
#define ATT_SMEM  (ATT_WORDS * 4)       // 32768 bytes

__global__ void __launch_bounds__(256, 2) attn_tc_kernel()
{
    extern __shared__ float sm[];
    uint32_t* smw = (uint32_t*)sm;
    const int tid  = threadIdx.x;
    const int lane = tid & 31, w = tid >> 5;
    const int r = lane >> 2, c = lane & 3;
    const int head = blockIdx.y, batch = blockIdx.z;
    const size_t base = (size_t)(batch * H_ + head) * HSZ;
    const __half* kbf = g_kh + base;
    const __half* vbf = g_vh + base;
    const uint32_t sb = (uint32_t)__cvta_generic_to_shared(sm);

    auto stage = [&](int t, int buf) {
        const __half* ksrc = kbf + (size_t)t * 4096;
        const __half* vsrc = vbf + (size_t)t * 4096;
        {
            int g = tid << 3;
            uint32_t dst = sb + (uint32_t)(buf * KVSW) * 4u + (uint32_t)g * 2u;
            asm volatile("cp.async.cg.shared.global [%0], [%1], 16;"
                         :: "r"(dst), "l"(ksrc + g));
            int g2 = (tid + 256) << 3;
            uint32_t dst2 = sb + (uint32_t)(buf * KVSW) * 4u + (uint32_t)g2 * 2u;
            asm volatile("cp.async.cg.shared.global [%0], [%1], 16;"
                         :: "r"(dst2), "l"(ksrc + g2));
        }
        {
            int g = tid << 3;
            uint32_t dst = sb + (uint32_t)(buf * KVSW + 2048) * 4u + (uint32_t)g * 2u;
            asm volatile("cp.async.cg.shared.global [%0], [%1], 16;"
                         :: "r"(dst), "l"(vsrc + g));
            int g2 = (tid + 256) << 3;
            uint32_t dst2 = sb + (uint32_t)(buf * KVSW + 2048) * 4u + (uint32_t)g2 * 2u;
            asm volatile("cp.async.cg.shared.global [%0], [%1], 16;"
                         :: "r"(dst2), "l"(vsrc + g2));
        }
        asm volatile("cp.async.commit_group;" ::: "memory");
    };

    stage(0, 0);

    // Q a-fragments in registers: m-tile = blockIdx.x*8 + w (1024 halves)
    uint4 qa[4];
    {
        const __half* qf = g_qh + base + (size_t)(blockIdx.x * 8 + w) * 1024;
#pragma unroll
        for (int ks = 0; ks < 4; ks++)
            qa[ks] = *(const uint4*)(qf + ks * 256 + lane * 8);
    }

    float o[8][4];
#pragma unroll
    for (int a = 0; a < 8; a++)
#pragma unroll
        for (int j = 0; j < 4; j++) o[a][j] = 0.f;
    float mi0 = -1e30f, mi1 = -1e30f, li0 = 0.f, li1 = 0.f;

    for (int t = 0; t < S_ / 64; t++) {
        asm volatile("cp.async.wait_group 0;" ::: "memory");
        __syncthreads();
        if (t + 1 < S_ / 64) stage(t + 1, (t + 1) & 1);

        const uint32_t* Kb = smw + (t & 1) * KVSW;
        const uint32_t* Vb = Kb + 2048;

        // ---- S = Q @ K^T ----
        float s[8][4];
#pragma unroll
        for (int a = 0; a < 8; a++)
#pragma unroll
            for (int j = 0; j < 4; j++) s[a][j] = 0.f;
#pragma unroll
        for (int ks = 0; ks < 4; ks++) {
#pragma unroll
            for (int a = 0; a < 8; a++) {
                uint2 kb2 = *(const uint2*)(Kb + ((a * 4 + ks) << 6) + (lane << 1));
                mma_f16(s[a], qa[ks].x, qa[ks].y, qa[ks].z, qa[ks].w, kb2.x, kb2.y);
            }
        }

        // ---- online softmax (exp2 domain; rows r, r+8) ----
        float mx0 = -1e30f, mx1 = -1e30f;
#pragma unroll
        for (int a = 0; a < 8; a++) {
            mx0 = fmaxf(mx0, fmaxf(s[a][0], s[a][1]));
            mx1 = fmaxf(mx1, fmaxf(s[a][2], s[a][3]));
        }
        mx0 = fmaxf(mx0, __shfl_xor_sync(0xffffffffu, mx0, 1));
        mx0 = fmaxf(mx0, __shfl_xor_sync(0xffffffffu, mx0, 2));
        mx1 = fmaxf(mx1, __shfl_xor_sync(0xffffffffu, mx1, 1));
        mx1 = fmaxf(mx1, __shfl_xor_sync(0xffffffffu, mx1, 2));
        float mn0 = fmaxf(mi0, mx0), mn1 = fmaxf(mi1, mx1);
        float cr0 = ex2f(mi0 - mn0), cr1 = ex2f(mi1 - mn1);
        float sum0 = 0.f, sum1 = 0.f;
#pragma unroll
        for (int a = 0; a < 8; a++) {
            s[a][0] = ex2f(s[a][0] - mn0);
            s[a][1] = ex2f(s[a][1] - mn0);
            s[a][2] = ex2f(s[a][2] - mn1);
            s[a][3] = ex2f(s[a][3] - mn1);
            sum0 += s[a][0] + s[a][1];
            sum1 += s[a][2] + s[a][3];
        }
        sum0 += __shfl_xor_sync(0xffffffffu, sum0, 1);
        sum0 += __shfl_xor_sync(0xffffffffu, sum0, 2);
        sum1 += __shfl_xor_sync(0xffffffffu, sum1, 1);
        sum1 += __shfl_xor_sync(0xffffffffu, sum1, 2);
        li0 = li0 * cr0 + sum0;  mi0 = mn0;
        li1 = li1 * cr1 + sum1;  mi1 = mn1;
#pragma unroll
        for (int a = 0; a < 8; a++) {
            o[a][0] *= cr0; o[a][1] *= cr0;
            o[a][2] *= cr1; o[a][3] *= cr1;
        }

        // ---- O += P @ V : P a-frags built directly from S c-frags (identity) ----
#pragma unroll
        for (int ks = 0; ks < 4; ks++) {
            uint32_t p0 = packh2(s[2 * ks][0],     s[2 * ks][1]);
            uint32_t p1 = packh2(s[2 * ks][2],     s[2 * ks][3]);
            uint32_t p2 = packh2(s[2 * ks + 1][0], s[2 * ks + 1][1]);
            uint32_t p3 = packh2(s[2 * ks + 1][2], s[2 * ks + 1][3]);
#pragma unroll
            for (int a = 0; a < 8; a++) {
                uint2 vb2 = *(const uint2*)(Vb + ((a * 4 + ks) << 6) + (lane << 1));
                mma_f16(o[a], p0, p1, p2, p3, vb2.x, vb2.y);
            }
        }
    }

    // ---- epilogue: normalize, write ctx as fp16 a-frag (R14-proven mapping) ----
    float inv0 = 1.f / li0, inv1 = 1.f / li1;
    const int mtg = batch * 64 + blockIdx.x * 8 + w;
    __half* cf = g_ch + (size_t)mtg * 12288 + (size_t)head * 1024;
#pragma unroll
    for (int a = 0; a < 8; a++) {
        __half* dst = cf + (a >> 1) * 256 + (r * 4 + c) * 8 + (a & 1) * 4;
        *(__half2*)(dst)     = __floats2half2_rn(o[a][0] * inv0, o[a][1] * inv0);
        *(__half2*)(dst + 2) = __floats2half2_rn(o[a][2] * inv1, o[a][3] * inv1);
    }
}

// ---------------- Launch ----------------
extern "C" void kernel_launch(void* const* d_in, const int* in_sizes, int n_in,
                              void* d_out, int out_size)
{
    const float* x  = (const float*)d_in[0];
    const float* Wq = (const float*)d_in[1];
    const float* bq = (const float*)d_in[2];
    const float* Wk = (const float*)d_in[3];
    const float* bk = (const float*)d_in[4];
    const float* Wv = (const float*)d_in[5];
    const float* bv = (const float*)d_in[6];
    const float* Wc = (const float*)d_in[7];
    const float* bc = (const float*)d_in[8];
    float* out = (float*)d_out;

    __half* xh; cudaGetSymbolAddress((void**)&xh, g_xh);

    cudaFuncSetAttribute(attn_tc_kernel,
                         cudaFuncAttributeMaxDynamicSharedMemorySize, ATT_SMEM);
    cudaFuncSetAttribute(qkv_tc_kernel,
                         cudaFuncAttributeMaxDynamicSharedMemorySize, GEMM_SMEM);
    cudaFuncSetAttribute(proj_tc_kernel,
                         cudaFuncAttributeMaxDynamicSharedMemorySize, GEMM_SMEM);

    swizzle_a_kernel<<<MTOT * DM_ / 4 / 256, 256>>>((const float4*)x, xh);
    dim3 gw(WSZ / 4 / 256, 4);
    swizzle_b_kernel<<<gw, 256>>>((const float4*)Wq, (const float4*)Wk,
                                  (const float4*)Wv, (const float4*)Wc);

    dim3 gq(MTOT / 128, DM_ / 128, 3);     // 128 x 6 x 3
    qkv_tc_kernel<<<gq, 256, GEMM_SMEM>>>(bq, bk, bv);

    dim3 ga(S_ / 128, H_, B_);             // 8 x 12 x 16
    attn_tc_kernel<<<ga, 256, ATT_SMEM>>>();

    dim3 gp(MTOT / 128, DM_ / 128);        // 128 x 6
    proj_tc_kernel<<<gp, 256, GEMM_SMEM>>>(bc, out);
}

// round 17
// speedup vs baseline: 3.5131x; 1.0237x over previous
#include <cuda_runtime.h>
#include <cuda_fp16.h>
#include <cstdint>

#define B_   16
#define S_   1024
#define DM_  768
#define H_   12
#define DH_  64
#define MTOT (B_ * S_)   // 16384
#define HSZ  (S_ * DH_)  // 65536 elems per (b,h)
#define WSZ  589824      // 768*768
#define SCALE_C 0.1803368801111204f   // 0.125 * log2(e)

// Scratch (allocation-free rule: __device__ globals)
__device__ __align__(16) __half g_qh[(size_t)B_ * H_ * HSZ];  // fp16 a-frag, pre-scaled
__device__ __align__(16) __half g_kh[(size_t)B_ * H_ * HSZ];  // fp16 b-frag
__device__ __align__(16) __half g_vh[(size_t)B_ * H_ * HSZ];  // fp16 b-frag
__device__ __align__(16) __half g_ch[(size_t)MTOT * DM_];     // fp16 a-frag ctx
__device__ __align__(16) __half g_xh[(size_t)MTOT * DM_];     // fp16 a-frag x
__device__ __align__(16) __half g_wh[(size_t)4 * WSZ];        // fp16 b-frag Wq,Wk,Wv,Wc

// ---------------- helpers ----------------
__device__ __forceinline__ float ex2f(float x) {
    float y;
    asm("ex2.approx.ftz.f32 %0, %1;" : "=f"(y) : "f"(x));
    return y;
}

__device__ __forceinline__ uint32_t packh2(float a, float b) {
    __half2 h = __floats2half2_rn(a, b);
    return *(uint32_t*)&h;
}

__device__ __forceinline__ void mma_f16(float c[4],
                                        uint32_t a0, uint32_t a1, uint32_t a2, uint32_t a3,
                                        uint32_t b0, uint32_t b1) {
    asm volatile(
        "mma.sync.aligned.m16n8k16.row.col.f32.f16.f16.f32 "
        "{%0,%1,%2,%3}, {%4,%5,%6,%7}, {%8,%9}, {%0,%1,%2,%3};"
        : "+f"(c[0]), "+f"(c[1]), "+f"(c[2]), "+f"(c[3])
        : "r"(a0), "r"(a1), "r"(a2), "r"(a3), "r"(b0), "r"(b1));
}

// ---------------- pre-swizzle kernels (R14-proven) ----------------
__global__ void swizzle_a_kernel(const float4* __restrict__ src, __half* __restrict__ dst) {
    int i = blockIdx.x * 256 + threadIdx.x;
    float4 v = src[i];
    int row = i / (DM_ / 4);
    int kc  = (i % (DM_ / 4)) * 4;
    int mt = row >> 4, rr = row & 15;
    int kt2 = kc >> 4, cc = kc & 15;
    int h0 = ((rr & 7) * 4 + ((cc & 7) >> 1)) * 8 + (cc >> 3) * 4 + (rr >> 3) * 2;
    __half* d = dst + ((size_t)mt * 48 + kt2) * 256 + h0;
    *(__half2*)(d)     = __floats2half2_rn(v.x, v.y);
    *(__half2*)(d + 8) = __floats2half2_rn(v.z, v.w);
}

__global__ void swizzle_b_kernel(const float4* __restrict__ W0,
                                 const float4* __restrict__ W1,
                                 const float4* __restrict__ W2,
                                 const float4* __restrict__ W3) {
    int w = blockIdx.y;
    const float4* src = (w == 0) ? W0 : (w == 1) ? W1 : (w == 2) ? W2 : W3;
    int i = blockIdx.x * 256 + threadIdx.x;
    float4 v = src[i];
    int n  = i / (DM_ / 4);
    int kc = (i % (DM_ / 4)) * 4;
    int nt = n >> 3, kt2 = kc >> 4, cc = kc & 15;
    int h0 = (n & 7) * 16 + ((cc & 7) >> 1) * 4 + (cc >> 3) * 2;
    __half* d = g_wh + (size_t)w * WSZ + ((size_t)nt * 48 + kt2) * 128 + h0;
    *(__half2*)(d)     = __floats2half2_rn(v.x, v.y);
    *(__half2*)(d + 4) = __floats2half2_rn(v.z, v.w);
}

// ---------------- fp16 fragment-direct pipelined GEMM core ----------------
// 128 threads / 4 warps; warp tile 64x64 (1.0 smem wavefront per MMA).
// Block 128x128, BK=64, 3-stage cp.async.
#define STGW 8192
#define GEMM_SMEM (3 * STGW * 4)         // 98304 bytes

__device__ __forceinline__ void tc_gemm_f16(const __half* __restrict__ Ag,
                                            const __half* __restrict__ Bg,
                                            int m0, int n0, float* smem,
                                            float acc[4][8][4])
{
    const int tid  = threadIdx.x;
    const int lane = tid & 31;
    const int wid  = tid >> 5;       // 0..3
    const int wm   = wid >> 1;       // 0..1
    const int wn   = wid & 1;        // 0..1
    const uint32_t sb = (uint32_t)__cvta_generic_to_shared(smem);

    const __half* srcA[8];
    const __half* srcB[8];
    uint32_t dstA[8], dstB[8];
#pragma unroll
    for (int i = 0; i < 8; i++) {
        int idx = tid + (i << 7);    // 0..1023 16B chunks
        int mt = idx >> 7, k2a = (idx >> 5) & 3, cha = idx & 31;
        srcA[i] = Ag + (size_t)((m0 >> 4) + mt) * 12288 + k2a * 256 + cha * 8;
        dstA[i] = (uint32_t)((mt * 4 + k2a) * 128 + cha * 4);
        int nt = idx >> 6, k2b = (idx >> 4) & 3, chb = idx & 15;
        srcB[i] = Bg + (size_t)((n0 >> 3) + nt) * 6144 + k2b * 128 + chb * 8;
        dstB[i] = (uint32_t)(4096 + (nt * 4 + k2b) * 64 + chb * 4);
    }

    auto pf = [&](int kt, int buf) {
        uint32_t bbase = sb + (uint32_t)(buf * STGW) * 4u;
#pragma unroll
        for (int i = 0; i < 8; i++) {
            asm volatile("cp.async.cg.shared.global [%0], [%1], 16;"
                         :: "r"(bbase + dstA[i] * 4u), "l"(srcA[i] + (size_t)kt * 1024));
            asm volatile("cp.async.cg.shared.global [%0], [%1], 16;"
                         :: "r"(bbase + dstB[i] * 4u), "l"(srcB[i] + (size_t)kt * 512));
        }
        asm volatile("cp.async.commit_group;" ::: "memory");
    };

    pf(0, 0); pf(1, 1);
    for (int kt = 0; kt < 12; kt++) {
        if (kt < 11) asm volatile("cp.async.wait_group 1;" ::: "memory");
        else         asm volatile("cp.async.wait_group 0;" ::: "memory");
        __syncthreads();
        if (kt + 2 < 12) pf(kt + 2, (kt + 2) % 3);

        const uint32_t* sA = (const uint32_t*)smem + (kt % 3) * STGW;
        const uint32_t* sB = sA + 4096;
#pragma unroll
        for (int ks = 0; ks < 4; ks++) {
            uint4 a[4]; uint2 b[8];
#pragma unroll
            for (int mi = 0; mi < 4; mi++)
                a[mi] = *(const uint4*)(sA + (((wm * 4 + mi) << 2) + ks) * 128 + (lane << 2));
#pragma unroll
            for (int ni = 0; ni < 8; ni++)
                b[ni] = *(const uint2*)(sB + (((wn * 8 + ni) << 2) + ks) * 64 + (lane << 1));
#pragma unroll
            for (int mi = 0; mi < 4; mi++)
#pragma unroll
                for (int ni = 0; ni < 8; ni++)
                    mma_f16(acc[mi][ni], a[mi].x, a[mi].y, a[mi].z, a[mi].w,
                            b[ni].x, b[ni].y);
        }
    }
}

// ---------------- Kernel 1: fused QKV projection ----------------
__global__ void __launch_bounds__(128, 2) qkv_tc_kernel(
    const float* __restrict__ bq, const float* __restrict__ bk,
    const float* __restrict__ bv)
{
    extern __shared__ float smem[];
    const int which = blockIdx.z;
    const float* bias = (which == 0) ? bq : (which == 1) ? bk : bv;

    const int m0 = blockIdx.x * 128;
    const int n0 = blockIdx.y * 128;
    float acc[4][8][4] = {};
    tc_gemm_f16(g_xh, g_wh + (size_t)which * WSZ, m0, n0, smem, acc);

    const int lane = threadIdx.x & 31;
    const int wid  = threadIdx.x >> 5;
    const int wm = wid >> 1, wn = wid & 1;
    const int r = lane >> 2, c = lane & 3;
    const int c2 = 2 * c;
    const int bb = m0 >> 10;
    const int s0 = m0 & 1023;

    if (which == 0) {
#pragma unroll
        for (int mi = 0; mi < 4; mi++) {
            int s  = s0 + wm * 64 + mi * 16;
            int mt = s >> 4;
#pragma unroll
            for (int ni = 0; ni < 8; ni++) {
                int n   = n0 + wn * 64 + ni * 8 + c2;
                int h   = n >> 6;
                int kt2 = (n >> 4) & 3;
                float bi0 = bias[n], bi1 = bias[n + 1];
                __half* dst = g_qh + (size_t)(bb * H_ + h) * HSZ
                                   + ((size_t)(mt * 4 + kt2)) * 256
                                   + (r * 4 + c) * 8 + (ni & 1) * 4;
                *(__half2*)(dst)     = __floats2half2_rn((acc[mi][ni][0] + bi0) * SCALE_C,
                                                         (acc[mi][ni][1] + bi1) * SCALE_C);
                *(__half2*)(dst + 2) = __floats2half2_rn((acc[mi][ni][2] + bi0) * SCALE_C,
                                                         (acc[mi][ni][3] + bi1) * SCALE_C);
            }
        }
    } else if (which == 1) {
#pragma unroll
        for (int mi = 0; mi < 4; mi++) {
            int sl = s0 + wm * 64 + mi * 16 + r;
            int slp = (sl >> 6) * 4096 + (((sl >> 3) & 7) << 9) + (r << 4);
#pragma unroll
            for (int ni = 0; ni < 8; ni++) {
                int nf = n0 + wn * 64 + ni * 8 + c2;
                int h = nf >> 6, d = nf & 63;
                float bi0 = bias[nf], bi1 = bias[nf + 1];
                __half* dst = g_kh + (size_t)(bb * H_ + h) * HSZ + slp
                                   + ((d >> 4) << 7) + (c << 2) + ((ni & 1) << 1);
                *(__half2*)(dst)       = __floats2half2_rn(acc[mi][ni][0] + bi0,
                                                           acc[mi][ni][1] + bi1);
                *(__half2*)(dst + 512) = __floats2half2_rn(acc[mi][ni][2] + bi0,
                                                           acc[mi][ni][3] + bi1);
            }
        }
    } else {
#pragma unroll
        for (int mi = 0; mi < 4; mi++) {
            int sl = s0 + wm * 64 + mi * 16 + r;
            int slp = (sl >> 6) * 4096 + ((mi & 3) << 7) + ((r >> 1) << 2) + (r & 1);
#pragma unroll
            for (int ni = 0; ni < 8; ni++) {
                int nf = n0 + wn * 64 + ni * 8 + c2;
                int h = nf >> 6, d = nf & 63;
                float bi0 = bias[nf], bi1 = bias[nf + 1];
                __half* dst = g_vh + (size_t)(bb * H_ + h) * HSZ + slp
                                   + (((d >> 3) & 7) << 9) + ((d & 7) << 4);
                dst[0]  = __float2half_rn(acc[mi][ni][0] + bi0);
                dst[16] = __float2half_rn(acc[mi][ni][1] + bi1);
                dst[2]  = __float2half_rn(acc[mi][ni][2] + bi0);
                dst[18] = __float2half_rn(acc[mi][ni][3] + bi1);
            }
        }
    }
}

// ---------------- Kernel 3: output projection ----------------
__global__ void __launch_bounds__(128, 2) proj_tc_kernel(
    const float* __restrict__ bc, float* __restrict__ out)
{
    extern __shared__ float smem[];
    const int m0 = blockIdx.x * 128;
    const int n0 = blockIdx.y * 128;
    float acc[4][8][4] = {};
    tc_gemm_f16(g_ch, g_wh + (size_t)3 * WSZ, m0, n0, smem, acc);

    const int lane = threadIdx.x & 31;
    const int wid  = threadIdx.x >> 5;
    const int wm = wid >> 1, wn = wid & 1;
    const int r = lane >> 2, c2 = (lane & 3) * 2;
#pragma unroll
    for (int mi = 0; mi < 4; mi++) {
        int r0 = m0 + wm * 64 + mi * 16 + r;
#pragma unroll
        for (int ni = 0; ni < 8; ni++) {
            int n  = n0 + wn * 64 + ni * 8 + c2;
            float b0 = bc[n], b1 = bc[n + 1];
#pragma unroll
            for (int rr = 0; rr < 2; rr++) {
                int m = r0 + rr * 8;
                float2 o = make_float2(acc[mi][ni][rr * 2 + 0] + b0,
                                       acc[mi][ni][rr * 2 + 1] + b1);
                *(float2*)(out + (size_t)m * DM_ + n) = o;
            }
        }
    }
}

// ---------------- Kernel 2: flash attention (EXACT R16 — proven) ----------------
#define KVSW  4096
#define ATT_WORDS (2 * KVSW)
#define ATT_SMEM  (ATT_WORDS * 4)       // 32768 bytes

__global__ void __launch_bounds__(256, 2) attn_tc_kernel()
{
    extern __shared__ float sm[];
    uint32_t* smw = (uint32_t*)sm;
    const int tid  = threadIdx.x;
    const int lane = tid & 31, w = tid >> 5;
    const int r = lane >> 2, c = lane & 3;
    const int head = blockIdx.y, batch = blockIdx.z;
    const size_t base = (size_t)(batch * H_ + head) * HSZ;
    const __half* kbf = g_kh + base;
    const __half* vbf = g_vh + base;
    const uint32_t sb = (uint32_t)__cvta_generic_to_shared(sm);

    auto stage = [&](int t, int buf) {
        const __half* ksrc = kbf + (size_t)t * 4096;
        const __half* vsrc = vbf + (size_t)t * 4096;
        {
            int g = tid << 3;
            uint32_t dst = sb + (uint32_t)(buf * KVSW) * 4u + (uint32_t)g * 2u;
            asm volatile("cp.async.cg.shared.global [%0], [%1], 16;"
                         :: "r"(dst), "l"(ksrc + g));
            int g2 = (tid + 256) << 3;
            uint32_t dst2 = sb + (uint32_t)(buf * KVSW) * 4u + (uint32_t)g2 * 2u;
            asm volatile("cp.async.cg.shared.global [%0], [%1], 16;"
                         :: "r"(dst2), "l"(ksrc + g2));
        }
        {
            int g = tid << 3;
            uint32_t dst = sb + (uint32_t)(buf * KVSW + 2048) * 4u + (uint32_t)g * 2u;
            asm volatile("cp.async.cg.shared.global [%0], [%1], 16;"
                         :: "r"(dst), "l"(vsrc + g));
            int g2 = (tid + 256) << 3;
            uint32_t dst2 = sb + (uint32_t)(buf * KVSW + 2048) * 4u + (uint32_t)g2 * 2u;
            asm volatile("cp.async.cg.shared.global [%0], [%1], 16;"
                         :: "r"(dst2), "l"(vsrc + g2));
        }
        asm volatile("cp.async.commit_group;" ::: "memory");
    };

    stage(0, 0);

    uint4 qa[4];
    {
        const __half* qf = g_qh + base + (size_t)(blockIdx.x * 8 + w) * 1024;
#pragma unroll
        for (int ks = 0; ks < 4; ks++)
            qa[ks] = *(const uint4*)(qf + ks * 256 + lane * 8);
    }

    float o[8][4];
#pragma unroll
    for (int a = 0; a < 8; a++)
#pragma unroll
        for (int j = 0; j < 4; j++) o[a][j] = 0.f;
    float mi0 = -1e30f, mi1 = -1e30f, li0 = 0.f, li1 = 0.f;

    for (int t = 0; t < S_ / 64; t++) {
        asm volatile("cp.async.wait_group 0;" ::: "memory");
        __syncthreads();
        if (t + 1 < S_ / 64) stage(t + 1, (t + 1) & 1);

        const uint32_t* Kb = smw + (t & 1) * KVSW;
        const uint32_t* Vb = Kb + 2048;

        float s[8][4];
#pragma unroll
        for (int a = 0; a < 8; a++)
#pragma unroll
            for (int j = 0; j < 4; j++) s[a][j] = 0.f;
#pragma unroll
        for (int ks = 0; ks < 4; ks++) {
#pragma unroll
            for (int a = 0; a < 8; a++) {
                uint2 kb2 = *(const uint2*)(Kb + ((a * 4 + ks) << 6) + (lane << 1));
                mma_f16(s[a], qa[ks].x, qa[ks].y, qa[ks].z, qa[ks].w, kb2.x, kb2.y);
            }
        }

        float mx0 = -1e30f, mx1 = -1e30f;
#pragma unroll
        for (int a = 0; a < 8; a++) {
            mx0 = fmaxf(mx0, fmaxf(s[a][0], s[a][1]));
            mx1 = fmaxf(mx1, fmaxf(s[a][2], s[a][3]));
        }
        mx0 = fmaxf(mx0, __shfl_xor_sync(0xffffffffu, mx0, 1));
        mx0 = fmaxf(mx0, __shfl_xor_sync(0xffffffffu, mx0, 2));
        mx1 = fmaxf(mx1, __shfl_xor_sync(0xffffffffu, mx1, 1));
        mx1 = fmaxf(mx1, __shfl_xor_sync(0xffffffffu, mx1, 2));
        float mn0 = fmaxf(mi0, mx0), mn1 = fmaxf(mi1, mx1);
        float cr0 = ex2f(mi0 - mn0), cr1 = ex2f(mi1 - mn1);
        float sum0 = 0.f, sum1 = 0.f;
#pragma unroll
        for (int a = 0; a < 8; a++) {
            s[a][0] = ex2f(s[a][0] - mn0);
            s[a][1] = ex2f(s[a][1] - mn0);
            s[a][2] = ex2f(s[a][2] - mn1);
            s[a][3] = ex2f(s[a][3] - mn1);
            sum0 += s[a][0] + s[a][1];
            sum1 += s[a][2] + s[a][3];
        }
        sum0 += __shfl_xor_sync(0xffffffffu, sum0, 1);
        sum0 += __shfl_xor_sync(0xffffffffu, sum0, 2);
        sum1 += __shfl_xor_sync(0xffffffffu, sum1, 1);
        sum1 += __shfl_xor_sync(0xffffffffu, sum1, 2);
        li0 = li0 * cr0 + sum0;  mi0 = mn0;
        li1 = li1 * cr1 + sum1;  mi1 = mn1;
#pragma unroll
        for (int a = 0; a < 8; a++) {
            o[a][0] *= cr0; o[a][1] *= cr0;
            o[a][2] *= cr1; o[a][3] *= cr1;
        }

#pragma unroll
        for (int ks = 0; ks < 4; ks++) {
            uint32_t p0 = packh2(s[2 * ks][0],     s[2 * ks][1]);
            uint32_t p1 = packh2(s[2 * ks][2],     s[2 * ks][3]);
            uint32_t p2 = packh2(s[2 * ks + 1][0], s[2 * ks + 1][1]);
            uint32_t p3 = packh2(s[2 * ks + 1][2], s[2 * ks + 1][3]);
#pragma unroll
            for (int a = 0; a < 8; a++) {
                uint2 vb2 = *(const uint2*)(Vb + ((a * 4 + ks) << 6) + (lane << 1));
                mma_f16(o[a], p0, p1, p2, p3, vb2.x, vb2.y);
            }
        }
    }

    float inv0 = 1.f / li0, inv1 = 1.f / li1;
    const int mtg = batch * 64 + blockIdx.x * 8 + w;
    __half* cf = g_ch + (size_t)mtg * 12288 + (size_t)head * 1024;
#pragma unroll
    for (int a = 0; a < 8; a++) {
        __half* dst = cf + (a >> 1) * 256 + (r * 4 + c) * 8 + (a & 1) * 4;
        *(__half2*)(dst)     = __floats2half2_rn(o[a][0] * inv0, o[a][1] * inv0);
        *(__half2*)(dst + 2) = __floats2half2_rn(o[a][2] * inv1, o[a][3] * inv1);
    }
}

// ---------------- Launch ----------------
extern "C" void kernel_launch(void* const* d_in, const int* in_sizes, int n_in,
                              void* d_out, int out_size)
{
    const float* x  = (const float*)d_in[0];
    const float* Wq = (const float*)d_in[1];
    const float* bq = (const float*)d_in[2];
    const float* Wk = (const float*)d_in[3];
    const float* bk = (const float*)d_in[4];
    const float* Wv = (const float*)d_in[5];
    const float* bv = (const float*)d_in[6];
    const float* Wc = (const float*)d_in[7];
    const float* bc = (const float*)d_in[8];
    float* out = (float*)d_out;

    __half* xh; cudaGetSymbolAddress((void**)&xh, g_xh);

    cudaFuncSetAttribute(attn_tc_kernel,
                         cudaFuncAttributeMaxDynamicSharedMemorySize, ATT_SMEM);
    cudaFuncSetAttribute(qkv_tc_kernel,
                         cudaFuncAttributeMaxDynamicSharedMemorySize, GEMM_SMEM);
    cudaFuncSetAttribute(proj_tc_kernel,
                         cudaFuncAttributeMaxDynamicSharedMemorySize, GEMM_SMEM);

    swizzle_a_kernel<<<MTOT * DM_ / 4 / 256, 256>>>((const float4*)x, xh);
    dim3 gw(WSZ / 4 / 256, 4);
    swizzle_b_kernel<<<gw, 256>>>((const float4*)Wq, (const float4*)Wk,
                                  (const float4*)Wv, (const float4*)Wc);

    dim3 gq(MTOT / 128, DM_ / 128, 3);     // 128 x 6 x 3
    qkv_tc_kernel<<<gq, 128, GEMM_SMEM>>>(bq, bk, bv);

    dim3 ga(S_ / 128, H_, B_);             // 8 x 12 x 16
    attn_tc_kernel<<<ga, 256, ATT_SMEM>>>();

    dim3 gp(MTOT / 128, DM_ / 128);        // 128 x 6
    proj_tc_kernel<<<gp, 128, GEMM_SMEM>>>(bc, out);
}